// round 2
// baseline (speedup 1.0000x reference)
#include <cuda_runtime.h>
#include <cuda_bf16.h>
#include <cstdint>

#define BSZ   128
#define SEQ   256
#define FDIM  512
#define EDIM  512
#define HEADS 8
#define BSROWS (BSZ*SEQ)          // 32768
#define MLPD  2048
#define MIN_POS 1e-6f

// ---------------- scratch (static device globals; no runtime allocation) ----
__device__ float g_xn  [(size_t)BSROWS*FDIM];   // layernormed input / reused for LN2
__device__ float g_xe  [(size_t)BSROWS*EDIM];   // L1-normalized embedding (constant over iters)
__device__ float g_h   [(size_t)BSROWS*EDIM];   // NNMF state
__device__ float g_u1  [(size_t)BSROWS*EDIM];   // intermediate u1 (also raw embed before norm)
__device__ float g_r   [(size_t)BSROWS*EDIM];   // reconstruction
__device__ float g_xres[(size_t)BSROWS*FDIM];   // x + attn residual
__device__ float g_mlp [(size_t)BSROWS*MLPD];   // MLP hidden

// ---------------- LayerNorm: warp per row (512) ------------------------------
__global__ __launch_bounds__(256) void ln_kernel(
    const float* __restrict__ x, const float* __restrict__ g,
    const float* __restrict__ b, float* __restrict__ out)
{
    int row  = blockIdx.x * 8 + (threadIdx.x >> 5);
    int lane = threadIdx.x & 31;
    const float* xr = x + (size_t)row * 512;
    float4 v[4];
    float s = 0.f, sq = 0.f;
#pragma unroll
    for (int w = 0; w < 4; w++) {
        v[w] = *(const float4*)&xr[w * 128 + lane * 4];
        s  += v[w].x + v[w].y + v[w].z + v[w].w;
        sq += v[w].x*v[w].x + v[w].y*v[w].y + v[w].z*v[w].z + v[w].w*v[w].w;
    }
#pragma unroll
    for (int off = 16; off > 0; off >>= 1) {
        s  += __shfl_xor_sync(0xffffffffu, s,  off);
        sq += __shfl_xor_sync(0xffffffffu, sq, off);
    }
    float mu   = s * (1.f / 512.f);
    float var  = sq * (1.f / 512.f) - mu * mu;
    float rstd = rsqrtf(var + 1e-5f);
    float* orow = out + (size_t)row * 512;
#pragma unroll
    for (int w = 0; w < 4; w++) {
        int c = w * 128 + lane * 4;
        float4 gv = *(const float4*)&g[c];
        float4 bv = *(const float4*)&b[c];
        float4 o;
        o.x = (v[w].x - mu) * rstd * gv.x + bv.x;
        o.y = (v[w].y - mu) * rstd * gv.y + bv.y;
        o.z = (v[w].z - mu) * rstd * gv.z + bv.z;
        o.w = (v[w].w - mu) * rstd * gv.w + bv.w;
        *(float4*)&orow[c] = o;
    }
}

// ---------------- per-64-group L1 normalize (warp per group) ----------------
__global__ __launch_bounds__(256) void l1norm64_kernel(
    const float* __restrict__ in, float* __restrict__ out)
{
    int grp  = blockIdx.x * 8 + (threadIdx.x >> 5);
    int lane = threadIdx.x & 31;
    size_t base = (size_t)grp * 64 + lane * 2;
    float2 v = *(const float2*)&in[base];
    float s = fabsf(v.x) + fabsf(v.y);
#pragma unroll
    for (int off = 16; off > 0; off >>= 1) s += __shfl_xor_sync(0xffffffffu, s, off);
    float inv = 1.f / fmaxf(s, 1e-12f);
    float2 o; o.x = v.x * inv; o.y = v.y * inv;
    *(float2*)&out[base] = o;
}

// ---------------- generic SGEMM  C[M,N] = A[M,K] @ W[N,K]^T + bias ----------
// EPI: 0 = clip(MIN_POS), 1 = +res, 2 = gelu(tanh)
__device__ __forceinline__ float gelu_tanh(float v) {
    float t = tanhf(0.7978845608028654f * (v + 0.044715f * v * v * v));
    return 0.5f * v * (1.f + t);
}

template <int EPI>
__global__ __launch_bounds__(256) void sgemm_kernel(
    const float* __restrict__ A, const float* __restrict__ W,
    const float* __restrict__ bias, const float* __restrict__ res,
    float* __restrict__ C, int N, int K)
{
    __shared__ float As[16][132];
    __shared__ float Ws[16][132];
    const int tid = threadIdx.x, tx = tid & 15, ty = tid >> 4;
    const int n0 = blockIdx.x * 128;
    const size_t m0 = (size_t)blockIdx.y * 128;

    float acc[8][8];
#pragma unroll
    for (int r = 0; r < 8; r++)
#pragma unroll
        for (int j = 0; j < 8; j++) acc[r][j] = 0.f;

    for (int kt = 0; kt < K; kt += 16) {
        __syncthreads();
#pragma unroll
        for (int q = 0; q < 2; q++) {
            int lin4 = tid * 2 + q;
            int row  = lin4 >> 2;
            int c4   = (lin4 & 3) << 2;
            float4 va = *(const float4*)&A[(m0 + row) * K + kt + c4];
            As[c4 + 0][row] = va.x; As[c4 + 1][row] = va.y;
            As[c4 + 2][row] = va.z; As[c4 + 3][row] = va.w;
            float4 vw = *(const float4*)&W[(size_t)(n0 + row) * K + kt + c4];
            Ws[c4 + 0][row] = vw.x; Ws[c4 + 1][row] = vw.y;
            Ws[c4 + 2][row] = vw.z; Ws[c4 + 3][row] = vw.w;
        }
        __syncthreads();
#pragma unroll
        for (int k = 0; k < 16; k++) {
            float4 a0 = *(const float4*)&As[k][ty * 4];
            float4 a1 = *(const float4*)&As[k][64 + ty * 4];
            float4 b0 = *(const float4*)&Ws[k][tx * 4];
            float4 b1 = *(const float4*)&Ws[k][64 + tx * 4];
            float av[8] = {a0.x, a0.y, a0.z, a0.w, a1.x, a1.y, a1.z, a1.w};
            float bv[8] = {b0.x, b0.y, b0.z, b0.w, b1.x, b1.y, b1.z, b1.w};
#pragma unroll
            for (int r = 0; r < 8; r++)
#pragma unroll
                for (int j = 0; j < 8; j++) acc[r][j] += av[r] * bv[j];
        }
    }

#pragma unroll
    for (int mi = 0; mi < 2; mi++)
#pragma unroll
        for (int ni = 0; ni < 2; ni++)
#pragma unroll
            for (int r = 0; r < 4; r++) {
                size_t m = m0 + mi * 64 + ty * 4 + r;
                int n = n0 + ni * 64 + tx * 4;
                float4 bi = *(const float4*)&bias[n];
                float vv[4];
#pragma unroll
                for (int j = 0; j < 4; j++) vv[j] = acc[mi * 4 + r][ni * 4 + j];
                vv[0] += bi.x; vv[1] += bi.y; vv[2] += bi.z; vv[3] += bi.w;
                if (EPI == 0) {
#pragma unroll
                    for (int j = 0; j < 4; j++) vv[j] = fmaxf(vv[j], MIN_POS);
                } else if (EPI == 1) {
                    float4 rr = *(const float4*)&res[m * N + n];
                    vv[0] += rr.x; vv[1] += rr.y; vv[2] += rr.z; vv[3] += rr.w;
                } else if (EPI == 2) {
#pragma unroll
                    for (int j = 0; j < 4; j++) vv[j] = gelu_tanh(vv[j]);
                }
                float4 o; o.x = vv[0]; o.y = vv[1]; o.z = vv[2]; o.w = vv[3];
                *(float4*)&C[m * N + n] = o;
            }
}

// ---------------- NNMF kernel A -----------------------------------------
// per (b, head, itile): t1 = Gw^T @ h  (128 x 64 over K=256)
//   r  = l1norm(clip(t1 @ lw))        -> g_r
//   u1 = (xe / r) @ lw^T              -> g_u1
__global__ __launch_bounds__(256) void nnmfA_kernel(
    const float* __restrict__ h, const float* __restrict__ gw,
    const float* __restrict__ lw, const float* __restrict__ xe,
    float* __restrict__ r_out, float* __restrict__ u1_out)
{
    extern __shared__ float sm[];
    float (*As)[128]  = (float(*)[128])(sm);           // 2048
    float (*Bs)[64]   = (float(*)[64])(sm + 2048);     // 1024
    float (*lws)[68]  = (float(*)[68])(sm + 3072);     // 4352
    float (*lwsT)[68] = (float(*)[68])(sm + 7424);     // 4352
    float (*Tst)[132] = (float(*)[132])(sm + 11776);   // 8448
    float* sums = sm + 20224;                           // 128  -> total 20352 floats

    const int tid = threadIdx.x, tx = tid & 15, ty = tid >> 4;
    const int i0 = blockIdx.x * 128, head = blockIdx.y, b = blockIdx.z;

    // local_w + transpose into smem
#pragma unroll
    for (int q = 0; q < 16; q++) {
        int idx = q * 256 + tid;
        int g = idx >> 6, f = idx & 63;
        float v = lw[idx];
        lws[g][f] = v;
        lwsT[f][g] = v;
    }

    const float* hb = h + (((size_t)b * SEQ) * HEADS + head) * 64;  // +o*512+g
    float acc[8][4];
#pragma unroll
    for (int r = 0; r < 8; r++)
#pragma unroll
        for (int j = 0; j < 4; j++) acc[r][j] = 0.f;

    for (int kt = 0; kt < SEQ; kt += 16) {
        __syncthreads();
#pragma unroll
        for (int q = 0; q < 2; q++) {
            int lin = (tid * 2 + q) * 4;
            int k = lin >> 7, m = lin & 127;
            *(float4*)&As[k][m] = *(const float4*)&gw[(kt + k) * SEQ + i0 + m];
        }
        {
            int lin = tid * 4;
            int k = lin >> 6, g = lin & 63;
            *(float4*)&Bs[k][g] = *(const float4*)&hb[(size_t)(kt + k) * 512 + g];
        }
        __syncthreads();
#pragma unroll
        for (int k = 0; k < 16; k++) {
            float4 a0 = *(const float4*)&As[k][ty * 4];
            float4 a1 = *(const float4*)&As[k][64 + ty * 4];
            float4 b0 = *(const float4*)&Bs[k][tx * 4];
            float av[8] = {a0.x, a0.y, a0.z, a0.w, a1.x, a1.y, a1.z, a1.w};
            float bv[4] = {b0.x, b0.y, b0.z, b0.w};
#pragma unroll
            for (int r = 0; r < 8; r++)
#pragma unroll
                for (int j = 0; j < 4; j++) acc[r][j] += av[r] * bv[j];
        }
    }
    __syncthreads();
    // store t1 transposed: Tst[g][i]
#pragma unroll
    for (int r = 0; r < 4; r++)
#pragma unroll
        for (int j = 0; j < 4; j++) {
            Tst[tx * 4 + j][ty * 4 + r]      = acc[r][j];
            Tst[tx * 4 + j][64 + ty * 4 + r] = acc[4 + r][j];
        }
    __syncthreads();

    // mix1: rc[i][f] = sum_g t1[i][g]*lw[g][f], clamp
    float racc[8][4];
#pragma unroll
    for (int r = 0; r < 8; r++)
#pragma unroll
        for (int j = 0; j < 4; j++) racc[r][j] = 0.f;
#pragma unroll 16
    for (int k = 0; k < 64; k++) {
        float4 a0 = *(const float4*)&Tst[k][ty * 4];
        float4 a1 = *(const float4*)&Tst[k][64 + ty * 4];
        float4 b0 = *(const float4*)&lws[k][tx * 4];
        float av[8] = {a0.x, a0.y, a0.z, a0.w, a1.x, a1.y, a1.z, a1.w};
        float bv[4] = {b0.x, b0.y, b0.z, b0.w};
#pragma unroll
        for (int r = 0; r < 8; r++)
#pragma unroll
            for (int j = 0; j < 4; j++) racc[r][j] += av[r] * bv[j];
    }
#pragma unroll
    for (int r = 0; r < 8; r++)
#pragma unroll
        for (int j = 0; j < 4; j++) racc[r][j] = fmaxf(racc[r][j], MIN_POS);

    // row sums across tx via shuffle (16-lane groups)
    float rp[8];
#pragma unroll
    for (int r = 0; r < 8; r++) rp[r] = racc[r][0] + racc[r][1] + racc[r][2] + racc[r][3];
#pragma unroll
    for (int off = 1; off < 16; off <<= 1)
#pragma unroll
        for (int r = 0; r < 8; r++) rp[r] += __shfl_xor_sync(0xffffffffu, rp[r], off);
    if (tx == 0) {
#pragma unroll
        for (int r = 0; r < 4; r++) {
            sums[ty * 4 + r]      = rp[r];
            sums[64 + ty * 4 + r] = rp[4 + r];
        }
    }
    __syncthreads();

    // r_out = rc/s ; xr = xe * s / rc, stored transposed into Tst[f][i]
    const size_t rowbase = (((size_t)b * SEQ + i0) * HEADS + head) * 64;
#pragma unroll
    for (int mi = 0; mi < 2; mi++)
#pragma unroll
        for (int r = 0; r < 4; r++) {
            int m = mi * 64 + ty * 4 + r;
            float s = sums[m];
            float4 xev = *(const float4*)&xe[rowbase + (size_t)m * 512 + tx * 4];
            float rc0 = racc[mi * 4 + r][0], rc1 = racc[mi * 4 + r][1];
            float rc2 = racc[mi * 4 + r][2], rc3 = racc[mi * 4 + r][3];
            float invs = 1.f / s;
            float4 rv; rv.x = rc0 * invs; rv.y = rc1 * invs; rv.z = rc2 * invs; rv.w = rc3 * invs;
            *(float4*)&r_out[rowbase + (size_t)m * 512 + tx * 4] = rv;
            Tst[tx * 4 + 0][m] = xev.x * s / rc0;
            Tst[tx * 4 + 1][m] = xev.y * s / rc1;
            Tst[tx * 4 + 2][m] = xev.z * s / rc2;
            Tst[tx * 4 + 3][m] = xev.w * s / rc3;
        }
    __syncthreads();

    // mix2: u1[i][g] = sum_f xr[i][f]*lw[g][f]
    float uacc[8][4];
#pragma unroll
    for (int r = 0; r < 8; r++)
#pragma unroll
        for (int j = 0; j < 4; j++) uacc[r][j] = 0.f;
#pragma unroll 16
    for (int k = 0; k < 64; k++) {
        float4 a0 = *(const float4*)&Tst[k][ty * 4];
        float4 a1 = *(const float4*)&Tst[k][64 + ty * 4];
        float4 b0 = *(const float4*)&lwsT[k][tx * 4];
        float av[8] = {a0.x, a0.y, a0.z, a0.w, a1.x, a1.y, a1.z, a1.w};
        float bv[4] = {b0.x, b0.y, b0.z, b0.w};
#pragma unroll
        for (int r = 0; r < 8; r++)
#pragma unroll
            for (int j = 0; j < 4; j++) uacc[r][j] += av[r] * bv[j];
    }
#pragma unroll
    for (int mi = 0; mi < 2; mi++)
#pragma unroll
        for (int r = 0; r < 4; r++) {
            int m = mi * 64 + ty * 4 + r;
            float4 o;
            o.x = uacc[mi * 4 + r][0]; o.y = uacc[mi * 4 + r][1];
            o.z = uacc[mi * 4 + r][2]; o.w = uacc[mi * 4 + r][3];
            *(float4*)&u1_out[rowbase + (size_t)m * 512 + tx * 4] = o;
        }
}

// ---------------- NNMF kernel B -----------------------------------------
// per (b, head, otile): u2 = Gw @ u1 ; h <- l1norm(clip(h * u2))
__global__ __launch_bounds__(256) void nnmfB_kernel(
    const float* __restrict__ u1, const float* __restrict__ gw,
    const float* __restrict__ h_in, float* __restrict__ h_out)
{
    __shared__ float As[16][132];
    __shared__ float Bs[16][64];
    __shared__ float sums[128];

    const int tid = threadIdx.x, tx = tid & 15, ty = tid >> 4;
    const int o0 = blockIdx.x * 128, head = blockIdx.y, b = blockIdx.z;

    const float* ub = u1 + (((size_t)b * SEQ) * HEADS + head) * 64;
    float acc[8][4];
#pragma unroll
    for (int r = 0; r < 8; r++)
#pragma unroll
        for (int j = 0; j < 4; j++) acc[r][j] = 0.f;

    for (int kt = 0; kt < SEQ; kt += 16) {
        __syncthreads();
#pragma unroll
        for (int q = 0; q < 2; q++) {
            int lin4 = tid * 2 + q;
            int row = lin4 >> 2;
            int c4 = (lin4 & 3) << 2;
            float4 v = *(const float4*)&gw[(o0 + row) * SEQ + kt + c4];
            As[c4 + 0][row] = v.x; As[c4 + 1][row] = v.y;
            As[c4 + 2][row] = v.z; As[c4 + 3][row] = v.w;
        }
        {
            int lin = tid * 4;
            int k = lin >> 6, g = lin & 63;
            *(float4*)&Bs[k][g] = *(const float4*)&ub[(size_t)(kt + k) * 512 + g];
        }
        __syncthreads();
#pragma unroll
        for (int k = 0; k < 16; k++) {
            float4 a0 = *(const float4*)&As[k][ty * 4];
            float4 a1 = *(const float4*)&As[k][64 + ty * 4];
            float4 b0 = *(const float4*)&Bs[k][tx * 4];
            float av[8] = {a0.x, a0.y, a0.z, a0.w, a1.x, a1.y, a1.z, a1.w};
            float bv[4] = {b0.x, b0.y, b0.z, b0.w};
#pragma unroll
            for (int r = 0; r < 8; r++)
#pragma unroll
                for (int j = 0; j < 4; j++) acc[r][j] += av[r] * bv[j];
        }
    }

    const size_t rowbase = (((size_t)b * SEQ + o0) * HEADS + head) * 64;
    float hv[8][4];
#pragma unroll
    for (int mi = 0; mi < 2; mi++)
#pragma unroll
        for (int r = 0; r < 4; r++) {
            int m = mi * 64 + ty * 4 + r;
            float4 hl = *(const float4*)&h_in[rowbase + (size_t)m * 512 + tx * 4];
            hv[mi * 4 + r][0] = fmaxf(hl.x * acc[mi * 4 + r][0], MIN_POS);
            hv[mi * 4 + r][1] = fmaxf(hl.y * acc[mi * 4 + r][1], MIN_POS);
            hv[mi * 4 + r][2] = fmaxf(hl.z * acc[mi * 4 + r][2], MIN_POS);
            hv[mi * 4 + r][3] = fmaxf(hl.w * acc[mi * 4 + r][3], MIN_POS);
        }
    float rp[8];
#pragma unroll
    for (int r = 0; r < 8; r++) rp[r] = hv[r][0] + hv[r][1] + hv[r][2] + hv[r][3];
#pragma unroll
    for (int off = 1; off < 16; off <<= 1)
#pragma unroll
        for (int r = 0; r < 8; r++) rp[r] += __shfl_xor_sync(0xffffffffu, rp[r], off);
    if (tx == 0) {
#pragma unroll
        for (int r = 0; r < 4; r++) {
            sums[ty * 4 + r]      = rp[r];
            sums[64 + ty * 4 + r] = rp[4 + r];
        }
    }
    __syncthreads();
#pragma unroll
    for (int mi = 0; mi < 2; mi++)
#pragma unroll
        for (int r = 0; r < 4; r++) {
            int m = mi * 64 + ty * 4 + r;
            float inv = 1.f / sums[m];
            float4 o;
            o.x = hv[mi * 4 + r][0] * inv; o.y = hv[mi * 4 + r][1] * inv;
            o.z = hv[mi * 4 + r][2] * inv; o.w = hv[mi * 4 + r][3] * inv;
            *(float4*)&h_out[rowbase + (size_t)m * 512 + tx * 4] = o;
        }
}

// ---------------- host launcher ------------------------------------------
extern "C" void kernel_launch(void* const* d_in, const int* in_sizes, int n_in,
                              void* d_out, int out_size)
{
    const float* x    = (const float*)d_in[0];
    const float* ew   = (const float*)d_in[1];
    const float* eb   = (const float*)d_in[2];
    const float* lw   = (const float*)d_in[3];
    const float* gw   = (const float*)d_in[4];
    const float* ow   = (const float*)d_in[5];
    const float* ob   = (const float*)d_in[6];
    const float* ln1g = (const float*)d_in[7];
    const float* ln1b = (const float*)d_in[8];
    const float* ln2g = (const float*)d_in[9];
    const float* ln2b = (const float*)d_in[10];
    const float* w1   = (const float*)d_in[11];
    const float* b1   = (const float*)d_in[12];
    const float* w2   = (const float*)d_in[13];
    const float* b2   = (const float*)d_in[14];
    const float* h0   = (const float*)d_in[15];
    float* out = (float*)d_out;

    float *xn, *xe, *h, *u1, *r, *xres, *mlp;
    cudaGetSymbolAddress((void**)&xn,   g_xn);
    cudaGetSymbolAddress((void**)&xe,   g_xe);
    cudaGetSymbolAddress((void**)&h,    g_h);
    cudaGetSymbolAddress((void**)&u1,   g_u1);
    cudaGetSymbolAddress((void**)&r,    g_r);
    cudaGetSymbolAddress((void**)&xres, g_xres);
    cudaGetSymbolAddress((void**)&mlp,  g_mlp);

    const int A_SMEM = 20352 * 4;  // bytes of dynamic smem for nnmfA
    cudaFuncSetAttribute(nnmfA_kernel, cudaFuncAttributeMaxDynamicSharedMemorySize, A_SMEM);

    // 1. LN1
    ln_kernel<<<BSROWS / 8, 256>>>(x, ln1g, ln1b, xn);
    // 2. embed + clip  (raw into u1 buffer)
    sgemm_kernel<0><<<dim3(EDIM / 128, BSROWS / 128), 256>>>(xn, ew, eb, nullptr, u1, EDIM, FDIM);
    // 3. per-head L1 normalize -> xe
    l1norm64_kernel<<<BSROWS * HEADS / 8, 256>>>(u1, xe);
    // 4. NNMF iterations
    for (int it = 0; it < 10; it++) {
        const float* hcur = (it == 0) ? h0 : h;
        nnmfA_kernel<<<dim3(2, HEADS, BSZ), 256, A_SMEM>>>(hcur, gw, lw, xe, r, u1);
        if (it < 9)
            nnmfB_kernel<<<dim3(2, HEADS, BSZ), 256>>>(u1, gw, hcur, h);
    }
    // 5. out projection + residual with x
    sgemm_kernel<1><<<dim3(FDIM / 128, BSROWS / 128), 256>>>(r, ow, ob, x, xres, FDIM, EDIM);
    // 6. LN2
    ln_kernel<<<BSROWS / 8, 256>>>(xres, ln2g, ln2b, xn);
    // 7. MLP up + gelu
    sgemm_kernel<2><<<dim3(MLPD / 128, BSROWS / 128), 256>>>(xn, w1, b1, nullptr, mlp, MLPD, FDIM);
    // 8. MLP down + residual -> out
    sgemm_kernel<1><<<dim3(FDIM / 128, BSROWS / 128), 256>>>(mlp, w2, b2, xres, out, FDIM, MLPD);
}

// round 4
// speedup vs baseline: 2.0813x; 2.0813x over previous
#include <cuda_runtime.h>
#include <cstdint>

#define BSZ   128
#define SEQ   256
#define FDIM  512
#define EDIM  512
#define HEADS 8
#define BSROWS (BSZ*SEQ)
#define MLPD  2048
#define MIN_POS 1e-6f

__device__ float g_xn  [(size_t)BSROWS*FDIM];
__device__ float g_xe  [(size_t)BSROWS*EDIM];
__device__ float g_h   [(size_t)BSROWS*EDIM];   // h  [b,o,e]
__device__ float g_hT  [(size_t)BSROWS*EDIM];   // hT [b,e,o]
__device__ float g_u1T [(size_t)BSROWS*EDIM];   // u1T[b,e,i]
__device__ float g_t1  [(size_t)BSROWS*EDIM];   // t1 [b,i,e] / raw embed temp
__device__ float g_u2  [(size_t)BSROWS*EDIM];   // u2 [b,o,e]
__device__ float g_r   [(size_t)BSROWS*EDIM];
__device__ float g_xres[(size_t)BSROWS*FDIM];
__device__ float g_mlp [(size_t)BSROWS*MLPD];
__device__ float g_gwT [(size_t)SEQ*SEQ];

// ---------------- helpers -----------------------------------------------------
__device__ __forceinline__ uint32_t s2u(const void* p) {
    uint32_t a;
    asm("{ .reg .u64 t; cvta.to.shared.u64 t, %1; cvt.u32.u64 %0, t; }" : "=r"(a) : "l"(p));
    return a;
}
#define CP16(dst, src) \
    asm volatile("cp.async.cg.shared.global [%0], [%1], 16;" :: "r"(dst), "l"(src))
#define CP_COMMIT() asm volatile("cp.async.commit_group;" ::: "memory")
#define CP_WAIT(n)  asm volatile("cp.async.wait_group %0;" :: "n"(n) : "memory")

__device__ __forceinline__ void mma_tf32(float* c, const uint32_t* a, const uint32_t* b) {
    asm volatile(
        "mma.sync.aligned.m16n8k8.row.col.f32.tf32.tf32.f32 "
        "{%0,%1,%2,%3}, {%4,%5,%6,%7}, {%8,%9}, {%0,%1,%2,%3};"
        : "+f"(c[0]), "+f"(c[1]), "+f"(c[2]), "+f"(c[3])
        : "r"(a[0]), "r"(a[1]), "r"(a[2]), "r"(a[3]), "r"(b[0]), "r"(b[1]));
}

static __device__ __forceinline__ float gelu_tanh(float v) {
    float t = tanhf(0.7978845608028654f * (v + 0.044715f * v * v * v));
    return 0.5f * v * (1.f + t);
}

// ---------------- tf32 mma.sync GEMM: C[M,N]=A[M,K]@B[N,K]^T (+bias)(+epi) ----
// block tile 128x128, K-chunk 32, cp.async double buffer.
// EPI: 0=bias+clip 1=bias+res 2=bias+gelu 3=none
#define SMP 36                 // padded K-stride in smem
#define STG (128*SMP)          // floats per stage per operand
#define MM_SMEM (4*STG*4)      // bytes: 2 operands x 2 stages

template <int EPI>
__global__ __launch_bounds__(256) void mma_gemm(
    const float* __restrict__ A, const float* __restrict__ B,
    const float* __restrict__ bias, const float* __restrict__ res,
    float* __restrict__ C, int K, int N,
    long long sB, long long sC)
{
    extern __shared__ float sm[];
    float* As = sm;            // [2][128][36]
    float* Bs = sm + 2 * STG;  // [2][128][36]
    const int tid = threadIdx.x, wid = tid >> 5, lane = tid & 31;
    const int grp = lane >> 2, qid = lane & 3;
    const int n0 = blockIdx.x * 128;
    const size_t m0 = (size_t)blockIdx.y * 128;
    B += (size_t)blockIdx.z * sB;
    C += (size_t)blockIdx.z * sC;
    if (EPI == 1) res += (size_t)blockIdx.z * sC;
    const int wm = (wid & 1) * 64, wn = (wid >> 1) * 32;

    const uint32_t sA = s2u(As), sBb = s2u(Bs);

    // async load one 128x32 chunk of A and B into stage s
    auto load_chunk = [&](int s, int kt) {
#pragma unroll
        for (int i = 0; i < 4; i++) {
            int id = tid + 256 * i;
            int row = id >> 3, kq = (id & 7) * 4;
            CP16(sA + (uint32_t)(s * STG + row * SMP + kq) * 4,
                 &A[(m0 + row) * K + kt + kq]);
        }
#pragma unroll
        for (int i = 0; i < 4; i++) {
            int id = tid + 256 * i;
            int row = id >> 3, kq = (id & 7) * 4;
            CP16(sBb + (uint32_t)(s * STG + row * SMP + kq) * 4,
                 &B[(size_t)(n0 + row) * K + kt + kq]);
        }
    };

    float cfr[4][4][4];
#pragma unroll
    for (int mt = 0; mt < 4; mt++)
#pragma unroll
        for (int nt = 0; nt < 4; nt++)
#pragma unroll
            for (int i = 0; i < 4; i++) cfr[mt][nt][i] = 0.f;

    const int nch = K >> 5;
    load_chunk(0, 0);
    CP_COMMIT();

    for (int c = 0; c < nch; c++) {
        if (c + 1 < nch) {
            load_chunk((c + 1) & 1, (c + 1) * 32);
            CP_COMMIT();
            CP_WAIT(1);
        } else {
            CP_WAIT(0);
        }
        __syncthreads();
        const float* as = As + (c & 1) * STG;
        const float* bs = Bs + (c & 1) * STG;
#pragma unroll
        for (int kk = 0; kk < 32; kk += 8) {
            uint32_t af[4][4], bf[4][2];
#pragma unroll
            for (int mt = 0; mt < 4; mt++) {
                int row = wm + mt * 16 + grp;
                af[mt][0] = __float_as_uint(as[row * SMP + kk + qid]);
                af[mt][1] = __float_as_uint(as[(row + 8) * SMP + kk + qid]);
                af[mt][2] = __float_as_uint(as[row * SMP + kk + 4 + qid]);
                af[mt][3] = __float_as_uint(as[(row + 8) * SMP + kk + 4 + qid]);
            }
#pragma unroll
            for (int nt = 0; nt < 4; nt++) {
                int col = wn + nt * 8 + grp;
                bf[nt][0] = __float_as_uint(bs[col * SMP + kk + qid]);
                bf[nt][1] = __float_as_uint(bs[col * SMP + kk + 4 + qid]);
            }
#pragma unroll
            for (int mt = 0; mt < 4; mt++)
#pragma unroll
                for (int nt = 0; nt < 4; nt++)
                    mma_tf32(cfr[mt][nt], af[mt], bf[nt]);
        }
        __syncthreads();
    }

    // epilogue
#pragma unroll
    for (int mt = 0; mt < 4; mt++) {
        const size_t r0 = m0 + wm + mt * 16 + grp;
#pragma unroll
        for (int nt = 0; nt < 4; nt++) {
            const int col = n0 + wn + nt * 8 + qid * 2;
            float bx = 0.f, by = 0.f;
            if (EPI != 3) {
                float2 bv = *(const float2*)&bias[col];
                bx = bv.x; by = bv.y;
            }
            float v0 = cfr[mt][nt][0] + bx, v1 = cfr[mt][nt][1] + by;
            float v2 = cfr[mt][nt][2] + bx, v3 = cfr[mt][nt][3] + by;
            if (EPI == 0) {
                v0 = fmaxf(v0, MIN_POS); v1 = fmaxf(v1, MIN_POS);
                v2 = fmaxf(v2, MIN_POS); v3 = fmaxf(v3, MIN_POS);
            } else if (EPI == 1) {
                float2 ra = *(const float2*)&res[r0 * N + col];
                float2 rb = *(const float2*)&res[(r0 + 8) * N + col];
                v0 += ra.x; v1 += ra.y; v2 += rb.x; v3 += rb.y;
            } else if (EPI == 2) {
                v0 = gelu_tanh(v0); v1 = gelu_tanh(v1);
                v2 = gelu_tanh(v2); v3 = gelu_tanh(v3);
            }
            float2 o0; o0.x = v0; o0.y = v1;
            float2 o1; o1.x = v2; o1.y = v3;
            *(float2*)&C[r0 * N + col] = o0;
            *(float2*)&C[(r0 + 8) * N + col] = o1;
        }
    }
}

// ---------------- batched transpose [R,C] -> [C,R] ---------------------------
__global__ void transpose_kernel(
    const float* __restrict__ in, float* __restrict__ out, int R, int C)
{
    __shared__ float t[32][33];
    in  += (size_t)blockIdx.z * R * C;
    out += (size_t)blockIdx.z * R * C;
    int r0 = blockIdx.y * 32, c0 = blockIdx.x * 32;
    int lx = threadIdx.x, ly = threadIdx.y;
#pragma unroll
    for (int i = 0; i < 32; i += 8) t[ly + i][lx] = in[(size_t)(r0 + ly + i) * C + c0 + lx];
    __syncthreads();
#pragma unroll
    for (int i = 0; i < 32; i += 8) out[(size_t)(c0 + ly + i) * R + r0 + lx] = t[lx][ly + i];
}

// ---------------- LayerNorm ---------------------------------------------------
__global__ __launch_bounds__(256) void ln_kernel(
    const float* __restrict__ x, const float* __restrict__ g,
    const float* __restrict__ b, float* __restrict__ out)
{
    int row  = blockIdx.x * 8 + (threadIdx.x >> 5);
    int lane = threadIdx.x & 31;
    const float* xr = x + (size_t)row * 512;
    float4 v[4];
    float s = 0.f, sq = 0.f;
#pragma unroll
    for (int w = 0; w < 4; w++) {
        v[w] = *(const float4*)&xr[w * 128 + lane * 4];
        s  += v[w].x + v[w].y + v[w].z + v[w].w;
        sq += v[w].x*v[w].x + v[w].y*v[w].y + v[w].z*v[w].z + v[w].w*v[w].w;
    }
#pragma unroll
    for (int off = 16; off > 0; off >>= 1) {
        s  += __shfl_xor_sync(0xffffffffu, s,  off);
        sq += __shfl_xor_sync(0xffffffffu, sq, off);
    }
    float mu = s * (1.f / 512.f);
    float var = sq * (1.f / 512.f) - mu * mu;
    float rstd = rsqrtf(var + 1e-5f);
    float* orow = out + (size_t)row * 512;
#pragma unroll
    for (int w = 0; w < 4; w++) {
        int c = w * 128 + lane * 4;
        float4 gv = *(const float4*)&g[c];
        float4 bv = *(const float4*)&b[c];
        float4 o;
        o.x = (v[w].x - mu) * rstd * gv.x + bv.x;
        o.y = (v[w].y - mu) * rstd * gv.y + bv.y;
        o.z = (v[w].z - mu) * rstd * gv.z + bv.z;
        o.w = (v[w].w - mu) * rstd * gv.w + bv.w;
        *(float4*)&orow[c] = o;
    }
}

__global__ __launch_bounds__(256) void l1norm64_kernel(
    const float* __restrict__ in, float* __restrict__ out)
{
    int grp  = blockIdx.x * 8 + (threadIdx.x >> 5);
    int lane = threadIdx.x & 31;
    size_t base = (size_t)grp * 64 + lane * 2;
    float2 v = *(const float2*)&in[base];
    float s = fabsf(v.x) + fabsf(v.y);
#pragma unroll
    for (int off = 16; off > 0; off >>= 1) s += __shfl_xor_sync(0xffffffffu, s, off);
    float inv = 1.f / fmaxf(s, 1e-12f);
    float2 o; o.x = v.x * inv; o.y = v.y * inv;
    *(float2*)&out[base] = o;
}

// ---------------- NNMF A lite: local mixes around t1 -------------------------
// reads t1[b,i,e]; writes r[b,i,e], u1T[b,e,i]
__global__ __launch_bounds__(256) void nnmfA_lite(
    const float* __restrict__ t1, const float* __restrict__ lw,
    const float* __restrict__ xe, float* __restrict__ r_out,
    float* __restrict__ u1T)
{
    extern __shared__ float smf[];
    float (*lws)[68]  = (float(*)[68])(smf);
    float (*lwsT)[68] = (float(*)[68])(smf + 4352);
    float (*Tst)[132] = (float(*)[132])(smf + 8704);
    float* sums = smf + 17152;   // total 17280 floats

    const int tid = threadIdx.x, tx = tid & 15, ty = tid >> 4;
    const int i0 = blockIdx.x * 128, head = blockIdx.y, b = blockIdx.z;

#pragma unroll
    for (int q = 0; q < 16; q++) {
        int idx = q * 256 + tid;
        int g = idx >> 6, f = idx & 63;
        float v = lw[idx];
        lws[g][f] = v;
        lwsT[f][g] = v;
    }

    const size_t base = ((size_t)b * SEQ + i0) * 512 + head * 64;
    // t1 tile -> Tst transposed [g][i]
#pragma unroll
    for (int a = 0; a < 8; a++) {
        int m = (a >> 2) * 64 + ty * 4 + (a & 3);
        float4 v = *(const float4*)&t1[base + (size_t)m * 512 + tx * 4];
        Tst[tx*4+0][m] = v.x; Tst[tx*4+1][m] = v.y;
        Tst[tx*4+2][m] = v.z; Tst[tx*4+3][m] = v.w;
    }
    __syncthreads();

    // mix1: rc[i][f] = sum_g t1[i][g]*lw[g][f], clamp
    float racc[8][4];
#pragma unroll
    for (int r = 0; r < 8; r++)
#pragma unroll
        for (int j = 0; j < 4; j++) racc[r][j] = 0.f;
#pragma unroll 16
    for (int k = 0; k < 64; k++) {
        float4 a0 = *(const float4*)&Tst[k][ty * 4];
        float4 a1 = *(const float4*)&Tst[k][64 + ty * 4];
        float4 b0 = *(const float4*)&lws[k][tx * 4];
        float av[8] = {a0.x, a0.y, a0.z, a0.w, a1.x, a1.y, a1.z, a1.w};
        float bv[4] = {b0.x, b0.y, b0.z, b0.w};
#pragma unroll
        for (int r = 0; r < 8; r++)
#pragma unroll
            for (int j = 0; j < 4; j++) racc[r][j] += av[r] * bv[j];
    }
#pragma unroll
    for (int r = 0; r < 8; r++)
#pragma unroll
        for (int j = 0; j < 4; j++) racc[r][j] = fmaxf(racc[r][j], MIN_POS);

    float rp[8];
#pragma unroll
    for (int r = 0; r < 8; r++) rp[r] = racc[r][0] + racc[r][1] + racc[r][2] + racc[r][3];
#pragma unroll
    for (int off = 1; off < 16; off <<= 1)
#pragma unroll
        for (int r = 0; r < 8; r++) rp[r] += __shfl_xor_sync(0xffffffffu, rp[r], off);
    if (tx == 0) {
#pragma unroll
        for (int r = 0; r < 4; r++) {
            sums[ty * 4 + r]      = rp[r];
            sums[64 + ty * 4 + r] = rp[4 + r];
        }
    }
    __syncthreads();

    // r = rc/s ; xr = xe*s/rc -> Tst[f][i]
#pragma unroll
    for (int mi = 0; mi < 2; mi++)
#pragma unroll
        for (int r = 0; r < 4; r++) {
            int m = mi * 64 + ty * 4 + r;
            float s = sums[m];
            float4 xev = *(const float4*)&xe[base + (size_t)m * 512 + tx * 4];
            float rc0 = racc[mi*4+r][0], rc1 = racc[mi*4+r][1];
            float rc2 = racc[mi*4+r][2], rc3 = racc[mi*4+r][3];
            float invs = 1.f / s;
            float4 rv; rv.x = rc0*invs; rv.y = rc1*invs; rv.z = rc2*invs; rv.w = rc3*invs;
            *(float4*)&r_out[base + (size_t)m * 512 + tx * 4] = rv;
            Tst[tx*4+0][m] = xev.x * s / rc0;
            Tst[tx*4+1][m] = xev.y * s / rc1;
            Tst[tx*4+2][m] = xev.z * s / rc2;
            Tst[tx*4+3][m] = xev.w * s / rc3;
        }
    __syncthreads();

    // mix2: u1[i][g] = sum_f xr[i][f]*lw[g][f]
    float uacc[8][4];
#pragma unroll
    for (int r = 0; r < 8; r++)
#pragma unroll
        for (int j = 0; j < 4; j++) uacc[r][j] = 0.f;
#pragma unroll 16
    for (int k = 0; k < 64; k++) {
        float4 a0 = *(const float4*)&Tst[k][ty * 4];
        float4 a1 = *(const float4*)&Tst[k][64 + ty * 4];
        float4 b0 = *(const float4*)&lwsT[k][tx * 4];
        float av[8] = {a0.x, a0.y, a0.z, a0.w, a1.x, a1.y, a1.z, a1.w};
        float bv[4] = {b0.x, b0.y, b0.z, b0.w};
#pragma unroll
        for (int r = 0; r < 8; r++)
#pragma unroll
            for (int j = 0; j < 4; j++) uacc[r][j] += av[r] * bv[j];
    }
    __syncthreads();
    // stage u1 transposed [g][i] for coalesced u1T store
#pragma unroll
    for (int a = 0; a < 8; a++) {
        int m = (a >> 2) * 64 + ty * 4 + (a & 3);
#pragma unroll
        for (int j = 0; j < 4; j++) Tst[tx * 4 + j][m] = uacc[a][j];
    }
    __syncthreads();
    const size_t ubase = ((size_t)b * 512 + head * 64) * 256 + i0;
#pragma unroll
    for (int q = 0; q < 8; q++) {
        int idx = q * 1024 + tid * 4;
        int g = idx >> 7, m = idx & 127;
        float4 v = *(const float4*)&Tst[g][m];
        *(float4*)&u1T[ubase + (size_t)g * 256 + m] = v;
    }
}

// ---------------- NNMF B lite: h <- l1norm(clip(h*u2)), writes h and hT ------
__global__ __launch_bounds__(256) void nnmfB_lite(
    const float* __restrict__ u2, const float* __restrict__ h_in,
    float* __restrict__ h_out, float* __restrict__ hT)
{
    __shared__ float Ts[64][132];
    __shared__ float sums[128];
    const int tid = threadIdx.x, tx = tid & 15, ty = tid >> 4;
    const int o0 = blockIdx.x * 128, head = blockIdx.y, b = blockIdx.z;
    const size_t base = ((size_t)b * SEQ + o0) * 512 + head * 64;

    float hv[8][4];
#pragma unroll
    for (int a = 0; a < 8; a++) {
        int m = (a >> 2) * 64 + ty * 4 + (a & 3);
        float4 uv = *(const float4*)&u2[base + (size_t)m * 512 + tx * 4];
        float4 hl = *(const float4*)&h_in[base + (size_t)m * 512 + tx * 4];
        hv[a][0] = fmaxf(hl.x * uv.x, MIN_POS);
        hv[a][1] = fmaxf(hl.y * uv.y, MIN_POS);
        hv[a][2] = fmaxf(hl.z * uv.z, MIN_POS);
        hv[a][3] = fmaxf(hl.w * uv.w, MIN_POS);
    }
    float rp[8];
#pragma unroll
    for (int r = 0; r < 8; r++) rp[r] = hv[r][0] + hv[r][1] + hv[r][2] + hv[r][3];
#pragma unroll
    for (int off = 1; off < 16; off <<= 1)
#pragma unroll
        for (int r = 0; r < 8; r++) rp[r] += __shfl_xor_sync(0xffffffffu, rp[r], off);
    if (tx == 0) {
#pragma unroll
        for (int r = 0; r < 4; r++) {
            sums[ty * 4 + r]      = rp[r];
            sums[64 + ty * 4 + r] = rp[4 + r];
        }
    }
    __syncthreads();
#pragma unroll
    for (int a = 0; a < 8; a++) {
        int m = (a >> 2) * 64 + ty * 4 + (a & 3);
        float inv = 1.f / sums[m];
        float4 o;
        o.x = hv[a][0]*inv; o.y = hv[a][1]*inv; o.z = hv[a][2]*inv; o.w = hv[a][3]*inv;
        *(float4*)&h_out[base + (size_t)m * 512 + tx * 4] = o;
        Ts[tx*4+0][m] = o.x; Ts[tx*4+1][m] = o.y; Ts[tx*4+2][m] = o.z; Ts[tx*4+3][m] = o.w;
    }
    __syncthreads();
    const size_t tb = ((size_t)b * 512 + head * 64) * 256 + o0;
#pragma unroll
    for (int q = 0; q < 8; q++) {
        int idx = q * 1024 + tid * 4;
        int g = idx >> 7, m = idx & 127;
        float4 v = *(const float4*)&Ts[g][m];
        *(float4*)&hT[tb + (size_t)g * 256 + m] = v;
    }
}

// ---------------- host launcher -----------------------------------------------
extern "C" void kernel_launch(void* const* d_in, const int* in_sizes, int n_in,
                              void* d_out, int out_size)
{
    const float* x    = (const float*)d_in[0];
    const float* ew   = (const float*)d_in[1];
    const float* eb   = (const float*)d_in[2];
    const float* lw   = (const float*)d_in[3];
    const float* gw   = (const float*)d_in[4];
    const float* ow   = (const float*)d_in[5];
    const float* ob   = (const float*)d_in[6];
    const float* ln1g = (const float*)d_in[7];
    const float* ln1b = (const float*)d_in[8];
    const float* ln2g = (const float*)d_in[9];
    const float* ln2b = (const float*)d_in[10];
    const float* w1   = (const float*)d_in[11];
    const float* b1   = (const float*)d_in[12];
    const float* w2   = (const float*)d_in[13];
    const float* b2   = (const float*)d_in[14];
    const float* h0   = (const float*)d_in[15];
    float* out = (float*)d_out;

    float *xn, *xe, *h, *hT, *u1T, *t1, *u2, *r, *xres, *mlp, *gwT;
    cudaGetSymbolAddress((void**)&xn,   g_xn);
    cudaGetSymbolAddress((void**)&xe,   g_xe);
    cudaGetSymbolAddress((void**)&h,    g_h);
    cudaGetSymbolAddress((void**)&hT,   g_hT);
    cudaGetSymbolAddress((void**)&u1T,  g_u1T);
    cudaGetSymbolAddress((void**)&t1,   g_t1);
    cudaGetSymbolAddress((void**)&u2,   g_u2);
    cudaGetSymbolAddress((void**)&r,    g_r);
    cudaGetSymbolAddress((void**)&xres, g_xres);
    cudaGetSymbolAddress((void**)&mlp,  g_mlp);
    cudaGetSymbolAddress((void**)&gwT,  g_gwT);

    cudaFuncSetAttribute(mma_gemm<0>, cudaFuncAttributeMaxDynamicSharedMemorySize, MM_SMEM);
    cudaFuncSetAttribute(mma_gemm<1>, cudaFuncAttributeMaxDynamicSharedMemorySize, MM_SMEM);
    cudaFuncSetAttribute(mma_gemm<2>, cudaFuncAttributeMaxDynamicSharedMemorySize, MM_SMEM);
    cudaFuncSetAttribute(mma_gemm<3>, cudaFuncAttributeMaxDynamicSharedMemorySize, MM_SMEM);
    const int A_SMEM = 17280 * 4;
    cudaFuncSetAttribute(nnmfA_lite, cudaFuncAttributeMaxDynamicSharedMemorySize, A_SMEM);

    const long long SB = 512LL * 256;   // hT/u1T per-batch stride
    const long long SC = 256LL * 512;   // t1/u2 per-batch stride

    ln_kernel<<<BSROWS / 8, 256>>>(x, ln1g, ln1b, xn);
    // embed + clip (raw into t1 temp)
    mma_gemm<0><<<dim3(4, 256, 1), 256, MM_SMEM>>>(xn, ew, eb, nullptr, t1, 512, 512, 0, 0);
    l1norm64_kernel<<<BSROWS * HEADS / 8, 256>>>(t1, xe);
    transpose_kernel<<<dim3(8, 8, 1), dim3(32, 8)>>>(gw, gwT, 256, 256);
    transpose_kernel<<<dim3(16, 8, 128), dim3(32, 8)>>>(h0, hT, 256, 512);

    for (int it = 0; it < 10; it++) {
        // t1[b,i,e] = gwT[i,:] . hT[b,e,:]   (M=256, N=512, K=256)
        mma_gemm<3><<<dim3(4, 2, 128), 256, MM_SMEM>>>(gwT, hT, nullptr, nullptr, t1, 256, 512, SB, SC);
        nnmfA_lite<<<dim3(2, HEADS, BSZ), 256, A_SMEM>>>(t1, lw, xe, r, u1T);
        if (it < 9) {
            // u2[b,o,e] = gw[o,:] . u1T[b,e,:]
            mma_gemm<3><<<dim3(4, 2, 128), 256, MM_SMEM>>>(gw, u1T, nullptr, nullptr, u2, 256, 512, SB, SC);
            nnmfB_lite<<<dim3(2, HEADS, BSZ), 256>>>(u2, (it == 0) ? h0 : h, h, hT);
        }
    }

    // out projection + residual with x
    mma_gemm<1><<<dim3(4, 256, 1), 256, MM_SMEM>>>(r, ow, ob, x, xres, 512, 512, 0, 0);
    ln_kernel<<<BSROWS / 8, 256>>>(xres, ln2g, ln2b, xn);
    // MLP up + gelu
    mma_gemm<2><<<dim3(16, 256, 1), 256, MM_SMEM>>>(xn, w1, b1, nullptr, mlp, 512, 2048, 0, 0);
    // MLP down + residual -> out
    mma_gemm<1><<<dim3(4, 256, 1), 256, MM_SMEM>>>(mlp, w2, b2, xres, out, 2048, 512, 0, 0);
}

// round 5
// speedup vs baseline: 2.2171x; 1.0652x over previous
#include <cuda_runtime.h>
#include <cstdint>

#define BSZ   128
#define SEQ   256
#define FDIM  512
#define EDIM  512
#define HEADS 8
#define BSROWS (BSZ*SEQ)
#define MLPD  2048
#define MIN_POS 1e-6f

__device__ float g_xn  [(size_t)BSROWS*FDIM];
__device__ float g_xe  [(size_t)BSROWS*EDIM];
__device__ float g_h   [(size_t)BSROWS*EDIM];   // h  [b,o,e]
__device__ float g_hT  [(size_t)BSROWS*EDIM];   // hT [b,e,o] (tf32-rounded)
__device__ float g_u1T [(size_t)BSROWS*EDIM];   // u1T[b,e,i] (tf32-rounded)
__device__ float g_t1  [(size_t)BSROWS*EDIM];   // t1 [b,i,e]
__device__ float g_r   [(size_t)BSROWS*EDIM];
__device__ float g_xres[(size_t)BSROWS*FDIM];
__device__ float g_mlp [(size_t)BSROWS*MLPD];
__device__ float g_gwT [(size_t)SEQ*SEQ];
__device__ float g_gwR [(size_t)SEQ*SEQ];
__device__ float g_ewR [(size_t)EDIM*FDIM];
__device__ float g_owR [(size_t)FDIM*EDIM];
__device__ float g_w1R [(size_t)MLPD*FDIM];
__device__ float g_w2R [(size_t)FDIM*MLPD];

// ---------------- helpers -----------------------------------------------------
__device__ __forceinline__ float rtf(float x) {   // round-to-nearest tf32
    uint32_t u;
    asm("cvt.rna.tf32.f32 %0, %1;" : "=r"(u) : "f"(x));
    return __uint_as_float(u);
}
#define CP16(dst, src) \
    asm volatile("cp.async.cg.shared.global [%0], [%1], 16;" :: "r"(dst), "l"(src))
#define CP_COMMIT() asm volatile("cp.async.commit_group;" ::: "memory")
#define CP_WAIT(n)  asm volatile("cp.async.wait_group %0;" :: "n"(n) : "memory")
__device__ __forceinline__ uint32_t s2u(const void* p) {
    uint32_t a;
    asm("{ .reg .u64 t; cvta.to.shared.u64 t, %1; cvt.u32.u64 %0, t; }" : "=r"(a) : "l"(p));
    return a;
}
__device__ __forceinline__ void mma_tf32(float* c, const uint32_t* a, const uint32_t* b) {
    asm volatile(
        "mma.sync.aligned.m16n8k8.row.col.f32.tf32.tf32.f32 "
        "{%0,%1,%2,%3}, {%4,%5,%6,%7}, {%8,%9}, {%0,%1,%2,%3};"
        : "+f"(c[0]), "+f"(c[1]), "+f"(c[2]), "+f"(c[3])
        : "r"(a[0]), "r"(a[1]), "r"(a[2]), "r"(a[3]), "r"(b[0]), "r"(b[1]));
}
static __device__ __forceinline__ float gelu_tanh(float v) {
    float t = tanhf(0.7978845608028654f * (v + 0.044715f * v * v * v));
    return 0.5f * v * (1.f + t);
}

// ---------------- tf32 mma GEMM: C[M,N]=A[M,K]@B[N,K]^T ----------------------
// 128x128 tile, K-chunk 32, 3-stage cp.async.
// EPI: 0=bias+clip+L1norm64  1=bias+res  2=bias+gelu(round)  3=plain
//      4=fused NNMF-B: h=l1norm64(clip(h_in*acc)); writes C=h, aux=hT(rounded)
#define SMP 36
#define STG (128*SMP)
#define MM_SMEM (6*STG*4)

template <int EPI>
__global__ __launch_bounds__(256) void mma_gemm(
    const float* __restrict__ A, const float* __restrict__ B,
    const float* __restrict__ bias, const float* __restrict__ res,
    float* __restrict__ C, float* __restrict__ aux, int K, int N,
    long long sB, long long sC)
{
    extern __shared__ float sm[];
    const int tid = threadIdx.x, wid = tid >> 5, lane = tid & 31;
    const int grp = lane >> 2, qid = lane & 3;
    const int n0 = blockIdx.x * 128;
    const size_t m0 = (size_t)blockIdx.y * 128;
    B += (size_t)blockIdx.z * sB;
    C += (size_t)blockIdx.z * sC;
    if (EPI == 1 || EPI == 4) res += (size_t)blockIdx.z * sC;
    if (EPI == 4) aux += (size_t)blockIdx.z * sC;
    const int wm = (wid & 1) * 64, wn = (wid >> 1) * 32;
    const uint32_t sAu = s2u(sm);

    auto load_chunk = [&](int st, int kt) {
        uint32_t base = sAu + (uint32_t)(st * 2 * STG) * 4;
#pragma unroll
        for (int i = 0; i < 4; i++) {
            int id = tid + 256 * i;
            int row = id >> 3, kq = (id & 7) * 4;
            CP16(base + (uint32_t)(row * SMP + kq) * 4, &A[(m0 + row) * K + kt + kq]);
        }
        base += STG * 4;
#pragma unroll
        for (int i = 0; i < 4; i++) {
            int id = tid + 256 * i;
            int row = id >> 3, kq = (id & 7) * 4;
            CP16(base + (uint32_t)(row * SMP + kq) * 4, &B[(size_t)(n0 + row) * K + kt + kq]);
        }
        CP_COMMIT();
    };

    float cfr[4][4][4];
#pragma unroll
    for (int mt = 0; mt < 4; mt++)
#pragma unroll
        for (int nt = 0; nt < 4; nt++)
#pragma unroll
            for (int i = 0; i < 4; i++) cfr[mt][nt][i] = 0.f;

    const int nch = K >> 5;
    load_chunk(0, 0);
    if (nch > 1) load_chunk(1, 32);

    for (int c = 0; c < nch; c++) {
        if (c == nch - 1) CP_WAIT(0);
        else              CP_WAIT(1);
        __syncthreads();
        const float* as = sm + (c % 3) * 2 * STG;
        const float* bs = as + STG;
#pragma unroll
        for (int kk = 0; kk < 32; kk += 8) {
            uint32_t af[4][4], bf[4][2];
#pragma unroll
            for (int mt = 0; mt < 4; mt++) {
                int row = wm + mt * 16 + grp;
                af[mt][0] = __float_as_uint(as[row * SMP + kk + qid]);
                af[mt][1] = __float_as_uint(as[(row + 8) * SMP + kk + qid]);
                af[mt][2] = __float_as_uint(as[row * SMP + kk + 4 + qid]);
                af[mt][3] = __float_as_uint(as[(row + 8) * SMP + kk + 4 + qid]);
            }
#pragma unroll
            for (int nt = 0; nt < 4; nt++) {
                int col = wn + nt * 8 + grp;
                bf[nt][0] = __float_as_uint(bs[col * SMP + kk + qid]);
                bf[nt][1] = __float_as_uint(bs[col * SMP + kk + 4 + qid]);
            }
#pragma unroll
            for (int mt = 0; mt < 4; mt++)
#pragma unroll
                for (int nt = 0; nt < 4; nt++)
                    mma_tf32(cfr[mt][nt], af[mt], bf[nt]);
        }
        if (c + 2 < nch) load_chunk((c + 2) % 3, (c + 2) * 32);
        __syncthreads();
    }

    if (EPI == 0 || EPI == 4) {
        // clip(+bias / *h_in); group-64 L1 normalize; write
        float* Ts   = sm;           // [128][132] staging (EPI4)
        float* psum = sm + 16896;   // [128][5]
#pragma unroll
        for (int mt = 0; mt < 4; mt++) {
            const size_t r0 = m0 + wm + mt * 16 + grp;
#pragma unroll
            for (int nt = 0; nt < 4; nt++) {
                const int col = n0 + wn + nt * 8 + qid * 2;
                if (EPI == 0) {
                    float2 bv = *(const float2*)&bias[col];
                    cfr[mt][nt][0] = fmaxf(cfr[mt][nt][0] + bv.x, MIN_POS);
                    cfr[mt][nt][1] = fmaxf(cfr[mt][nt][1] + bv.y, MIN_POS);
                    cfr[mt][nt][2] = fmaxf(cfr[mt][nt][2] + bv.x, MIN_POS);
                    cfr[mt][nt][3] = fmaxf(cfr[mt][nt][3] + bv.y, MIN_POS);
                } else {
                    float2 ha = *(const float2*)&res[r0 * N + col];
                    float2 hb = *(const float2*)&res[(r0 + 8) * N + col];
                    cfr[mt][nt][0] = fmaxf(cfr[mt][nt][0] * ha.x, MIN_POS);
                    cfr[mt][nt][1] = fmaxf(cfr[mt][nt][1] * ha.y, MIN_POS);
                    cfr[mt][nt][2] = fmaxf(cfr[mt][nt][2] * hb.x, MIN_POS);
                    cfr[mt][nt][3] = fmaxf(cfr[mt][nt][3] * hb.y, MIN_POS);
                }
            }
        }
        // partial sums over this warp's 32 cols, per row
#pragma unroll
        for (int mt = 0; mt < 4; mt++) {
#pragma unroll
            for (int rs = 0; rs < 2; rs++) {
                float s = 0.f;
#pragma unroll
                for (int nt = 0; nt < 4; nt++) s += cfr[mt][nt][rs*2] + cfr[mt][nt][rs*2+1];
                s += __shfl_xor_sync(0xffffffffu, s, 1);
                s += __shfl_xor_sync(0xffffffffu, s, 2);
                int row = wm + mt * 16 + grp + rs * 8;
                if (qid == 0) psum[row * 5 + (wid >> 1)] = s;
            }
        }
        __syncthreads();
        const int gc = (wid >> 2) * 2;
#pragma unroll
        for (int mt = 0; mt < 4; mt++) {
            const size_t r0 = m0 + wm + mt * 16 + grp;
            float inv0 = 1.f / (psum[(wm + mt*16 + grp) * 5 + gc]     + psum[(wm + mt*16 + grp) * 5 + gc + 1]);
            float inv1 = 1.f / (psum[(wm + mt*16 + grp + 8) * 5 + gc] + psum[(wm + mt*16 + grp + 8) * 5 + gc + 1]);
#pragma unroll
            for (int nt = 0; nt < 4; nt++) {
                const int col = wn + nt * 8 + qid * 2;
                float v0 = cfr[mt][nt][0] * inv0, v1 = cfr[mt][nt][1] * inv0;
                float v2 = cfr[mt][nt][2] * inv1, v3 = cfr[mt][nt][3] * inv1;
                float2 o0; o0.x = v0; o0.y = v1;
                float2 o1; o1.x = v2; o1.y = v3;
                *(float2*)&C[r0 * N + n0 + col] = o0;
                *(float2*)&C[(r0 + 8) * N + n0 + col] = o1;
                if (EPI == 4) {
                    int rr = wm + mt * 16 + grp;
                    Ts[(col + 0) * 132 + rr]     = rtf(v0);
                    Ts[(col + 1) * 132 + rr]     = rtf(v1);
                    Ts[(col + 0) * 132 + rr + 8] = rtf(v2);
                    Ts[(col + 1) * 132 + rr + 8] = rtf(v3);
                }
            }
        }
        if (EPI == 4) {
            __syncthreads();
#pragma unroll
            for (int q = 0; q < 16; q++) {
                int idx = q * 1024 + tid * 4;
                int col = idx >> 7, row = idx & 127;
                float4 v = *(const float4*)&Ts[col * 132 + row];
                *(float4*)&aux[(size_t)(n0 + col) * 256 + m0 + row] = v;
            }
        }
        return;
    }

    // EPI 1/2/3 epilogue
#pragma unroll
    for (int mt = 0; mt < 4; mt++) {
        const size_t r0 = m0 + wm + mt * 16 + grp;
#pragma unroll
        for (int nt = 0; nt < 4; nt++) {
            const int col = n0 + wn + nt * 8 + qid * 2;
            float bx = 0.f, by = 0.f;
            if (EPI != 3) {
                float2 bv = *(const float2*)&bias[col];
                bx = bv.x; by = bv.y;
            }
            float v0 = cfr[mt][nt][0] + bx, v1 = cfr[mt][nt][1] + by;
            float v2 = cfr[mt][nt][2] + bx, v3 = cfr[mt][nt][3] + by;
            if (EPI == 1) {
                float2 ra = *(const float2*)&res[r0 * N + col];
                float2 rb = *(const float2*)&res[(r0 + 8) * N + col];
                v0 += ra.x; v1 += ra.y; v2 += rb.x; v3 += rb.y;
            } else if (EPI == 2) {
                v0 = rtf(gelu_tanh(v0)); v1 = rtf(gelu_tanh(v1));
                v2 = rtf(gelu_tanh(v2)); v3 = rtf(gelu_tanh(v3));
            }
            float2 o0; o0.x = v0; o0.y = v1;
            float2 o1; o1.x = v2; o1.y = v3;
            *(float2*)&C[r0 * N + col] = o0;
            *(float2*)&C[(r0 + 8) * N + col] = o1;
        }
    }
}

// ---------------- elementwise tf32 round -------------------------------------
__global__ __launch_bounds__(256) void round_kernel(
    const float* __restrict__ in, float* __restrict__ out, int n4)
{
    int i = blockIdx.x * 256 + threadIdx.x;
    if (i < n4) {
        float4 v = *(const float4*)&in[i * 4];
        v.x = rtf(v.x); v.y = rtf(v.y); v.z = rtf(v.z); v.w = rtf(v.w);
        *(float4*)&out[i * 4] = v;
    }
}

// ---------------- batched transpose [R,C]->[C,R], tf32-rounded ---------------
__global__ void transpose_kernel(
    const float* __restrict__ in, float* __restrict__ out, int R, int C)
{
    __shared__ float t[32][33];
    in  += (size_t)blockIdx.z * R * C;
    out += (size_t)blockIdx.z * R * C;
    int r0 = blockIdx.y * 32, c0 = blockIdx.x * 32;
    int lx = threadIdx.x, ly = threadIdx.y;
#pragma unroll
    for (int i = 0; i < 32; i += 8)
        t[ly + i][lx] = rtf(in[(size_t)(r0 + ly + i) * C + c0 + lx]);
    __syncthreads();
#pragma unroll
    for (int i = 0; i < 32; i += 8)
        out[(size_t)(c0 + ly + i) * R + r0 + lx] = t[lx][ly + i];
}

// ---------------- LayerNorm (tf32-rounded output) -----------------------------
__global__ __launch_bounds__(256) void ln_kernel(
    const float* __restrict__ x, const float* __restrict__ g,
    const float* __restrict__ b, float* __restrict__ out)
{
    int row  = blockIdx.x * 8 + (threadIdx.x >> 5);
    int lane = threadIdx.x & 31;
    const float* xr = x + (size_t)row * 512;
    float4 v[4];
    float s = 0.f, sq = 0.f;
#pragma unroll
    for (int w = 0; w < 4; w++) {
        v[w] = *(const float4*)&xr[w * 128 + lane * 4];
        s  += v[w].x + v[w].y + v[w].z + v[w].w;
        sq += v[w].x*v[w].x + v[w].y*v[w].y + v[w].z*v[w].z + v[w].w*v[w].w;
    }
#pragma unroll
    for (int off = 16; off > 0; off >>= 1) {
        s  += __shfl_xor_sync(0xffffffffu, s,  off);
        sq += __shfl_xor_sync(0xffffffffu, sq, off);
    }
    float mu = s * (1.f / 512.f);
    float var = sq * (1.f / 512.f) - mu * mu;
    float rstd = rsqrtf(var + 1e-5f);
    float* orow = out + (size_t)row * 512;
#pragma unroll
    for (int w = 0; w < 4; w++) {
        int c = w * 128 + lane * 4;
        float4 gv = *(const float4*)&g[c];
        float4 bv = *(const float4*)&b[c];
        float4 o;
        o.x = rtf((v[w].x - mu) * rstd * gv.x + bv.x);
        o.y = rtf((v[w].y - mu) * rstd * gv.y + bv.y);
        o.z = rtf((v[w].z - mu) * rstd * gv.z + bv.z);
        o.w = rtf((v[w].w - mu) * rstd * gv.w + bv.w);
        *(float4*)&orow[c] = o;
    }
}

// ---------------- NNMF A lite: local mixes around t1 -------------------------
// reads t1[b,i,e]; writes u1T[b,e,i] (rounded), r[b,i,e] (rounded) if WR
template <bool WR>
__global__ __launch_bounds__(256) void nnmfA_lite(
    const float* __restrict__ t1, const float* __restrict__ lw,
    const float* __restrict__ xe, float* __restrict__ r_out,
    float* __restrict__ u1T)
{
    extern __shared__ float smf[];
    float (*lws)[68]  = (float(*)[68])(smf);
    float (*lwsT)[68] = (float(*)[68])(smf + 4352);
    float (*Tst)[132] = (float(*)[132])(smf + 8704);
    float* sums = smf + 17152;   // total 17280 floats

    const int tid = threadIdx.x, tx = tid & 15, ty = tid >> 4;
    const int i0 = blockIdx.x * 128, head = blockIdx.y, b = blockIdx.z;

#pragma unroll
    for (int q = 0; q < 16; q++) {
        int idx = q * 256 + tid;
        int g = idx >> 6, f = idx & 63;
        float v = lw[idx];
        lws[g][f] = v;
        lwsT[f][g] = v;
    }

    const size_t base = ((size_t)b * SEQ + i0) * 512 + head * 64;
#pragma unroll
    for (int a = 0; a < 8; a++) {
        int m = (a >> 2) * 64 + ty * 4 + (a & 3);
        float4 v = *(const float4*)&t1[base + (size_t)m * 512 + tx * 4];
        Tst[tx*4+0][m] = v.x; Tst[tx*4+1][m] = v.y;
        Tst[tx*4+2][m] = v.z; Tst[tx*4+3][m] = v.w;
    }
    __syncthreads();

    float racc[8][4];
#pragma unroll
    for (int r = 0; r < 8; r++)
#pragma unroll
        for (int j = 0; j < 4; j++) racc[r][j] = 0.f;
#pragma unroll 16
    for (int k = 0; k < 64; k++) {
        float4 a0 = *(const float4*)&Tst[k][ty * 4];
        float4 a1 = *(const float4*)&Tst[k][64 + ty * 4];
        float4 b0 = *(const float4*)&lws[k][tx * 4];
        float av[8] = {a0.x, a0.y, a0.z, a0.w, a1.x, a1.y, a1.z, a1.w};
        float bv[4] = {b0.x, b0.y, b0.z, b0.w};
#pragma unroll
        for (int r = 0; r < 8; r++)
#pragma unroll
            for (int j = 0; j < 4; j++) racc[r][j] += av[r] * bv[j];
    }
#pragma unroll
    for (int r = 0; r < 8; r++)
#pragma unroll
        for (int j = 0; j < 4; j++) racc[r][j] = fmaxf(racc[r][j], MIN_POS);

    float rp[8];
#pragma unroll
    for (int r = 0; r < 8; r++) rp[r] = racc[r][0] + racc[r][1] + racc[r][2] + racc[r][3];
#pragma unroll
    for (int off = 1; off < 16; off <<= 1)
#pragma unroll
        for (int r = 0; r < 8; r++) rp[r] += __shfl_xor_sync(0xffffffffu, rp[r], off);
    if (tx == 0) {
#pragma unroll
        for (int r = 0; r < 4; r++) {
            sums[ty * 4 + r]      = rp[r];
            sums[64 + ty * 4 + r] = rp[4 + r];
        }
    }
    __syncthreads();

#pragma unroll
    for (int mi = 0; mi < 2; mi++)
#pragma unroll
        for (int r = 0; r < 4; r++) {
            int m = mi * 64 + ty * 4 + r;
            float s = sums[m];
            float4 xev = *(const float4*)&xe[base + (size_t)m * 512 + tx * 4];
            float rc0 = racc[mi*4+r][0], rc1 = racc[mi*4+r][1];
            float rc2 = racc[mi*4+r][2], rc3 = racc[mi*4+r][3];
            if (WR) {
                float invs = 1.f / s;
                float4 rv;
                rv.x = rtf(rc0*invs); rv.y = rtf(rc1*invs);
                rv.z = rtf(rc2*invs); rv.w = rtf(rc3*invs);
                *(float4*)&r_out[base + (size_t)m * 512 + tx * 4] = rv;
            }
            Tst[tx*4+0][m] = xev.x * s / rc0;
            Tst[tx*4+1][m] = xev.y * s / rc1;
            Tst[tx*4+2][m] = xev.z * s / rc2;
            Tst[tx*4+3][m] = xev.w * s / rc3;
        }
    __syncthreads();

    float uacc[8][4];
#pragma unroll
    for (int r = 0; r < 8; r++)
#pragma unroll
        for (int j = 0; j < 4; j++) uacc[r][j] = 0.f;
#pragma unroll 16
    for (int k = 0; k < 64; k++) {
        float4 a0 = *(const float4*)&Tst[k][ty * 4];
        float4 a1 = *(const float4*)&Tst[k][64 + ty * 4];
        float4 b0 = *(const float4*)&lwsT[k][tx * 4];
        float av[8] = {a0.x, a0.y, a0.z, a0.w, a1.x, a1.y, a1.z, a1.w};
        float bv[4] = {b0.x, b0.y, b0.z, b0.w};
#pragma unroll
        for (int r = 0; r < 8; r++)
#pragma unroll
            for (int j = 0; j < 4; j++) uacc[r][j] += av[r] * bv[j];
    }
    __syncthreads();
#pragma unroll
    for (int a = 0; a < 8; a++) {
        int m = (a >> 2) * 64 + ty * 4 + (a & 3);
#pragma unroll
        for (int j = 0; j < 4; j++) Tst[tx * 4 + j][m] = rtf(uacc[a][j]);
    }
    __syncthreads();
    const size_t ubase = ((size_t)b * 512 + head * 64) * 256 + i0;
#pragma unroll
    for (int q = 0; q < 8; q++) {
        int idx = q * 1024 + tid * 4;
        int g = idx >> 7, m = idx & 127;
        float4 v = *(const float4*)&Tst[g][m];
        *(float4*)&u1T[ubase + (size_t)g * 256 + m] = v;
    }
}

// ---------------- host launcher -----------------------------------------------
extern "C" void kernel_launch(void* const* d_in, const int* in_sizes, int n_in,
                              void* d_out, int out_size)
{
    const float* x    = (const float*)d_in[0];
    const float* ew   = (const float*)d_in[1];
    const float* eb   = (const float*)d_in[2];
    const float* lw   = (const float*)d_in[3];
    const float* gw   = (const float*)d_in[4];
    const float* ow   = (const float*)d_in[5];
    const float* ob   = (const float*)d_in[6];
    const float* ln1g = (const float*)d_in[7];
    const float* ln1b = (const float*)d_in[8];
    const float* ln2g = (const float*)d_in[9];
    const float* ln2b = (const float*)d_in[10];
    const float* w1   = (const float*)d_in[11];
    const float* b1   = (const float*)d_in[12];
    const float* w2   = (const float*)d_in[13];
    const float* b2   = (const float*)d_in[14];
    const float* h0   = (const float*)d_in[15];
    float* out = (float*)d_out;

    float *xn, *xe, *h, *hT, *u1T, *t1, *r, *xres, *mlp, *gwT, *gwR;
    float *ewR, *owR, *w1R, *w2R;
    cudaGetSymbolAddress((void**)&xn,   g_xn);
    cudaGetSymbolAddress((void**)&xe,   g_xe);
    cudaGetSymbolAddress((void**)&h,    g_h);
    cudaGetSymbolAddress((void**)&hT,   g_hT);
    cudaGetSymbolAddress((void**)&u1T,  g_u1T);
    cudaGetSymbolAddress((void**)&t1,   g_t1);
    cudaGetSymbolAddress((void**)&r,    g_r);
    cudaGetSymbolAddress((void**)&xres, g_xres);
    cudaGetSymbolAddress((void**)&mlp,  g_mlp);
    cudaGetSymbolAddress((void**)&gwT,  g_gwT);
    cudaGetSymbolAddress((void**)&gwR,  g_gwR);
    cudaGetSymbolAddress((void**)&ewR,  g_ewR);
    cudaGetSymbolAddress((void**)&owR,  g_owR);
    cudaGetSymbolAddress((void**)&w1R,  g_w1R);
    cudaGetSymbolAddress((void**)&w2R,  g_w2R);

    cudaFuncSetAttribute(mma_gemm<0>, cudaFuncAttributeMaxDynamicSharedMemorySize, MM_SMEM);
    cudaFuncSetAttribute(mma_gemm<1>, cudaFuncAttributeMaxDynamicSharedMemorySize, MM_SMEM);
    cudaFuncSetAttribute(mma_gemm<2>, cudaFuncAttributeMaxDynamicSharedMemorySize, MM_SMEM);
    cudaFuncSetAttribute(mma_gemm<3>, cudaFuncAttributeMaxDynamicSharedMemorySize, MM_SMEM);
    cudaFuncSetAttribute(mma_gemm<4>, cudaFuncAttributeMaxDynamicSharedMemorySize, MM_SMEM);
    const int A_SMEM = 17280 * 4;
    cudaFuncSetAttribute(nnmfA_lite<false>, cudaFuncAttributeMaxDynamicSharedMemorySize, A_SMEM);
    cudaFuncSetAttribute(nnmfA_lite<true>,  cudaFuncAttributeMaxDynamicSharedMemorySize, A_SMEM);

    const long long SB = 512LL * 256;
    const long long SC = 256LL * 512;

    // one-time rounded weight copies + transposes
    round_kernel<<<(512*512/4+255)/256, 256>>>(ew, ewR, 512*512/4);
    round_kernel<<<(512*512/4+255)/256, 256>>>(ow, owR, 512*512/4);
    round_kernel<<<(2048*512/4+255)/256, 256>>>(w1, w1R, 2048*512/4);
    round_kernel<<<(2048*512/4+255)/256, 256>>>(w2, w2R, 2048*512/4);
    round_kernel<<<(256*256/4+255)/256, 256>>>(gw, gwR, 256*256/4);
    transpose_kernel<<<dim3(8, 8, 1), dim3(32, 8)>>>(gw, gwT, 256, 256);
    transpose_kernel<<<dim3(16, 8, 128), dim3(32, 8)>>>(h0, hT, 256, 512);

    ln_kernel<<<BSROWS / 8, 256>>>(x, ln1g, ln1b, xn);
    // embed + clip + per-head l1norm -> xe (fused)
    mma_gemm<0><<<dim3(4, 256, 1), 256, MM_SMEM>>>(xn, ewR, eb, nullptr, xe, nullptr, 512, 512, 0, 0);

    for (int it = 0; it < 10; it++) {
        // t1[b,i,e] = gwT[i,:] . hT[b,e,:]
        mma_gemm<3><<<dim3(4, 2, 128), 256, MM_SMEM>>>(gwT, hT, nullptr, nullptr, t1, nullptr, 256, 512, SB, SC);
        if (it < 9) {
            nnmfA_lite<false><<<dim3(2, HEADS, BSZ), 256, A_SMEM>>>(t1, lw, xe, r, u1T);
            // fused: acc = gw @ u1 ; h = l1norm(clip(h*acc)) ; writes h and hT
            mma_gemm<4><<<dim3(4, 2, 128), 256, MM_SMEM>>>(gwR, u1T, nullptr,
                (it == 0) ? h0 : h, h, hT, 256, 512, SB, SC);
        } else {
            nnmfA_lite<true><<<dim3(2, HEADS, BSZ), 256, A_SMEM>>>(t1, lw, xe, r, u1T);
        }
    }

    mma_gemm<1><<<dim3(4, 256, 1), 256, MM_SMEM>>>(r, owR, ob, x, xres, nullptr, 512, 512, 0, 0);
    ln_kernel<<<BSROWS / 8, 256>>>(xres, ln2g, ln2b, xn);
    mma_gemm<2><<<dim3(16, 256, 1), 256, MM_SMEM>>>(xn, w1R, b1, nullptr, mlp, nullptr, 512, 2048, 0, 0);
    mma_gemm<1><<<dim3(4, 256, 1), 256, MM_SMEM>>>(mlp, w2R, b2, xres, out, nullptr, 2048, 512, 0, 0);
}

// round 6
// speedup vs baseline: 2.2615x; 1.0201x over previous
#include <cuda_runtime.h>
#include <cstdint>

#define BSZ   128
#define SEQ   256
#define FDIM  512
#define EDIM  512
#define HEADS 8
#define BSROWS (BSZ*SEQ)
#define MLPD  2048
#define MIN_POS 1e-6f

__device__ float g_xn  [(size_t)BSROWS*FDIM];
__device__ float g_xe  [(size_t)BSROWS*EDIM];
__device__ float g_h   [(size_t)BSROWS*EDIM];   // h  [b,o,e]
__device__ float g_hT  [(size_t)BSROWS*EDIM];   // hT [b,e,o] (tf32-rounded)
__device__ float g_u1T [(size_t)BSROWS*EDIM];   // u1T[b,e,i] (tf32-rounded)
__device__ float g_t1  [(size_t)BSROWS*EDIM];   // t1 [b,i,e]
__device__ float g_r   [(size_t)BSROWS*EDIM];
__device__ float g_xres[(size_t)BSROWS*FDIM];
__device__ float g_mlp [(size_t)BSROWS*MLPD];
__device__ float g_gwT [(size_t)SEQ*SEQ];
__device__ float g_gwR [(size_t)SEQ*SEQ];
__device__ float g_ewR [(size_t)EDIM*FDIM];
__device__ float g_owR [(size_t)FDIM*EDIM];
__device__ float g_w1R [(size_t)MLPD*FDIM];
__device__ float g_w2R [(size_t)FDIM*MLPD];

// ---------------- helpers -----------------------------------------------------
__device__ __forceinline__ float rtf(float x) {   // round-to-nearest tf32
    uint32_t u;
    asm("cvt.rna.tf32.f32 %0, %1;" : "=r"(u) : "f"(x));
    return __uint_as_float(u);
}
#define CP16(dst, src) \
    asm volatile("cp.async.cg.shared.global [%0], [%1], 16;" :: "r"(dst), "l"(src))
#define CP_COMMIT() asm volatile("cp.async.commit_group;" ::: "memory")
#define CP_WAIT(n)  asm volatile("cp.async.wait_group %0;" :: "n"(n) : "memory")
#define LDSM4(r0, r1, r2, r3, addr) \
    asm volatile("ldmatrix.sync.aligned.m8n8.x4.shared.b16 {%0,%1,%2,%3}, [%4];" \
                 : "=r"(r0), "=r"(r1), "=r"(r2), "=r"(r3) : "r"(addr))
__device__ __forceinline__ uint32_t s2u(const void* p) {
    uint32_t a;
    asm("{ .reg .u64 t; cvta.to.shared.u64 t, %1; cvt.u32.u64 %0, t; }" : "=r"(a) : "l"(p));
    return a;
}
__device__ __forceinline__ void mma_tf32(float* c, const uint32_t* a, const uint32_t* b) {
    asm volatile(
        "mma.sync.aligned.m16n8k8.row.col.f32.tf32.tf32.f32 "
        "{%0,%1,%2,%3}, {%4,%5,%6,%7}, {%8,%9}, {%0,%1,%2,%3};"
        : "+f"(c[0]), "+f"(c[1]), "+f"(c[2]), "+f"(c[3])
        : "r"(a[0]), "r"(a[1]), "r"(a[2]), "r"(a[3]), "r"(b[0]), "r"(b[1]));
}
static __device__ __forceinline__ float gelu_tanh(float v) {
    float t = tanhf(0.7978845608028654f * (v + 0.044715f * v * v * v));
    return 0.5f * v * (1.f + t);
}

// ---------------- tf32 mma GEMM: C[M,N]=A[M,K]@B[N,K]^T ----------------------
// 128x128 tile, K-chunk 32, 2-stage cp.async, ldmatrix fragment loads.
// EPI: 0=bias+clip+L1norm64  1=bias+res  2=bias+gelu(round)  3=plain
//      4=fused NNMF-B: h=l1norm64(clip(h_in*acc)); writes C=h, aux=hT(rounded)
#define SMP 36
#define STG (128*SMP)
#define MM_SMEM (4*STG*4)   // 73728 B: 2 ops x 2 stages

template <int EPI>
__global__ __launch_bounds__(256) void mma_gemm(
    const float* __restrict__ A, const float* __restrict__ B,
    const float* __restrict__ bias, const float* __restrict__ res,
    float* __restrict__ C, float* __restrict__ aux, int K, int N,
    long long sB, long long sC)
{
    extern __shared__ float sm[];
    const int tid = threadIdx.x, wid = tid >> 5, lane = tid & 31;
    const int grp = lane >> 2, qid = lane & 3;
    const int n0 = blockIdx.x * 128;
    const size_t m0 = (size_t)blockIdx.y * 128;
    B += (size_t)blockIdx.z * sB;
    C += (size_t)blockIdx.z * sC;
    if (EPI == 1 || EPI == 4) res += (size_t)blockIdx.z * sC;
    if (EPI == 4) aux += (size_t)blockIdx.z * sC;
    const int wm = (wid & 1) * 64, wn = (wid >> 1) * 32;
    const uint32_t sAu = s2u(sm);

    // ldmatrix per-thread row/col assignments
    const int t8 = lane >> 3, r8 = lane & 7;
    const int rowA = wm + (t8 & 1) * 8 + r8;   // + mt*16
    const int colA = (t8 >> 1) * 4;            // + kk
    const int rowB = wn + (t8 >> 1) * 8 + r8;  // + ntp*16
    const int colB = (t8 & 1) * 4;             // + kk

    auto load_chunk = [&](int st, int kt) {
        uint32_t base = sAu + (uint32_t)(st * 2 * STG) * 4;
#pragma unroll
        for (int i = 0; i < 4; i++) {
            int id = tid + 256 * i;
            int row = id >> 3, kq = (id & 7) * 4;
            CP16(base + (uint32_t)(row * SMP + kq) * 4, &A[(m0 + row) * K + kt + kq]);
        }
        base += STG * 4;
#pragma unroll
        for (int i = 0; i < 4; i++) {
            int id = tid + 256 * i;
            int row = id >> 3, kq = (id & 7) * 4;
            CP16(base + (uint32_t)(row * SMP + kq) * 4, &B[(size_t)(n0 + row) * K + kt + kq]);
        }
        CP_COMMIT();
    };

    float cfr[4][4][4];
#pragma unroll
    for (int mt = 0; mt < 4; mt++)
#pragma unroll
        for (int nt = 0; nt < 4; nt++)
#pragma unroll
            for (int i = 0; i < 4; i++) cfr[mt][nt][i] = 0.f;

    const int nch = K >> 5;
    load_chunk(0, 0);
    if (nch > 1) load_chunk(1, 32);

    for (int c = 0; c < nch; c++) {
        if (c + 1 < nch) CP_WAIT(1);
        else             CP_WAIT(0);
        __syncthreads();
        const uint32_t sAs = sAu + (uint32_t)((c & 1) * 2 * STG) * 4;
        const uint32_t sBs = sAs + STG * 4;
#pragma unroll
        for (int kk = 0; kk < 32; kk += 8) {
            uint32_t af[4][4], bf[2][4];
#pragma unroll
            for (int mt = 0; mt < 4; mt++)
                LDSM4(af[mt][0], af[mt][1], af[mt][2], af[mt][3],
                      sAs + (uint32_t)((rowA + mt * 16) * SMP + kk + colA) * 4);
#pragma unroll
            for (int ntp = 0; ntp < 2; ntp++)
                LDSM4(bf[ntp][0], bf[ntp][1], bf[ntp][2], bf[ntp][3],
                      sBs + (uint32_t)((rowB + ntp * 16) * SMP + kk + colB) * 4);
#pragma unroll
            for (int mt = 0; mt < 4; mt++)
#pragma unroll
                for (int nt = 0; nt < 4; nt++)
                    mma_tf32(cfr[mt][nt], af[mt], &bf[nt >> 1][(nt & 1) * 2]);
        }
        __syncthreads();
        if (c + 2 < nch) load_chunk(c & 1, (c + 2) * 32);
    }

    if (EPI == 0 || EPI == 4) {
        float* Ts   = sm;           // [128][132] staging (EPI4)
        float* psum = sm + 16896;   // [128][5]
#pragma unroll
        for (int mt = 0; mt < 4; mt++) {
            const size_t r0 = m0 + wm + mt * 16 + grp;
#pragma unroll
            for (int nt = 0; nt < 4; nt++) {
                const int col = n0 + wn + nt * 8 + qid * 2;
                if (EPI == 0) {
                    float2 bv = *(const float2*)&bias[col];
                    cfr[mt][nt][0] = fmaxf(cfr[mt][nt][0] + bv.x, MIN_POS);
                    cfr[mt][nt][1] = fmaxf(cfr[mt][nt][1] + bv.y, MIN_POS);
                    cfr[mt][nt][2] = fmaxf(cfr[mt][nt][2] + bv.x, MIN_POS);
                    cfr[mt][nt][3] = fmaxf(cfr[mt][nt][3] + bv.y, MIN_POS);
                } else {
                    float2 ha = *(const float2*)&res[r0 * N + col];
                    float2 hb = *(const float2*)&res[(r0 + 8) * N + col];
                    cfr[mt][nt][0] = fmaxf(cfr[mt][nt][0] * ha.x, MIN_POS);
                    cfr[mt][nt][1] = fmaxf(cfr[mt][nt][1] * ha.y, MIN_POS);
                    cfr[mt][nt][2] = fmaxf(cfr[mt][nt][2] * hb.x, MIN_POS);
                    cfr[mt][nt][3] = fmaxf(cfr[mt][nt][3] * hb.y, MIN_POS);
                }
            }
        }
#pragma unroll
        for (int mt = 0; mt < 4; mt++) {
#pragma unroll
            for (int rs = 0; rs < 2; rs++) {
                float s = 0.f;
#pragma unroll
                for (int nt = 0; nt < 4; nt++) s += cfr[mt][nt][rs*2] + cfr[mt][nt][rs*2+1];
                s += __shfl_xor_sync(0xffffffffu, s, 1);
                s += __shfl_xor_sync(0xffffffffu, s, 2);
                int row = wm + mt * 16 + grp + rs * 8;
                if (qid == 0) psum[row * 5 + (wid >> 1)] = s;
            }
        }
        __syncthreads();
        const int gc = (wid >> 2) * 2;
#pragma unroll
        for (int mt = 0; mt < 4; mt++) {
            const size_t r0 = m0 + wm + mt * 16 + grp;
            float inv0 = 1.f / (psum[(wm + mt*16 + grp) * 5 + gc]     + psum[(wm + mt*16 + grp) * 5 + gc + 1]);
            float inv1 = 1.f / (psum[(wm + mt*16 + grp + 8) * 5 + gc] + psum[(wm + mt*16 + grp + 8) * 5 + gc + 1]);
#pragma unroll
            for (int nt = 0; nt < 4; nt++) {
                const int col = wn + nt * 8 + qid * 2;
                float v0 = cfr[mt][nt][0] * inv0, v1 = cfr[mt][nt][1] * inv0;
                float v2 = cfr[mt][nt][2] * inv1, v3 = cfr[mt][nt][3] * inv1;
                float2 o0; o0.x = v0; o0.y = v1;
                float2 o1; o1.x = v2; o1.y = v3;
                *(float2*)&C[r0 * N + n0 + col] = o0;
                *(float2*)&C[(r0 + 8) * N + n0 + col] = o1;
                if (EPI == 4) {
                    int rr = wm + mt * 16 + grp;
                    Ts[(col + 0) * 132 + rr]     = rtf(v0);
                    Ts[(col + 1) * 132 + rr]     = rtf(v1);
                    Ts[(col + 0) * 132 + rr + 8] = rtf(v2);
                    Ts[(col + 1) * 132 + rr + 8] = rtf(v3);
                }
            }
        }
        if (EPI == 4) {
            __syncthreads();
#pragma unroll
            for (int q = 0; q < 16; q++) {
                int idx = q * 1024 + tid * 4;
                int col = idx >> 7, row = idx & 127;
                float4 v = *(const float4*)&Ts[col * 132 + row];
                *(float4*)&aux[(size_t)(n0 + col) * 256 + m0 + row] = v;
            }
        }
        return;
    }

#pragma unroll
    for (int mt = 0; mt < 4; mt++) {
        const size_t r0 = m0 + wm + mt * 16 + grp;
#pragma unroll
        for (int nt = 0; nt < 4; nt++) {
            const int col = n0 + wn + nt * 8 + qid * 2;
            float bx = 0.f, by = 0.f;
            if (EPI != 3) {
                float2 bv = *(const float2*)&bias[col];
                bx = bv.x; by = bv.y;
            }
            float v0 = cfr[mt][nt][0] + bx, v1 = cfr[mt][nt][1] + by;
            float v2 = cfr[mt][nt][2] + bx, v3 = cfr[mt][nt][3] + by;
            if (EPI == 1) {
                float2 ra = *(const float2*)&res[r0 * N + col];
                float2 rb = *(const float2*)&res[(r0 + 8) * N + col];
                v0 += ra.x; v1 += ra.y; v2 += rb.x; v3 += rb.y;
            } else if (EPI == 2) {
                v0 = rtf(gelu_tanh(v0)); v1 = rtf(gelu_tanh(v1));
                v2 = rtf(gelu_tanh(v2)); v3 = rtf(gelu_tanh(v3));
            }
            float2 o0; o0.x = v0; o0.y = v1;
            float2 o1; o1.x = v2; o1.y = v3;
            *(float2*)&C[r0 * N + col] = o0;
            *(float2*)&C[(r0 + 8) * N + col] = o1;
        }
    }
}

// ---------------- elementwise tf32 round -------------------------------------
__global__ __launch_bounds__(256) void round_kernel(
    const float* __restrict__ in, float* __restrict__ out, int n4)
{
    int i = blockIdx.x * 256 + threadIdx.x;
    if (i < n4) {
        float4 v = *(const float4*)&in[i * 4];
        v.x = rtf(v.x); v.y = rtf(v.y); v.z = rtf(v.z); v.w = rtf(v.w);
        *(float4*)&out[i * 4] = v;
    }
}

// ---------------- batched transpose [R,C]->[C,R], tf32-rounded ---------------
__global__ void transpose_kernel(
    const float* __restrict__ in, float* __restrict__ out, int R, int C)
{
    __shared__ float t[32][33];
    in  += (size_t)blockIdx.z * R * C;
    out += (size_t)blockIdx.z * R * C;
    int r0 = blockIdx.y * 32, c0 = blockIdx.x * 32;
    int lx = threadIdx.x, ly = threadIdx.y;
#pragma unroll
    for (int i = 0; i < 32; i += 8)
        t[ly + i][lx] = rtf(in[(size_t)(r0 + ly + i) * C + c0 + lx]);
    __syncthreads();
#pragma unroll
    for (int i = 0; i < 32; i += 8)
        out[(size_t)(c0 + ly + i) * R + r0 + lx] = t[lx][ly + i];
}

// ---------------- LayerNorm (tf32-rounded output) -----------------------------
__global__ __launch_bounds__(256) void ln_kernel(
    const float* __restrict__ x, const float* __restrict__ g,
    const float* __restrict__ b, float* __restrict__ out)
{
    int row  = blockIdx.x * 8 + (threadIdx.x >> 5);
    int lane = threadIdx.x & 31;
    const float* xr = x + (size_t)row * 512;
    float4 v[4];
    float s = 0.f, sq = 0.f;
#pragma unroll
    for (int w = 0; w < 4; w++) {
        v[w] = *(const float4*)&xr[w * 128 + lane * 4];
        s  += v[w].x + v[w].y + v[w].z + v[w].w;
        sq += v[w].x*v[w].x + v[w].y*v[w].y + v[w].z*v[w].z + v[w].w*v[w].w;
    }
#pragma unroll
    for (int off = 16; off > 0; off >>= 1) {
        s  += __shfl_xor_sync(0xffffffffu, s,  off);
        sq += __shfl_xor_sync(0xffffffffu, sq, off);
    }
    float mu = s * (1.f / 512.f);
    float var = sq * (1.f / 512.f) - mu * mu;
    float rstd = rsqrtf(var + 1e-5f);
    float* orow = out + (size_t)row * 512;
#pragma unroll
    for (int w = 0; w < 4; w++) {
        int c = w * 128 + lane * 4;
        float4 gv = *(const float4*)&g[c];
        float4 bv = *(const float4*)&b[c];
        float4 o;
        o.x = rtf((v[w].x - mu) * rstd * gv.x + bv.x);
        o.y = rtf((v[w].y - mu) * rstd * gv.y + bv.y);
        o.z = rtf((v[w].z - mu) * rstd * gv.z + bv.z);
        o.w = rtf((v[w].w - mu) * rstd * gv.w + bv.w);
        *(float4*)&orow[c] = o;
    }
}

// ---------------- NNMF A lite: local mixes around t1 -------------------------
template <bool WR>
__global__ __launch_bounds__(256) void nnmfA_lite(
    const float* __restrict__ t1, const float* __restrict__ lw,
    const float* __restrict__ xe, float* __restrict__ r_out,
    float* __restrict__ u1T)
{
    extern __shared__ float smf[];
    float (*lws)[68]  = (float(*)[68])(smf);
    float (*lwsT)[68] = (float(*)[68])(smf + 4352);
    float (*Tst)[132] = (float(*)[132])(smf + 8704);
    float* sums = smf + 17152;   // total 17280 floats

    const int tid = threadIdx.x, tx = tid & 15, ty = tid >> 4;
    const int i0 = blockIdx.x * 128, head = blockIdx.y, b = blockIdx.z;

#pragma unroll
    for (int q = 0; q < 16; q++) {
        int idx = q * 256 + tid;
        int g = idx >> 6, f = idx & 63;
        float v = lw[idx];
        lws[g][f] = v;
        lwsT[f][g] = v;
    }

    const size_t base = ((size_t)b * SEQ + i0) * 512 + head * 64;
#pragma unroll
    for (int a = 0; a < 8; a++) {
        int m = (a >> 2) * 64 + ty * 4 + (a & 3);
        float4 v = *(const float4*)&t1[base + (size_t)m * 512 + tx * 4];
        Tst[tx*4+0][m] = v.x; Tst[tx*4+1][m] = v.y;
        Tst[tx*4+2][m] = v.z; Tst[tx*4+3][m] = v.w;
    }
    __syncthreads();

    float racc[8][4];
#pragma unroll
    for (int r = 0; r < 8; r++)
#pragma unroll
        for (int j = 0; j < 4; j++) racc[r][j] = 0.f;
#pragma unroll 16
    for (int k = 0; k < 64; k++) {
        float4 a0 = *(const float4*)&Tst[k][ty * 4];
        float4 a1 = *(const float4*)&Tst[k][64 + ty * 4];
        float4 b0 = *(const float4*)&lws[k][tx * 4];
        float av[8] = {a0.x, a0.y, a0.z, a0.w, a1.x, a1.y, a1.z, a1.w};
        float bv[4] = {b0.x, b0.y, b0.z, b0.w};
#pragma unroll
        for (int r = 0; r < 8; r++)
#pragma unroll
            for (int j = 0; j < 4; j++) racc[r][j] += av[r] * bv[j];
    }
#pragma unroll
    for (int r = 0; r < 8; r++)
#pragma unroll
        for (int j = 0; j < 4; j++) racc[r][j] = fmaxf(racc[r][j], MIN_POS);

    float rp[8];
#pragma unroll
    for (int r = 0; r < 8; r++) rp[r] = racc[r][0] + racc[r][1] + racc[r][2] + racc[r][3];
#pragma unroll
    for (int off = 1; off < 16; off <<= 1)
#pragma unroll
        for (int r = 0; r < 8; r++) rp[r] += __shfl_xor_sync(0xffffffffu, rp[r], off);
    if (tx == 0) {
#pragma unroll
        for (int r = 0; r < 4; r++) {
            sums[ty * 4 + r]      = rp[r];
            sums[64 + ty * 4 + r] = rp[4 + r];
        }
    }
    __syncthreads();

#pragma unroll
    for (int mi = 0; mi < 2; mi++)
#pragma unroll
        for (int r = 0; r < 4; r++) {
            int m = mi * 64 + ty * 4 + r;
            float s = sums[m];
            float4 xev = *(const float4*)&xe[base + (size_t)m * 512 + tx * 4];
            float rc0 = racc[mi*4+r][0], rc1 = racc[mi*4+r][1];
            float rc2 = racc[mi*4+r][2], rc3 = racc[mi*4+r][3];
            if (WR) {
                float invs = 1.f / s;
                float4 rv;
                rv.x = rtf(rc0*invs); rv.y = rtf(rc1*invs);
                rv.z = rtf(rc2*invs); rv.w = rtf(rc3*invs);
                *(float4*)&r_out[base + (size_t)m * 512 + tx * 4] = rv;
            }
            Tst[tx*4+0][m] = xev.x * s / rc0;
            Tst[tx*4+1][m] = xev.y * s / rc1;
            Tst[tx*4+2][m] = xev.z * s / rc2;
            Tst[tx*4+3][m] = xev.w * s / rc3;
        }
    __syncthreads();

    float uacc[8][4];
#pragma unroll
    for (int r = 0; r < 8; r++)
#pragma unroll
        for (int j = 0; j < 4; j++) uacc[r][j] = 0.f;
#pragma unroll 16
    for (int k = 0; k < 64; k++) {
        float4 a0 = *(const float4*)&Tst[k][ty * 4];
        float4 a1 = *(const float4*)&Tst[k][64 + ty * 4];
        float4 b0 = *(const float4*)&lwsT[k][tx * 4];
        float av[8] = {a0.x, a0.y, a0.z, a0.w, a1.x, a1.y, a1.z, a1.w};
        float bv[4] = {b0.x, b0.y, b0.z, b0.w};
#pragma unroll
        for (int r = 0; r < 8; r++)
#pragma unroll
            for (int j = 0; j < 4; j++) uacc[r][j] += av[r] * bv[j];
    }
    __syncthreads();
#pragma unroll
    for (int a = 0; a < 8; a++) {
        int m = (a >> 2) * 64 + ty * 4 + (a & 3);
#pragma unroll
        for (int j = 0; j < 4; j++) Tst[tx * 4 + j][m] = rtf(uacc[a][j]);
    }
    __syncthreads();
    const size_t ubase = ((size_t)b * 512 + head * 64) * 256 + i0;
#pragma unroll
    for (int q = 0; q < 8; q++) {
        int idx = q * 1024 + tid * 4;
        int g = idx >> 7, m = idx & 127;
        float4 v = *(const float4*)&Tst[g][m];
        *(float4*)&u1T[ubase + (size_t)g * 256 + m] = v;
    }
}

// ---------------- host launcher -----------------------------------------------
extern "C" void kernel_launch(void* const* d_in, const int* in_sizes, int n_in,
                              void* d_out, int out_size)
{
    const float* x    = (const float*)d_in[0];
    const float* ew   = (const float*)d_in[1];
    const float* eb   = (const float*)d_in[2];
    const float* lw   = (const float*)d_in[3];
    const float* gw   = (const float*)d_in[4];
    const float* ow   = (const float*)d_in[5];
    const float* ob   = (const float*)d_in[6];
    const float* ln1g = (const float*)d_in[7];
    const float* ln1b = (const float*)d_in[8];
    const float* ln2g = (const float*)d_in[9];
    const float* ln2b = (const float*)d_in[10];
    const float* w1   = (const float*)d_in[11];
    const float* b1   = (const float*)d_in[12];
    const float* w2   = (const float*)d_in[13];
    const float* b2   = (const float*)d_in[14];
    const float* h0   = (const float*)d_in[15];
    float* out = (float*)d_out;

    float *xn, *xe, *h, *hT, *u1T, *t1, *r, *xres, *mlp, *gwT, *gwR;
    float *ewR, *owR, *w1R, *w2R;
    cudaGetSymbolAddress((void**)&xn,   g_xn);
    cudaGetSymbolAddress((void**)&xe,   g_xe);
    cudaGetSymbolAddress((void**)&h,    g_h);
    cudaGetSymbolAddress((void**)&hT,   g_hT);
    cudaGetSymbolAddress((void**)&u1T,  g_u1T);
    cudaGetSymbolAddress((void**)&t1,   g_t1);
    cudaGetSymbolAddress((void**)&r,    g_r);
    cudaGetSymbolAddress((void**)&xres, g_xres);
    cudaGetSymbolAddress((void**)&mlp,  g_mlp);
    cudaGetSymbolAddress((void**)&gwT,  g_gwT);
    cudaGetSymbolAddress((void**)&gwR,  g_gwR);
    cudaGetSymbolAddress((void**)&ewR,  g_ewR);
    cudaGetSymbolAddress((void**)&owR,  g_owR);
    cudaGetSymbolAddress((void**)&w1R,  g_w1R);
    cudaGetSymbolAddress((void**)&w2R,  g_w2R);

    cudaFuncSetAttribute(mma_gemm<0>, cudaFuncAttributeMaxDynamicSharedMemorySize, MM_SMEM);
    cudaFuncSetAttribute(mma_gemm<1>, cudaFuncAttributeMaxDynamicSharedMemorySize, MM_SMEM);
    cudaFuncSetAttribute(mma_gemm<2>, cudaFuncAttributeMaxDynamicSharedMemorySize, MM_SMEM);
    cudaFuncSetAttribute(mma_gemm<3>, cudaFuncAttributeMaxDynamicSharedMemorySize, MM_SMEM);
    cudaFuncSetAttribute(mma_gemm<4>, cudaFuncAttributeMaxDynamicSharedMemorySize, MM_SMEM);
    const int A_SMEM = 17280 * 4;
    cudaFuncSetAttribute(nnmfA_lite<false>, cudaFuncAttributeMaxDynamicSharedMemorySize, A_SMEM);
    cudaFuncSetAttribute(nnmfA_lite<true>,  cudaFuncAttributeMaxDynamicSharedMemorySize, A_SMEM);

    const long long SB = 512LL * 256;
    const long long SC = 256LL * 512;

    round_kernel<<<(512*512/4+255)/256, 256>>>(ew, ewR, 512*512/4);
    round_kernel<<<(512*512/4+255)/256, 256>>>(ow, owR, 512*512/4);
    round_kernel<<<(2048*512/4+255)/256, 256>>>(w1, w1R, 2048*512/4);
    round_kernel<<<(2048*512/4+255)/256, 256>>>(w2, w2R, 2048*512/4);
    round_kernel<<<(256*256/4+255)/256, 256>>>(gw, gwR, 256*256/4);
    transpose_kernel<<<dim3(8, 8, 1), dim3(32, 8)>>>(gw, gwT, 256, 256);
    transpose_kernel<<<dim3(16, 8, 128), dim3(32, 8)>>>(h0, hT, 256, 512);

    ln_kernel<<<BSROWS / 8, 256>>>(x, ln1g, ln1b, xn);
    mma_gemm<0><<<dim3(4, 256, 1), 256, MM_SMEM>>>(xn, ewR, eb, nullptr, xe, nullptr, 512, 512, 0, 0);

    for (int it = 0; it < 10; it++) {
        mma_gemm<3><<<dim3(4, 2, 128), 256, MM_SMEM>>>(gwT, hT, nullptr, nullptr, t1, nullptr, 256, 512, SB, SC);
        if (it < 9) {
            nnmfA_lite<false><<<dim3(2, HEADS, BSZ), 256, A_SMEM>>>(t1, lw, xe, r, u1T);
            mma_gemm<4><<<dim3(4, 2, 128), 256, MM_SMEM>>>(gwR, u1T, nullptr,
                (it == 0) ? h0 : h, h, hT, 256, 512, SB, SC);
        } else {
            nnmfA_lite<true><<<dim3(2, HEADS, BSZ), 256, A_SMEM>>>(t1, lw, xe, r, u1T);
        }
    }

    mma_gemm<1><<<dim3(4, 256, 1), 256, MM_SMEM>>>(r, owR, ob, x, xres, nullptr, 512, 512, 0, 0);
    ln_kernel<<<BSROWS / 8, 256>>>(xres, ln2g, ln2b, xn);
    mma_gemm<2><<<dim3(16, 256, 1), 256, MM_SMEM>>>(xn, w1R, b1, nullptr, mlp, nullptr, 512, 2048, 0, 0);
    mma_gemm<1><<<dim3(4, 256, 1), 256, MM_SMEM>>>(mlp, w2R, b2, xres, out, nullptr, 2048, 512, 0, 0);
}

// round 7
// speedup vs baseline: 2.6693x; 1.1803x over previous
#include <cuda_runtime.h>
#include <cstdint>

#define BSZ   128
#define SEQ   256
#define FDIM  512
#define EDIM  512
#define HEADS 8
#define BSROWS (BSZ*SEQ)
#define MLPD  2048
#define MIN_POS 1e-6f

__device__ float g_xn  [(size_t)BSROWS*FDIM];
__device__ float g_xe  [(size_t)BSROWS*EDIM];
__device__ float g_h   [(size_t)BSROWS*EDIM];   // h  [b,o,e]
__device__ float g_hT  [(size_t)BSROWS*EDIM];   // hT [b,e,o] (tf32-rounded)
__device__ float g_u1T [(size_t)BSROWS*EDIM];   // u1T[b,e,i] (tf32-rounded)
__device__ float g_t1  [(size_t)BSROWS*EDIM];   // t1 [b,i,e]
__device__ float g_r   [(size_t)BSROWS*EDIM];
__device__ float g_xres[(size_t)BSROWS*FDIM];
__device__ float g_mlp [(size_t)BSROWS*MLPD];
__device__ float g_gwT [(size_t)SEQ*SEQ];
__device__ float g_gwR [(size_t)SEQ*SEQ];
__device__ float g_ewR [(size_t)EDIM*FDIM];
__device__ float g_owR [(size_t)FDIM*EDIM];
__device__ float g_w1R [(size_t)MLPD*FDIM];
__device__ float g_w2R [(size_t)FDIM*MLPD];

// ---------------- helpers -----------------------------------------------------
__device__ __forceinline__ float rtf(float x) {   // round-to-nearest tf32
    uint32_t u;
    asm("cvt.rna.tf32.f32 %0, %1;" : "=r"(u) : "f"(x));
    return __uint_as_float(u);
}
#define CP16(dst, src) \
    asm volatile("cp.async.cg.shared.global [%0], [%1], 16;" :: "r"(dst), "l"(src))
#define CP_COMMIT() asm volatile("cp.async.commit_group;" ::: "memory")
#define CP_WAIT(n)  asm volatile("cp.async.wait_group %0;" :: "n"(n) : "memory")
#define LDSM4(r0, r1, r2, r3, addr) \
    asm volatile("ldmatrix.sync.aligned.m8n8.x4.shared.b16 {%0,%1,%2,%3}, [%4];" \
                 : "=r"(r0), "=r"(r1), "=r"(r2), "=r"(r3) : "r"(addr))
__device__ __forceinline__ uint32_t s2u(const void* p) {
    uint32_t a;
    asm("{ .reg .u64 t; cvta.to.shared.u64 t, %1; cvt.u32.u64 %0, t; }" : "=r"(a) : "l"(p));
    return a;
}
__device__ __forceinline__ void mma_tf32(float* c, const uint32_t* a, const uint32_t* b) {
    asm volatile(
        "mma.sync.aligned.m16n8k8.row.col.f32.tf32.tf32.f32 "
        "{%0,%1,%2,%3}, {%4,%5,%6,%7}, {%8,%9}, {%0,%1,%2,%3};"
        : "+f"(c[0]), "+f"(c[1]), "+f"(c[2]), "+f"(c[3])
        : "r"(a[0]), "r"(a[1]), "r"(a[2]), "r"(a[3]), "r"(b[0]), "r"(b[1]));
}
static __device__ __forceinline__ float gelu_tanh(float v) {
    float t = tanhf(0.7978845608028654f * (v + 0.044715f * v * v * v));
    return 0.5f * v * (1.f + t);
}

// ---------------- tf32 mma GEMM: C[M,N]=A[M,K]@B[N,K]^T ----------------------
// 128x128 tile, K-chunk 32, 2-stage cp.async, ldmatrix fragment loads.
// EPI: 0=bias+clip+L1norm64  1=bias+res  2=bias+gelu(round)  3=plain
//      4=fused NNMF-B: h=l1norm64(clip(h_in*acc)); writes C=h, aux=hT(rounded)
#define SMP 36
#define STG (128*SMP)
#define MM_SMEM (4*STG*4)   // 73728 B

template <int EPI>
__global__ __launch_bounds__(256) void mma_gemm(
    const float* __restrict__ A, const float* __restrict__ B,
    const float* __restrict__ bias, const float* __restrict__ res,
    float* __restrict__ C, float* __restrict__ aux, int K, int N,
    long long sB, long long sC)
{
    extern __shared__ float sm[];
    const int tid = threadIdx.x, wid = tid >> 5, lane = tid & 31;
    const int grp = lane >> 2, qid = lane & 3;
    const int n0 = blockIdx.x * 128;
    const size_t m0 = (size_t)blockIdx.y * 128;
    B += (size_t)blockIdx.z * sB;
    C += (size_t)blockIdx.z * sC;
    if (EPI == 1 || EPI == 4) res += (size_t)blockIdx.z * sC;
    if (EPI == 4) aux += (size_t)blockIdx.z * sC;
    const int wm = (wid & 1) * 64, wn = (wid >> 1) * 32;
    const uint32_t sAu = s2u(sm);

    const int t8 = lane >> 3, r8 = lane & 7;
    const int rowA = wm + (t8 & 1) * 8 + r8;
    const int colA = (t8 >> 1) * 4;
    const int rowB = wn + (t8 >> 1) * 8 + r8;
    const int colB = (t8 & 1) * 4;

    auto load_chunk = [&](int st, int kt) {
        uint32_t base = sAu + (uint32_t)(st * 2 * STG) * 4;
#pragma unroll
        for (int i = 0; i < 4; i++) {
            int id = tid + 256 * i;
            int row = id >> 3, kq = (id & 7) * 4;
            CP16(base + (uint32_t)(row * SMP + kq) * 4, &A[(m0 + row) * K + kt + kq]);
        }
        base += STG * 4;
#pragma unroll
        for (int i = 0; i < 4; i++) {
            int id = tid + 256 * i;
            int row = id >> 3, kq = (id & 7) * 4;
            CP16(base + (uint32_t)(row * SMP + kq) * 4, &B[(size_t)(n0 + row) * K + kt + kq]);
        }
        CP_COMMIT();
    };

    float cfr[4][4][4];
#pragma unroll
    for (int mt = 0; mt < 4; mt++)
#pragma unroll
        for (int nt = 0; nt < 4; nt++)
#pragma unroll
            for (int i = 0; i < 4; i++) cfr[mt][nt][i] = 0.f;

    const int nch = K >> 5;
    load_chunk(0, 0);
    if (nch > 1) load_chunk(1, 32);

    for (int c = 0; c < nch; c++) {
        if (c + 1 < nch) CP_WAIT(1);
        else             CP_WAIT(0);
        __syncthreads();
        const uint32_t sAs = sAu + (uint32_t)((c & 1) * 2 * STG) * 4;
        const uint32_t sBs = sAs + STG * 4;
#pragma unroll
        for (int kk = 0; kk < 32; kk += 8) {
            uint32_t af[4][4], bf[2][4];
#pragma unroll
            for (int mt = 0; mt < 4; mt++)
                LDSM4(af[mt][0], af[mt][1], af[mt][2], af[mt][3],
                      sAs + (uint32_t)((rowA + mt * 16) * SMP + kk + colA) * 4);
#pragma unroll
            for (int ntp = 0; ntp < 2; ntp++)
                LDSM4(bf[ntp][0], bf[ntp][1], bf[ntp][2], bf[ntp][3],
                      sBs + (uint32_t)((rowB + ntp * 16) * SMP + kk + colB) * 4);
#pragma unroll
            for (int mt = 0; mt < 4; mt++)
#pragma unroll
                for (int nt = 0; nt < 4; nt++)
                    mma_tf32(cfr[mt][nt], af[mt], &bf[nt >> 1][(nt & 1) * 2]);
        }
        __syncthreads();
        if (c + 2 < nch) load_chunk(c & 1, (c + 2) * 32);
    }

    if (EPI == 0 || EPI == 4) {
        float* Ts   = sm;           // [128][132] staging (EPI4)
        float* psum = sm + 16896;   // [128][5]
#pragma unroll
        for (int mt = 0; mt < 4; mt++) {
            const size_t r0 = m0 + wm + mt * 16 + grp;
#pragma unroll
            for (int nt = 0; nt < 4; nt++) {
                const int col = n0 + wn + nt * 8 + qid * 2;
                if (EPI == 0) {
                    float2 bv = *(const float2*)&bias[col];
                    cfr[mt][nt][0] = fmaxf(cfr[mt][nt][0] + bv.x, MIN_POS);
                    cfr[mt][nt][1] = fmaxf(cfr[mt][nt][1] + bv.y, MIN_POS);
                    cfr[mt][nt][2] = fmaxf(cfr[mt][nt][2] + bv.x, MIN_POS);
                    cfr[mt][nt][3] = fmaxf(cfr[mt][nt][3] + bv.y, MIN_POS);
                } else {
                    float2 ha = *(const float2*)&res[r0 * N + col];
                    float2 hb = *(const float2*)&res[(r0 + 8) * N + col];
                    cfr[mt][nt][0] = fmaxf(cfr[mt][nt][0] * ha.x, MIN_POS);
                    cfr[mt][nt][1] = fmaxf(cfr[mt][nt][1] * ha.y, MIN_POS);
                    cfr[mt][nt][2] = fmaxf(cfr[mt][nt][2] * hb.x, MIN_POS);
                    cfr[mt][nt][3] = fmaxf(cfr[mt][nt][3] * hb.y, MIN_POS);
                }
            }
        }
#pragma unroll
        for (int mt = 0; mt < 4; mt++) {
#pragma unroll
            for (int rs = 0; rs < 2; rs++) {
                float s = 0.f;
#pragma unroll
                for (int nt = 0; nt < 4; nt++) s += cfr[mt][nt][rs*2] + cfr[mt][nt][rs*2+1];
                s += __shfl_xor_sync(0xffffffffu, s, 1);
                s += __shfl_xor_sync(0xffffffffu, s, 2);
                int row = wm + mt * 16 + grp + rs * 8;
                if (qid == 0) psum[row * 5 + (wid >> 1)] = s;
            }
        }
        __syncthreads();
        const int gc = (wid >> 2) * 2;
#pragma unroll
        for (int mt = 0; mt < 4; mt++) {
            const size_t r0 = m0 + wm + mt * 16 + grp;
            float inv0 = 1.f / (psum[(wm + mt*16 + grp) * 5 + gc]     + psum[(wm + mt*16 + grp) * 5 + gc + 1]);
            float inv1 = 1.f / (psum[(wm + mt*16 + grp + 8) * 5 + gc] + psum[(wm + mt*16 + grp + 8) * 5 + gc + 1]);
#pragma unroll
            for (int nt = 0; nt < 4; nt++) {
                const int col = wn + nt * 8 + qid * 2;
                float v0 = cfr[mt][nt][0] * inv0, v1 = cfr[mt][nt][1] * inv0;
                float v2 = cfr[mt][nt][2] * inv1, v3 = cfr[mt][nt][3] * inv1;
                float2 o0; o0.x = v0; o0.y = v1;
                float2 o1; o1.x = v2; o1.y = v3;
                *(float2*)&C[r0 * N + n0 + col] = o0;
                *(float2*)&C[(r0 + 8) * N + n0 + col] = o1;
                if (EPI == 4) {
                    int rr = wm + mt * 16 + grp;
                    Ts[(col + 0) * 132 + rr]     = rtf(v0);
                    Ts[(col + 1) * 132 + rr]     = rtf(v1);
                    Ts[(col + 0) * 132 + rr + 8] = rtf(v2);
                    Ts[(col + 1) * 132 + rr + 8] = rtf(v3);
                }
            }
        }
        if (EPI == 4) {
            __syncthreads();
#pragma unroll
            for (int q = 0; q < 16; q++) {
                int idx = q * 1024 + tid * 4;
                int col = idx >> 7, row = idx & 127;
                float4 v = *(const float4*)&Ts[col * 132 + row];
                *(float4*)&aux[(size_t)(n0 + col) * 256 + m0 + row] = v;
            }
        }
        return;
    }

#pragma unroll
    for (int mt = 0; mt < 4; mt++) {
        const size_t r0 = m0 + wm + mt * 16 + grp;
#pragma unroll
        for (int nt = 0; nt < 4; nt++) {
            const int col = n0 + wn + nt * 8 + qid * 2;
            float bx = 0.f, by = 0.f;
            if (EPI != 3) {
                float2 bv = *(const float2*)&bias[col];
                bx = bv.x; by = bv.y;
            }
            float v0 = cfr[mt][nt][0] + bx, v1 = cfr[mt][nt][1] + by;
            float v2 = cfr[mt][nt][2] + bx, v3 = cfr[mt][nt][3] + by;
            if (EPI == 1) {
                float2 ra = *(const float2*)&res[r0 * N + col];
                float2 rb = *(const float2*)&res[(r0 + 8) * N + col];
                v0 += ra.x; v1 += ra.y; v2 += rb.x; v3 += rb.y;
            } else if (EPI == 2) {
                v0 = rtf(gelu_tanh(v0)); v1 = rtf(gelu_tanh(v1));
                v2 = rtf(gelu_tanh(v2)); v3 = rtf(gelu_tanh(v3));
            }
            float2 o0; o0.x = v0; o0.y = v1;
            float2 o1; o1.x = v2; o1.y = v3;
            *(float2*)&C[r0 * N + col] = o0;
            *(float2*)&C[(r0 + 8) * N + col] = o1;
        }
    }
}

// ---------------- elementwise tf32 round -------------------------------------
__global__ __launch_bounds__(256) void round_kernel(
    const float* __restrict__ in, float* __restrict__ out, int n4)
{
    int i = blockIdx.x * 256 + threadIdx.x;
    if (i < n4) {
        float4 v = *(const float4*)&in[i * 4];
        v.x = rtf(v.x); v.y = rtf(v.y); v.z = rtf(v.z); v.w = rtf(v.w);
        *(float4*)&out[i * 4] = v;
    }
}

// ---------------- batched transpose [R,C]->[C,R], tf32-rounded ---------------
__global__ void transpose_kernel(
    const float* __restrict__ in, float* __restrict__ out, int R, int C)
{
    __shared__ float t[32][33];
    in  += (size_t)blockIdx.z * R * C;
    out += (size_t)blockIdx.z * R * C;
    int r0 = blockIdx.y * 32, c0 = blockIdx.x * 32;
    int lx = threadIdx.x, ly = threadIdx.y;
#pragma unroll
    for (int i = 0; i < 32; i += 8)
        t[ly + i][lx] = rtf(in[(size_t)(r0 + ly + i) * C + c0 + lx]);
    __syncthreads();
#pragma unroll
    for (int i = 0; i < 32; i += 8)
        out[(size_t)(c0 + ly + i) * R + r0 + lx] = t[lx][ly + i];
}

// ---------------- LayerNorm (tf32-rounded output) -----------------------------
__global__ __launch_bounds__(256) void ln_kernel(
    const float* __restrict__ x, const float* __restrict__ g,
    const float* __restrict__ b, float* __restrict__ out)
{
    int row  = blockIdx.x * 8 + (threadIdx.x >> 5);
    int lane = threadIdx.x & 31;
    const float* xr = x + (size_t)row * 512;
    float4 v[4];
    float s = 0.f, sq = 0.f;
#pragma unroll
    for (int w = 0; w < 4; w++) {
        v[w] = *(const float4*)&xr[w * 128 + lane * 4];
        s  += v[w].x + v[w].y + v[w].z + v[w].w;
        sq += v[w].x*v[w].x + v[w].y*v[w].y + v[w].z*v[w].z + v[w].w*v[w].w;
    }
#pragma unroll
    for (int off = 16; off > 0; off >>= 1) {
        s  += __shfl_xor_sync(0xffffffffu, s,  off);
        sq += __shfl_xor_sync(0xffffffffu, sq, off);
    }
    float mu = s * (1.f / 512.f);
    float var = sq * (1.f / 512.f) - mu * mu;
    float rstd = rsqrtf(var + 1e-5f);
    float* orow = out + (size_t)row * 512;
#pragma unroll
    for (int w = 0; w < 4; w++) {
        int c = w * 128 + lane * 4;
        float4 gv = *(const float4*)&g[c];
        float4 bv = *(const float4*)&b[c];
        float4 o;
        o.x = rtf((v[w].x - mu) * rstd * gv.x + bv.x);
        o.y = rtf((v[w].y - mu) * rstd * gv.y + bv.y);
        o.z = rtf((v[w].z - mu) * rstd * gv.z + bv.z);
        o.w = rtf((v[w].w - mu) * rstd * gv.w + bv.w);
        *(float4*)&orow[c] = o;
    }
}

// ---------------- NNMF A lite (tensor-core local mixes) ----------------------
// per (itile, head, b): reads t1[b,i,e]; writes u1T[b,e,i] (rounded);
// r[b,i,e] (rounded) if WR.
// mix1: rc[i][f] = sum_g t1[i][g] lw[g][f]; clamp; row L1 sums;
// xr = xe*s/rc; mix2: u1[i][g] = sum_f xr[i][f] lw[g][f].
#define LITE_SMEM ((8704 + 4352 + 4352) * 4)   // t1s[128][68] + lwT[64][68] + lwS[64][68]

template <bool WR>
__global__ __launch_bounds__(256) void nnmfA_lite(
    const float* __restrict__ t1, const float* __restrict__ lw,
    const float* __restrict__ xe, float* __restrict__ r_out,
    float* __restrict__ u1T)
{
    extern __shared__ float smf[];
    float* t1s = smf;             // [128][68]; reused for xr, then Ts[64][132]
    float* lwT = smf + 8704;      // [64][68]  B mix1: lwT[f][g]=lw[g][f]
    float* lwS = smf + 13056;     // [64][68]  B mix2: lwS[g][f]=lw[g][f]
    const uint32_t sT = s2u(t1s), sL1 = s2u(lwT), sL2 = s2u(lwS);

    const int tid = threadIdx.x, wid = tid >> 5, lane = tid & 31;
    const int grp = lane >> 2, qid = lane & 3;
    const int t8 = lane >> 3, r8 = lane & 7;
    const int i0 = blockIdx.x * 128, head = blockIdx.y, b = blockIdx.z;
    const int wm = wid * 16;

    // lw (rounded): both layouts
#pragma unroll
    for (int q = 0; q < 16; q++) {
        int idx = q * 256 + tid;
        int g = idx >> 6, f = idx & 63;
        float v = rtf(lw[idx]);
        lwT[f * 68 + g] = v;
        lwS[g * 68 + f] = v;
    }
    // t1 tile [128][64] (rounded)
    const size_t base = ((size_t)b * SEQ + i0) * 512 + head * 64;
#pragma unroll
    for (int q = 0; q < 8; q++) {
        int idx = q * 256 + tid;
        int row = idx >> 4, c4 = (idx & 15) * 4;
        float4 v = *(const float4*)&t1[base + (size_t)row * 512 + c4];
        float* d = &t1s[row * 68 + c4];
        d[0] = rtf(v.x); d[1] = rtf(v.y); d[2] = rtf(v.z); d[3] = rtf(v.w);
    }
    __syncthreads();

    const uint32_t aBase = sT + (uint32_t)((wm + (t8 & 1) * 8 + r8) * 68 + (t8 >> 1) * 4) * 4;
    const int bRow = (t8 >> 1) * 8 + r8, bCol = (t8 & 1) * 4;

    // ---- mix1 ----
    float rc[8][4];
#pragma unroll
    for (int nt = 0; nt < 8; nt++)
#pragma unroll
        for (int j = 0; j < 4; j++) rc[nt][j] = 0.f;
#pragma unroll
    for (int kk = 0; kk < 64; kk += 8) {
        uint32_t af[4], bf[4][4];
        LDSM4(af[0], af[1], af[2], af[3], aBase + (uint32_t)kk * 4);
#pragma unroll
        for (int n2 = 0; n2 < 4; n2++)
            LDSM4(bf[n2][0], bf[n2][1], bf[n2][2], bf[n2][3],
                  sL1 + (uint32_t)((n2 * 16 + bRow) * 68 + kk + bCol) * 4);
#pragma unroll
        for (int nt = 0; nt < 8; nt++)
            mma_tf32(rc[nt], af, &bf[nt >> 1][(nt & 1) * 2]);
    }
    // clamp + row L1 sums (rows fully in-warp)
    float s0 = 0.f, s1 = 0.f;
#pragma unroll
    for (int nt = 0; nt < 8; nt++) {
#pragma unroll
        for (int j = 0; j < 4; j++) rc[nt][j] = fmaxf(rc[nt][j], MIN_POS);
        s0 += rc[nt][0] + rc[nt][1];
        s1 += rc[nt][2] + rc[nt][3];
    }
    s0 += __shfl_xor_sync(0xffffffffu, s0, 1);
    s0 += __shfl_xor_sync(0xffffffffu, s0, 2);
    s1 += __shfl_xor_sync(0xffffffffu, s1, 1);
    s1 += __shfl_xor_sync(0xffffffffu, s1, 2);

    __syncthreads();   // done reading t1s via ldmatrix
    {
        const size_t ra = base + (size_t)(wm + grp) * 512;
        const size_t rb = base + (size_t)(wm + grp + 8) * 512;
        const float inv0 = 1.f / s0, inv1 = 1.f / s1;
#pragma unroll
        for (int nt = 0; nt < 8; nt++) {
            const int f = nt * 8 + qid * 2;
            float2 x0 = *(const float2*)&xe[ra + f];
            float2 x1 = *(const float2*)&xe[rb + f];
            if (WR) {
                float2 rv0; rv0.x = rtf(rc[nt][0] * inv0); rv0.y = rtf(rc[nt][1] * inv0);
                float2 rv1; rv1.x = rtf(rc[nt][2] * inv1); rv1.y = rtf(rc[nt][3] * inv1);
                *(float2*)&r_out[ra + f] = rv0;
                *(float2*)&r_out[rb + f] = rv1;
            }
            t1s[(wm + grp) * 68 + f]         = rtf(x0.x * s0 / rc[nt][0]);
            t1s[(wm + grp) * 68 + f + 1]     = rtf(x0.y * s0 / rc[nt][1]);
            t1s[(wm + grp + 8) * 68 + f]     = rtf(x1.x * s1 / rc[nt][2]);
            t1s[(wm + grp + 8) * 68 + f + 1] = rtf(x1.y * s1 / rc[nt][3]);
        }
    }
    __syncthreads();

    // ---- mix2 ----
    float uu[8][4];
#pragma unroll
    for (int nt = 0; nt < 8; nt++)
#pragma unroll
        for (int j = 0; j < 4; j++) uu[nt][j] = 0.f;
#pragma unroll
    for (int kk = 0; kk < 64; kk += 8) {
        uint32_t af[4], bf[4][4];
        LDSM4(af[0], af[1], af[2], af[3], aBase + (uint32_t)kk * 4);
#pragma unroll
        for (int n2 = 0; n2 < 4; n2++)
            LDSM4(bf[n2][0], bf[n2][1], bf[n2][2], bf[n2][3],
                  sL2 + (uint32_t)((n2 * 16 + bRow) * 68 + kk + bCol) * 4);
#pragma unroll
        for (int nt = 0; nt < 8; nt++)
            mma_tf32(uu[nt], af, &bf[nt >> 1][(nt & 1) * 2]);
    }
    __syncthreads();   // done reading t1s (xr)

    // stage u1 transposed [g][i] and write u1T coalesced
    float* Ts = t1s;   // [64][132]
#pragma unroll
    for (int nt = 0; nt < 8; nt++) {
        const int g = nt * 8 + qid * 2;
        Ts[(g + 0) * 132 + wm + grp]     = rtf(uu[nt][0]);
        Ts[(g + 1) * 132 + wm + grp]     = rtf(uu[nt][1]);
        Ts[(g + 0) * 132 + wm + grp + 8] = rtf(uu[nt][2]);
        Ts[(g + 1) * 132 + wm + grp + 8] = rtf(uu[nt][3]);
    }
    __syncthreads();
    const size_t ubase = ((size_t)b * 512 + head * 64) * 256 + i0;
#pragma unroll
    for (int q = 0; q < 8; q++) {
        int idx = q * 1024 + tid * 4;
        int g = idx >> 7, m = idx & 127;
        float4 v = *(const float4*)&Ts[g * 132 + m];
        *(float4*)&u1T[ubase + (size_t)g * 256 + m] = v;
    }
}

// ---------------- host launcher -----------------------------------------------
extern "C" void kernel_launch(void* const* d_in, const int* in_sizes, int n_in,
                              void* d_out, int out_size)
{
    const float* x    = (const float*)d_in[0];
    const float* ew   = (const float*)d_in[1];
    const float* eb   = (const float*)d_in[2];
    const float* lw   = (const float*)d_in[3];
    const float* gw   = (const float*)d_in[4];
    const float* ow   = (const float*)d_in[5];
    const float* ob   = (const float*)d_in[6];
    const float* ln1g = (const float*)d_in[7];
    const float* ln1b = (const float*)d_in[8];
    const float* ln2g = (const float*)d_in[9];
    const float* ln2b = (const float*)d_in[10];
    const float* w1   = (const float*)d_in[11];
    const float* b1   = (const float*)d_in[12];
    const float* w2   = (const float*)d_in[13];
    const float* b2   = (const float*)d_in[14];
    const float* h0   = (const float*)d_in[15];
    float* out = (float*)d_out;

    float *xn, *xe, *h, *hT, *u1T, *t1, *r, *xres, *mlp, *gwT, *gwR;
    float *ewR, *owR, *w1R, *w2R;
    cudaGetSymbolAddress((void**)&xn,   g_xn);
    cudaGetSymbolAddress((void**)&xe,   g_xe);
    cudaGetSymbolAddress((void**)&h,    g_h);
    cudaGetSymbolAddress((void**)&hT,   g_hT);
    cudaGetSymbolAddress((void**)&u1T,  g_u1T);
    cudaGetSymbolAddress((void**)&t1,   g_t1);
    cudaGetSymbolAddress((void**)&r,    g_r);
    cudaGetSymbolAddress((void**)&xres, g_xres);
    cudaGetSymbolAddress((void**)&mlp,  g_mlp);
    cudaGetSymbolAddress((void**)&gwT,  g_gwT);
    cudaGetSymbolAddress((void**)&gwR,  g_gwR);
    cudaGetSymbolAddress((void**)&ewR,  g_ewR);
    cudaGetSymbolAddress((void**)&owR,  g_owR);
    cudaGetSymbolAddress((void**)&w1R,  g_w1R);
    cudaGetSymbolAddress((void**)&w2R,  g_w2R);

    cudaFuncSetAttribute(mma_gemm<0>, cudaFuncAttributeMaxDynamicSharedMemorySize, MM_SMEM);
    cudaFuncSetAttribute(mma_gemm<1>, cudaFuncAttributeMaxDynamicSharedMemorySize, MM_SMEM);
    cudaFuncSetAttribute(mma_gemm<2>, cudaFuncAttributeMaxDynamicSharedMemorySize, MM_SMEM);
    cudaFuncSetAttribute(mma_gemm<3>, cudaFuncAttributeMaxDynamicSharedMemorySize, MM_SMEM);
    cudaFuncSetAttribute(mma_gemm<4>, cudaFuncAttributeMaxDynamicSharedMemorySize, MM_SMEM);
    cudaFuncSetAttribute(nnmfA_lite<false>, cudaFuncAttributeMaxDynamicSharedMemorySize, LITE_SMEM);
    cudaFuncSetAttribute(nnmfA_lite<true>,  cudaFuncAttributeMaxDynamicSharedMemorySize, LITE_SMEM);

    const long long SB = 512LL * 256;
    const long long SC = 256LL * 512;

    round_kernel<<<(512*512/4+255)/256, 256>>>(ew, ewR, 512*512/4);
    round_kernel<<<(512*512/4+255)/256, 256>>>(ow, owR, 512*512/4);
    round_kernel<<<(2048*512/4+255)/256, 256>>>(w1, w1R, 2048*512/4);
    round_kernel<<<(2048*512/4+255)/256, 256>>>(w2, w2R, 2048*512/4);
    round_kernel<<<(256*256/4+255)/256, 256>>>(gw, gwR, 256*256/4);
    transpose_kernel<<<dim3(8, 8, 1), dim3(32, 8)>>>(gw, gwT, 256, 256);
    transpose_kernel<<<dim3(16, 8, 128), dim3(32, 8)>>>(h0, hT, 256, 512);

    ln_kernel<<<BSROWS / 8, 256>>>(x, ln1g, ln1b, xn);
    mma_gemm<0><<<dim3(4, 256, 1), 256, MM_SMEM>>>(xn, ewR, eb, nullptr, xe, nullptr, 512, 512, 0, 0);

    for (int it = 0; it < 10; it++) {
        mma_gemm<3><<<dim3(4, 2, 128), 256, MM_SMEM>>>(gwT, hT, nullptr, nullptr, t1, nullptr, 256, 512, SB, SC);
        if (it < 9) {
            nnmfA_lite<false><<<dim3(2, HEADS, BSZ), 256, LITE_SMEM>>>(t1, lw, xe, r, u1T);
            mma_gemm<4><<<dim3(4, 2, 128), 256, MM_SMEM>>>(gwR, u1T, nullptr,
                (it == 0) ? h0 : h, h, hT, 256, 512, SB, SC);
        } else {
            nnmfA_lite<true><<<dim3(2, HEADS, BSZ), 256, LITE_SMEM>>>(t1, lw, xe, r, u1T);
        }
    }

    mma_gemm<1><<<dim3(4, 256, 1), 256, MM_SMEM>>>(r, owR, ob, x, xres, nullptr, 512, 512, 0, 0);
    ln_kernel<<<BSROWS / 8, 256>>>(xres, ln2g, ln2b, xn);
    mma_gemm<2><<<dim3(16, 256, 1), 256, MM_SMEM>>>(xn, w1R, b1, nullptr, mlp, nullptr, 512, 2048, 0, 0);
    mma_gemm<1><<<dim3(4, 256, 1), 256, MM_SMEM>>>(mlp, w2R, b2, xres, out, nullptr, 2048, 512, 0, 0);
}

// round 8
// speedup vs baseline: 2.8923x; 1.0835x over previous
#include <cuda_runtime.h>
#include <cstdint>

#define BSZ   128
#define SEQ   256
#define FDIM  512
#define EDIM  512
#define HEADS 8
#define BSROWS (BSZ*SEQ)
#define MLPD  2048
#define MIN_POS 1e-6f

__device__ float g_xn  [(size_t)BSROWS*FDIM];
__device__ float g_xe  [(size_t)BSROWS*EDIM];
__device__ float g_h   [(size_t)BSROWS*EDIM];   // h  [b,o,e]
__device__ float g_hT  [(size_t)BSROWS*EDIM];   // hT [b,e,o] (tf32-rounded)
__device__ float g_u1T [(size_t)BSROWS*EDIM];   // u1T[b,e,i] (tf32-rounded)
__device__ float g_r   [(size_t)BSROWS*EDIM];
__device__ float g_xres[(size_t)BSROWS*FDIM];
__device__ float g_mlp [(size_t)BSROWS*MLPD];
__device__ float g_gwT [(size_t)SEQ*SEQ];
__device__ float g_gwR [(size_t)SEQ*SEQ];
__device__ float g_ewR [(size_t)EDIM*FDIM];
__device__ float g_owR [(size_t)FDIM*EDIM];
__device__ float g_w1R [(size_t)MLPD*FDIM];
__device__ float g_w2R [(size_t)FDIM*MLPD];

// ---------------- helpers -----------------------------------------------------
__device__ __forceinline__ float rtf(float x) {   // round-to-nearest tf32
    uint32_t u;
    asm("cvt.rna.tf32.f32 %0, %1;" : "=r"(u) : "f"(x));
    return __uint_as_float(u);
}
#define CP16(dst, src) \
    asm volatile("cp.async.cg.shared.global [%0], [%1], 16;" :: "r"(dst), "l"(src))
#define CP_COMMIT() asm volatile("cp.async.commit_group;" ::: "memory")
#define CP_WAIT(n)  asm volatile("cp.async.wait_group %0;" :: "n"(n) : "memory")
#define LDSM4(r0, r1, r2, r3, addr) \
    asm volatile("ldmatrix.sync.aligned.m8n8.x4.shared.b16 {%0,%1,%2,%3}, [%4];" \
                 : "=r"(r0), "=r"(r1), "=r"(r2), "=r"(r3) : "r"(addr))
__device__ __forceinline__ uint32_t s2u(const void* p) {
    uint32_t a;
    asm("{ .reg .u64 t; cvta.to.shared.u64 t, %1; cvt.u32.u64 %0, t; }" : "=r"(a) : "l"(p));
    return a;
}
__device__ __forceinline__ void mma_tf32(float* c, const uint32_t* a, const uint32_t* b) {
    asm volatile(
        "mma.sync.aligned.m16n8k8.row.col.f32.tf32.tf32.f32 "
        "{%0,%1,%2,%3}, {%4,%5,%6,%7}, {%8,%9}, {%0,%1,%2,%3};"
        : "+f"(c[0]), "+f"(c[1]), "+f"(c[2]), "+f"(c[3])
        : "r"(a[0]), "r"(a[1]), "r"(a[2]), "r"(a[3]), "r"(b[0]), "r"(b[1]));
}
static __device__ __forceinline__ float gelu_tanh(float v) {
    float t = tanhf(0.7978845608028654f * (v + 0.044715f * v * v * v));
    return 0.5f * v * (1.f + t);
}

// ---------------- tf32 mma GEMM: C[M,N]=A[M,K]@B[N,K]^T ----------------------
// 128x128 tile, K-chunk 32, 2-stage cp.async, ldmatrix fragment loads.
// EPI: 0=bias+clip+L1norm64  1=bias+res  2=bias+gelu(round)  3=plain
//      4=fused NNMF-B: h=l1norm64(clip(h_in*acc)); C=h, aux=hT(rounded)
//      5=fused NNMF-A: local mixes on t1 fragments; bias=lw, res=xe, aux=u1T
//      6=fused NNMF-A last iter: only r=l1norm(clip(t1@lw)); C=r
#define SMP 36
#define STG (128*SMP)
#define MM_SMEM (4*STG*4)     // 73728 B
#define MM_SMEM5 102400       // t1s[128][132] + lwT[64][68] + lwS[64][68]

template <int EPI>
__global__ __launch_bounds__(256) void mma_gemm(
    const float* __restrict__ A, const float* __restrict__ B,
    const float* __restrict__ bias, const float* __restrict__ res,
    float* __restrict__ C, float* __restrict__ aux, int K, int N,
    long long sB, long long sC)
{
    extern __shared__ float sm[];
    const int tid = threadIdx.x, wid = tid >> 5, lane = tid & 31;
    const int grp = lane >> 2, qid = lane & 3;
    const int n0 = blockIdx.x * 128;
    const size_t m0 = (size_t)blockIdx.y * 128;
    B += (size_t)blockIdx.z * sB;
    C += (size_t)blockIdx.z * sC;
    if (EPI == 1 || EPI == 4 || EPI == 5) res += (size_t)blockIdx.z * sC;
    if (EPI == 4 || EPI == 5) aux += (size_t)blockIdx.z * sC;
    const int wm = (wid & 1) * 64, wn = (wid >> 1) * 32;
    const uint32_t sAu = s2u(sm);

    const int t8 = lane >> 3, r8 = lane & 7;
    const int rowA = wm + (t8 & 1) * 8 + r8;
    const int colA = (t8 >> 1) * 4;
    const int rowB = wn + (t8 >> 1) * 8 + r8;
    const int colB = (t8 & 1) * 4;

    auto load_chunk = [&](int st, int kt) {
        uint32_t base = sAu + (uint32_t)(st * 2 * STG) * 4;
#pragma unroll
        for (int i = 0; i < 4; i++) {
            int id = tid + 256 * i;
            int row = id >> 3, kq = (id & 7) * 4;
            CP16(base + (uint32_t)(row * SMP + kq) * 4, &A[(m0 + row) * K + kt + kq]);
        }
        base += STG * 4;
#pragma unroll
        for (int i = 0; i < 4; i++) {
            int id = tid + 256 * i;
            int row = id >> 3, kq = (id & 7) * 4;
            CP16(base + (uint32_t)(row * SMP + kq) * 4, &B[(size_t)(n0 + row) * K + kt + kq]);
        }
        CP_COMMIT();
    };

    float cfr[4][4][4];
#pragma unroll
    for (int mt = 0; mt < 4; mt++)
#pragma unroll
        for (int nt = 0; nt < 4; nt++)
#pragma unroll
            for (int i = 0; i < 4; i++) cfr[mt][nt][i] = 0.f;

    const int nch = K >> 5;
    load_chunk(0, 0);
    if (nch > 1) load_chunk(1, 32);

    for (int c = 0; c < nch; c++) {
        if (c + 1 < nch) CP_WAIT(1);
        else             CP_WAIT(0);
        __syncthreads();
        const uint32_t sAs = sAu + (uint32_t)((c & 1) * 2 * STG) * 4;
        const uint32_t sBs = sAs + STG * 4;
#pragma unroll
        for (int kk = 0; kk < 32; kk += 8) {
            uint32_t af[4][4], bf[2][4];
#pragma unroll
            for (int mt = 0; mt < 4; mt++)
                LDSM4(af[mt][0], af[mt][1], af[mt][2], af[mt][3],
                      sAs + (uint32_t)((rowA + mt * 16) * SMP + kk + colA) * 4);
#pragma unroll
            for (int ntp = 0; ntp < 2; ntp++)
                LDSM4(bf[ntp][0], bf[ntp][1], bf[ntp][2], bf[ntp][3],
                      sBs + (uint32_t)((rowB + ntp * 16) * SMP + kk + colB) * 4);
#pragma unroll
            for (int mt = 0; mt < 4; mt++)
#pragma unroll
                for (int nt = 0; nt < 4; nt++)
                    mma_tf32(cfr[mt][nt], af[mt], &bf[nt >> 1][(nt & 1) * 2]);
        }
        __syncthreads();
        if (c + 2 < nch) load_chunk(c & 1, (c + 2) * 32);
    }

    if (EPI == 5 || EPI == 6) {
        // ---- fused NNMF-A epilogue ----
        float* t1s = sm;             // [128][132]
        float* lwT = sm + 16896;     // [64][68] : lwT[f][g] = lw[g][f]
        float* lwS = sm + 21248;     // [64][68] : lwS[g][f] = lw[g][f]
        const uint32_t sT = sAu, sL1 = s2u(lwT), sL2 = s2u(lwS);
        // load lw (rounded) both layouts
#pragma unroll
        for (int q = 0; q < 16; q++) {
            int idx = q * 256 + tid;
            int g = idx >> 6, f = idx & 63;
            float v = rtf(bias[idx]);
            lwT[f * 68 + g] = v;
            lwS[g * 68 + f] = v;
        }
        // stage t1 fragments (rounded)
#pragma unroll
        for (int mt = 0; mt < 4; mt++) {
            const int row = wm + mt * 16 + grp;
#pragma unroll
            for (int nt = 0; nt < 4; nt++) {
                const int col = wn + nt * 8 + qid * 2;
                t1s[row * 132 + col]           = rtf(cfr[mt][nt][0]);
                t1s[row * 132 + col + 1]       = rtf(cfr[mt][nt][1]);
                t1s[(row + 8) * 132 + col]     = rtf(cfr[mt][nt][2]);
                t1s[(row + 8) * 132 + col + 1] = rtf(cfr[mt][nt][3]);
            }
        }
        __syncthreads();

        const int wm16 = wid * 16;
        const uint32_t aB0 = sT + (uint32_t)((wm16 + (t8 & 1) * 8 + r8) * 132 + (t8 >> 1) * 4) * 4;
        const int bRow2 = (t8 >> 1) * 8 + r8, bCol2 = (t8 & 1) * 4;

#pragma unroll
        for (int hp = 0; hp < 2; hp++) {
            const uint32_t aB = aB0 + (uint32_t)(hp * 64) * 4;
            // mix1: rc[i][f] = sum_g t1[i][g] lw[g][f]
            float rc[8][4];
#pragma unroll
            for (int nt = 0; nt < 8; nt++)
#pragma unroll
                for (int j = 0; j < 4; j++) rc[nt][j] = 0.f;
#pragma unroll
            for (int kk = 0; kk < 64; kk += 8) {
                uint32_t af[4], bf[4][4];
                LDSM4(af[0], af[1], af[2], af[3], aB + (uint32_t)kk * 4);
#pragma unroll
                for (int n2 = 0; n2 < 4; n2++)
                    LDSM4(bf[n2][0], bf[n2][1], bf[n2][2], bf[n2][3],
                          sL1 + (uint32_t)((n2 * 16 + bRow2) * 68 + kk + bCol2) * 4);
#pragma unroll
                for (int nt = 0; nt < 8; nt++)
                    mma_tf32(rc[nt], af, &bf[nt >> 1][(nt & 1) * 2]);
            }
            float s0 = 0.f, s1 = 0.f;
#pragma unroll
            for (int nt = 0; nt < 8; nt++) {
#pragma unroll
                for (int j = 0; j < 4; j++) rc[nt][j] = fmaxf(rc[nt][j], MIN_POS);
                s0 += rc[nt][0] + rc[nt][1];
                s1 += rc[nt][2] + rc[nt][3];
            }
            s0 += __shfl_xor_sync(0xffffffffu, s0, 1);
            s0 += __shfl_xor_sync(0xffffffffu, s0, 2);
            s1 += __shfl_xor_sync(0xffffffffu, s1, 1);
            s1 += __shfl_xor_sync(0xffffffffu, s1, 2);

            const size_t ra = (m0 + wm16 + grp) * (size_t)N + n0 + hp * 64;
            const size_t rb = ra + 8 * (size_t)N;

            if (EPI == 6) {
                // r = rc / s only
                const float inv0 = 1.f / s0, inv1 = 1.f / s1;
#pragma unroll
                for (int nt = 0; nt < 8; nt++) {
                    const int f = nt * 8 + qid * 2;
                    float2 rv0; rv0.x = rtf(rc[nt][0] * inv0); rv0.y = rtf(rc[nt][1] * inv0);
                    float2 rv1; rv1.x = rtf(rc[nt][2] * inv1); rv1.y = rtf(rc[nt][3] * inv1);
                    *(float2*)&C[ra + f] = rv0;
                    *(float2*)&C[rb + f] = rv1;
                }
                continue;
            }

            // xr = xe*s/rc -> t1s (warp-private rows)
#pragma unroll
            for (int nt = 0; nt < 8; nt++) {
                const int f = nt * 8 + qid * 2;
                float2 x0 = *(const float2*)&res[ra + f];
                float2 x1 = *(const float2*)&res[rb + f];
                t1s[(wm16 + grp) * 132 + hp * 64 + f]         = rtf(x0.x * s0 / rc[nt][0]);
                t1s[(wm16 + grp) * 132 + hp * 64 + f + 1]     = rtf(x0.y * s0 / rc[nt][1]);
                t1s[(wm16 + grp + 8) * 132 + hp * 64 + f]     = rtf(x1.x * s1 / rc[nt][2]);
                t1s[(wm16 + grp + 8) * 132 + hp * 64 + f + 1] = rtf(x1.y * s1 / rc[nt][3]);
            }
            __syncwarp();

            // mix2: u1[i][g] = sum_f xr[i][f] lw[g][f]
            float uu[8][4];
#pragma unroll
            for (int nt = 0; nt < 8; nt++)
#pragma unroll
                for (int j = 0; j < 4; j++) uu[nt][j] = 0.f;
#pragma unroll
            for (int kk = 0; kk < 64; kk += 8) {
                uint32_t af[4], bf[4][4];
                LDSM4(af[0], af[1], af[2], af[3], aB + (uint32_t)kk * 4);
#pragma unroll
                for (int n2 = 0; n2 < 4; n2++)
                    LDSM4(bf[n2][0], bf[n2][1], bf[n2][2], bf[n2][3],
                          sL2 + (uint32_t)((n2 * 16 + bRow2) * 68 + kk + bCol2) * 4);
#pragma unroll
                for (int nt = 0; nt < 8; nt++)
                    mma_tf32(uu[nt], af, &bf[nt >> 1][(nt & 1) * 2]);
            }
            // direct u1T stores: aux[(e)*256 + i], 32B-sector aligned over grp
            {
                const size_t eb = (size_t)(n0 + hp * 64) * 256 + m0;
                const int i = wm16 + grp;
#pragma unroll
                for (int nt = 0; nt < 8; nt++) {
                    const int g = nt * 8 + qid * 2;
                    aux[eb + (size_t)g * 256 + i]           = rtf(uu[nt][0]);
                    aux[eb + (size_t)(g + 1) * 256 + i]     = rtf(uu[nt][1]);
                    aux[eb + (size_t)g * 256 + i + 8]       = rtf(uu[nt][2]);
                    aux[eb + (size_t)(g + 1) * 256 + i + 8] = rtf(uu[nt][3]);
                }
            }
        }
        return;
    }

    if (EPI == 0 || EPI == 4) {
        float* Ts   = sm;           // [128][132] staging (EPI4)
        float* psum = sm + 16896;   // [128][5]
#pragma unroll
        for (int mt = 0; mt < 4; mt++) {
            const size_t r0 = m0 + wm + mt * 16 + grp;
#pragma unroll
            for (int nt = 0; nt < 4; nt++) {
                const int col = n0 + wn + nt * 8 + qid * 2;
                if (EPI == 0) {
                    float2 bv = *(const float2*)&bias[col];
                    cfr[mt][nt][0] = fmaxf(cfr[mt][nt][0] + bv.x, MIN_POS);
                    cfr[mt][nt][1] = fmaxf(cfr[mt][nt][1] + bv.y, MIN_POS);
                    cfr[mt][nt][2] = fmaxf(cfr[mt][nt][2] + bv.x, MIN_POS);
                    cfr[mt][nt][3] = fmaxf(cfr[mt][nt][3] + bv.y, MIN_POS);
                } else {
                    float2 ha = *(const float2*)&res[r0 * N + col];
                    float2 hb = *(const float2*)&res[(r0 + 8) * N + col];
                    cfr[mt][nt][0] = fmaxf(cfr[mt][nt][0] * ha.x, MIN_POS);
                    cfr[mt][nt][1] = fmaxf(cfr[mt][nt][1] * ha.y, MIN_POS);
                    cfr[mt][nt][2] = fmaxf(cfr[mt][nt][2] * hb.x, MIN_POS);
                    cfr[mt][nt][3] = fmaxf(cfr[mt][nt][3] * hb.y, MIN_POS);
                }
            }
        }
#pragma unroll
        for (int mt = 0; mt < 4; mt++) {
#pragma unroll
            for (int rs = 0; rs < 2; rs++) {
                float s = 0.f;
#pragma unroll
                for (int nt = 0; nt < 4; nt++) s += cfr[mt][nt][rs*2] + cfr[mt][nt][rs*2+1];
                s += __shfl_xor_sync(0xffffffffu, s, 1);
                s += __shfl_xor_sync(0xffffffffu, s, 2);
                int row = wm + mt * 16 + grp + rs * 8;
                if (qid == 0) psum[row * 5 + (wid >> 1)] = s;
            }
        }
        __syncthreads();
        const int gc = (wid >> 2) * 2;
#pragma unroll
        for (int mt = 0; mt < 4; mt++) {
            const size_t r0 = m0 + wm + mt * 16 + grp;
            float inv0 = 1.f / (psum[(wm + mt*16 + grp) * 5 + gc]     + psum[(wm + mt*16 + grp) * 5 + gc + 1]);
            float inv1 = 1.f / (psum[(wm + mt*16 + grp + 8) * 5 + gc] + psum[(wm + mt*16 + grp + 8) * 5 + gc + 1]);
#pragma unroll
            for (int nt = 0; nt < 4; nt++) {
                const int col = wn + nt * 8 + qid * 2;
                float v0 = cfr[mt][nt][0] * inv0, v1 = cfr[mt][nt][1] * inv0;
                float v2 = cfr[mt][nt][2] * inv1, v3 = cfr[mt][nt][3] * inv1;
                float2 o0; o0.x = v0; o0.y = v1;
                float2 o1; o1.x = v2; o1.y = v3;
                *(float2*)&C[r0 * N + n0 + col] = o0;
                *(float2*)&C[(r0 + 8) * N + n0 + col] = o1;
                if (EPI == 4) {
                    int rr = wm + mt * 16 + grp;
                    Ts[(col + 0) * 132 + rr]     = rtf(v0);
                    Ts[(col + 1) * 132 + rr]     = rtf(v1);
                    Ts[(col + 0) * 132 + rr + 8] = rtf(v2);
                    Ts[(col + 1) * 132 + rr + 8] = rtf(v3);
                }
            }
        }
        if (EPI == 4) {
            __syncthreads();
#pragma unroll
            for (int q = 0; q < 16; q++) {
                int idx = q * 1024 + tid * 4;
                int col = idx >> 7, row = idx & 127;
                float4 v = *(const float4*)&Ts[col * 132 + row];
                *(float4*)&aux[(size_t)(n0 + col) * 256 + m0 + row] = v;
            }
        }
        return;
    }

#pragma unroll
    for (int mt = 0; mt < 4; mt++) {
        const size_t r0 = m0 + wm + mt * 16 + grp;
#pragma unroll
        for (int nt = 0; nt < 4; nt++) {
            const int col = n0 + wn + nt * 8 + qid * 2;
            float bx = 0.f, by = 0.f;
            if (EPI != 3) {
                float2 bv = *(const float2*)&bias[col];
                bx = bv.x; by = bv.y;
            }
            float v0 = cfr[mt][nt][0] + bx, v1 = cfr[mt][nt][1] + by;
            float v2 = cfr[mt][nt][2] + bx, v3 = cfr[mt][nt][3] + by;
            if (EPI == 1) {
                float2 ra = *(const float2*)&res[r0 * N + col];
                float2 rb = *(const float2*)&res[(r0 + 8) * N + col];
                v0 += ra.x; v1 += ra.y; v2 += rb.x; v3 += rb.y;
            } else if (EPI == 2) {
                v0 = rtf(gelu_tanh(v0)); v1 = rtf(gelu_tanh(v1));
                v2 = rtf(gelu_tanh(v2)); v3 = rtf(gelu_tanh(v3));
            }
            float2 o0; o0.x = v0; o0.y = v1;
            float2 o1; o1.x = v2; o1.y = v3;
            *(float2*)&C[r0 * N + col] = o0;
            *(float2*)&C[(r0 + 8) * N + col] = o1;
        }
    }
}

// ---------------- elementwise tf32 round -------------------------------------
__global__ __launch_bounds__(256) void round_kernel(
    const float* __restrict__ in, float* __restrict__ out, int n4)
{
    int i = blockIdx.x * 256 + threadIdx.x;
    if (i < n4) {
        float4 v = *(const float4*)&in[i * 4];
        v.x = rtf(v.x); v.y = rtf(v.y); v.z = rtf(v.z); v.w = rtf(v.w);
        *(float4*)&out[i * 4] = v;
    }
}

// ---------------- batched transpose [R,C]->[C,R], tf32-rounded ---------------
__global__ void transpose_kernel(
    const float* __restrict__ in, float* __restrict__ out, int R, int C)
{
    __shared__ float t[32][33];
    in  += (size_t)blockIdx.z * R * C;
    out += (size_t)blockIdx.z * R * C;
    int r0 = blockIdx.y * 32, c0 = blockIdx.x * 32;
    int lx = threadIdx.x, ly = threadIdx.y;
#pragma unroll
    for (int i = 0; i < 32; i += 8)
        t[ly + i][lx] = rtf(in[(size_t)(r0 + ly + i) * C + c0 + lx]);
    __syncthreads();
#pragma unroll
    for (int i = 0; i < 32; i += 8)
        out[(size_t)(c0 + ly + i) * R + r0 + lx] = t[lx][ly + i];
}

// ---------------- LayerNorm (tf32-rounded output) -----------------------------
__global__ __launch_bounds__(256) void ln_kernel(
    const float* __restrict__ x, const float* __restrict__ g,
    const float* __restrict__ b, float* __restrict__ out)
{
    int row  = blockIdx.x * 8 + (threadIdx.x >> 5);
    int lane = threadIdx.x & 31;
    const float* xr = x + (size_t)row * 512;
    float4 v[4];
    float s = 0.f, sq = 0.f;
#pragma unroll
    for (int w = 0; w < 4; w++) {
        v[w] = *(const float4*)&xr[w * 128 + lane * 4];
        s  += v[w].x + v[w].y + v[w].z + v[w].w;
        sq += v[w].x*v[w].x + v[w].y*v[w].y + v[w].z*v[w].z + v[w].w*v[w].w;
    }
#pragma unroll
    for (int off = 16; off > 0; off >>= 1) {
        s  += __shfl_xor_sync(0xffffffffu, s,  off);
        sq += __shfl_xor_sync(0xffffffffu, sq, off);
    }
    float mu = s * (1.f / 512.f);
    float var = sq * (1.f / 512.f) - mu * mu;
    float rstd = rsqrtf(var + 1e-5f);
    float* orow = out + (size_t)row * 512;
#pragma unroll
    for (int w = 0; w < 4; w++) {
        int c = w * 128 + lane * 4;
        float4 gv = *(const float4*)&g[c];
        float4 bv = *(const float4*)&b[c];
        float4 o;
        o.x = rtf((v[w].x - mu) * rstd * gv.x + bv.x);
        o.y = rtf((v[w].y - mu) * rstd * gv.y + bv.y);
        o.z = rtf((v[w].z - mu) * rstd * gv.z + bv.z);
        o.w = rtf((v[w].w - mu) * rstd * gv.w + bv.w);
        *(float4*)&orow[c] = o;
    }
}

// ---------------- host launcher -----------------------------------------------
extern "C" void kernel_launch(void* const* d_in, const int* in_sizes, int n_in,
                              void* d_out, int out_size)
{
    const float* x    = (const float*)d_in[0];
    const float* ew   = (const float*)d_in[1];
    const float* eb   = (const float*)d_in[2];
    const float* lw   = (const float*)d_in[3];
    const float* gw   = (const float*)d_in[4];
    const float* ow   = (const float*)d_in[5];
    const float* ob   = (const float*)d_in[6];
    const float* ln1g = (const float*)d_in[7];
    const float* ln1b = (const float*)d_in[8];
    const float* ln2g = (const float*)d_in[9];
    const float* ln2b = (const float*)d_in[10];
    const float* w1   = (const float*)d_in[11];
    const float* b1   = (const float*)d_in[12];
    const float* w2   = (const float*)d_in[13];
    const float* b2   = (const float*)d_in[14];
    const float* h0   = (const float*)d_in[15];
    float* out = (float*)d_out;

    float *xn, *xe, *h, *hT, *u1T, *r, *xres, *mlp, *gwT, *gwR;
    float *ewR, *owR, *w1R, *w2R;
    cudaGetSymbolAddress((void**)&xn,   g_xn);
    cudaGetSymbolAddress((void**)&xe,   g_xe);
    cudaGetSymbolAddress((void**)&h,    g_h);
    cudaGetSymbolAddress((void**)&hT,   g_hT);
    cudaGetSymbolAddress((void**)&u1T,  g_u1T);
    cudaGetSymbolAddress((void**)&r,    g_r);
    cudaGetSymbolAddress((void**)&xres, g_xres);
    cudaGetSymbolAddress((void**)&mlp,  g_mlp);
    cudaGetSymbolAddress((void**)&gwT,  g_gwT);
    cudaGetSymbolAddress((void**)&gwR,  g_gwR);
    cudaGetSymbolAddress((void**)&ewR,  g_ewR);
    cudaGetSymbolAddress((void**)&owR,  g_owR);
    cudaGetSymbolAddress((void**)&w1R,  g_w1R);
    cudaGetSymbolAddress((void**)&w2R,  g_w2R);

    cudaFuncSetAttribute(mma_gemm<0>, cudaFuncAttributeMaxDynamicSharedMemorySize, MM_SMEM);
    cudaFuncSetAttribute(mma_gemm<1>, cudaFuncAttributeMaxDynamicSharedMemorySize, MM_SMEM);
    cudaFuncSetAttribute(mma_gemm<2>, cudaFuncAttributeMaxDynamicSharedMemorySize, MM_SMEM);
    cudaFuncSetAttribute(mma_gemm<3>, cudaFuncAttributeMaxDynamicSharedMemorySize, MM_SMEM);
    cudaFuncSetAttribute(mma_gemm<4>, cudaFuncAttributeMaxDynamicSharedMemorySize, MM_SMEM);
    cudaFuncSetAttribute(mma_gemm<5>, cudaFuncAttributeMaxDynamicSharedMemorySize, MM_SMEM5);
    cudaFuncSetAttribute(mma_gemm<6>, cudaFuncAttributeMaxDynamicSharedMemorySize, MM_SMEM5);

    const long long SB = 512LL * 256;
    const long long SC = 256LL * 512;

    round_kernel<<<(512*512/4+255)/256, 256>>>(ew, ewR, 512*512/4);
    round_kernel<<<(512*512/4+255)/256, 256>>>(ow, owR, 512*512/4);
    round_kernel<<<(2048*512/4+255)/256, 256>>>(w1, w1R, 2048*512/4);
    round_kernel<<<(2048*512/4+255)/256, 256>>>(w2, w2R, 2048*512/4);
    round_kernel<<<(256*256/4+255)/256, 256>>>(gw, gwR, 256*256/4);
    transpose_kernel<<<dim3(8, 8, 1), dim3(32, 8)>>>(gw, gwT, 256, 256);
    transpose_kernel<<<dim3(16, 8, 128), dim3(32, 8)>>>(h0, hT, 256, 512);

    ln_kernel<<<BSROWS / 8, 256>>>(x, ln1g, ln1b, xn);
    mma_gemm<0><<<dim3(4, 256, 1), 256, MM_SMEM>>>(xn, ewR, eb, nullptr, xe, nullptr, 512, 512, 0, 0);

    for (int it = 0; it < 10; it++) {
        if (it < 9) {
            // fused: t1 = gwT @ hT (fragments) -> local mixes -> u1T
            mma_gemm<5><<<dim3(4, 2, 128), 256, MM_SMEM5>>>(gwT, hT, lw, xe, r, u1T, 256, 512, SB, SC);
            // fused: acc = gw @ u1 ; h = l1norm(clip(h*acc)) ; writes h and hT
            mma_gemm<4><<<dim3(4, 2, 128), 256, MM_SMEM>>>(gwR, u1T, nullptr,
                (it == 0) ? h0 : h, h, hT, 256, 512, SB, SC);
        } else {
            // last iter: only r = l1norm(clip(t1 @ lw))
            mma_gemm<6><<<dim3(4, 2, 128), 256, MM_SMEM5>>>(gwT, hT, lw, xe, r, u1T, 256, 512, SB, SC);
        }
    }

    mma_gemm<1><<<dim3(4, 256, 1), 256, MM_SMEM>>>(r, owR, ob, x, xres, nullptr, 512, 512, 0, 0);
    ln_kernel<<<BSROWS / 8, 256>>>(xres, ln2g, ln2b, xn);
    mma_gemm<2><<<dim3(16, 256, 1), 256, MM_SMEM>>>(xn, w1R, b1, nullptr, mlp, nullptr, 512, 2048, 0, 0);
    mma_gemm<1><<<dim3(4, 256, 1), 256, MM_SMEM>>>(mlp, w2R, b2, xres, out, nullptr, 2048, 512, 0, 0);
}

// round 10
// speedup vs baseline: 3.1187x; 1.0783x over previous
#include <cuda_runtime.h>
#include <cstdint>

#define BSZ   128
#define SEQ   256
#define FDIM  512
#define EDIM  512
#define HEADS 8
#define BSROWS (BSZ*SEQ)
#define MLPD  2048
#define MIN_POS 1e-6f

__device__ float g_xn  [(size_t)BSROWS*FDIM];
__device__ float g_xe  [(size_t)BSROWS*EDIM];
__device__ float g_h   [(size_t)BSROWS*EDIM];   // h  [b,o,e]
__device__ float g_hT  [(size_t)BSROWS*EDIM];   // hT [b,e,o] (tf32-rounded)
__device__ float g_u1T [(size_t)BSROWS*EDIM];   // u1T[b,e,i] (tf32-rounded)
__device__ float g_r   [(size_t)BSROWS*EDIM];
__device__ float g_xres[(size_t)BSROWS*FDIM];
__device__ float g_mlp [(size_t)BSROWS*MLPD];
__device__ float g_gwT [(size_t)SEQ*SEQ];
__device__ float g_gwR [(size_t)SEQ*SEQ];
__device__ float g_ewR [(size_t)EDIM*FDIM];
__device__ float g_owR [(size_t)FDIM*EDIM];
__device__ float g_w1R [(size_t)MLPD*FDIM];
__device__ float g_w2R [(size_t)FDIM*MLPD];

// ---------------- helpers -----------------------------------------------------
__device__ __forceinline__ float rtf(float x) {   // round-to-nearest tf32
    uint32_t u;
    asm("cvt.rna.tf32.f32 %0, %1;" : "=r"(u) : "f"(x));
    return __uint_as_float(u);
}
#define CP16(dst, src) \
    asm volatile("cp.async.cg.shared.global [%0], [%1], 16;" :: "r"(dst), "l"(src))
#define CP_COMMIT() asm volatile("cp.async.commit_group;" ::: "memory")
#define CP_WAIT(n)  asm volatile("cp.async.wait_group %0;" :: "n"(n) : "memory")
#define LDSM4(r0, r1, r2, r3, addr) \
    asm volatile("ldmatrix.sync.aligned.m8n8.x4.shared.b16 {%0,%1,%2,%3}, [%4];" \
                 : "=r"(r0), "=r"(r1), "=r"(r2), "=r"(r3) : "r"(addr))
__device__ __forceinline__ uint32_t s2u(const void* p) {
    uint32_t a;
    asm("{ .reg .u64 t; cvta.to.shared.u64 t, %1; cvt.u32.u64 %0, t; }" : "=r"(a) : "l"(p));
    return a;
}
__device__ __forceinline__ void mma_tf32(float* c, const uint32_t* a, const uint32_t* b) {
    asm volatile(
        "mma.sync.aligned.m16n8k8.row.col.f32.tf32.tf32.f32 "
        "{%0,%1,%2,%3}, {%4,%5,%6,%7}, {%8,%9}, {%0,%1,%2,%3};"
        : "+f"(c[0]), "+f"(c[1]), "+f"(c[2]), "+f"(c[3])
        : "r"(a[0]), "r"(a[1]), "r"(a[2]), "r"(a[3]), "r"(b[0]), "r"(b[1]));
}
static __device__ __forceinline__ float gelu_tanh(float v) {
    float t = tanhf(0.7978845608028654f * (v + 0.044715f * v * v * v));
    return 0.5f * v * (1.f + t);
}

// ---------------- tf32 mma GEMM: C[M,N]=A[M,K]@B[N,K]^T ----------------------
// 128x128 tile, K-chunk 32, 2-stage cp.async, ldmatrix fragment loads.
// EPI: 0=bias+clip+L1norm64  1=bias+res  2=bias+gelu(round)  3=plain
//      4=fused NNMF-B: h=l1norm64(clip(h_in*acc)); C=h, aux=hT(rounded)
//      5=fused NNMF-A: local mixes on t1 fragments; bias=lw, res=xe, aux=u1T
//      6=fused NNMF-A last iter: only r=l1norm(clip(t1@lw)); C=r
#define SMP 36
#define STG (128*SMP)
#define MM_SMEM (4*STG*4)     // 73728 B
#define MM_SMEM5 102400       // t1s[128][132] + lwT[64][68] + lwS[64][68]

template <int EPI>
__global__ __launch_bounds__(256, 2) void mma_gemm(
    const float* __restrict__ A, const float* __restrict__ B,
    const float* __restrict__ bias, const float* __restrict__ res,
    float* __restrict__ C, float* __restrict__ aux, int K, int N,
    long long sB, long long sC)
{
    extern __shared__ float sm[];
    const int tid = threadIdx.x, wid = tid >> 5, lane = tid & 31;
    const int grp = lane >> 2, qid = lane & 3;
    const int n0 = blockIdx.x * 128;
    const size_t m0 = (size_t)blockIdx.y * 128;
    B += (size_t)blockIdx.z * sB;
    C += (size_t)blockIdx.z * sC;
    if (EPI == 1 || EPI == 4 || EPI == 5) res += (size_t)blockIdx.z * sC;
    if (EPI == 4 || EPI == 5) aux += (size_t)blockIdx.z * sC;
    const int wm = (wid & 1) * 64, wn = (wid >> 1) * 32;
    const uint32_t sAu = s2u(sm);

    const int t8 = lane >> 3, r8 = lane & 7;
    const int rowA = wm + (t8 & 1) * 8 + r8;
    const int colA = (t8 >> 1) * 4;
    const int rowB = wn + (t8 >> 1) * 8 + r8;
    const int colB = (t8 & 1) * 4;

    auto load_chunk = [&](int st, int kt) {
        uint32_t base = sAu + (uint32_t)(st * 2 * STG) * 4;
#pragma unroll
        for (int i = 0; i < 4; i++) {
            int id = tid + 256 * i;
            int row = id >> 3, kq = (id & 7) * 4;
            CP16(base + (uint32_t)(row * SMP + kq) * 4, &A[(m0 + row) * K + kt + kq]);
        }
        base += STG * 4;
#pragma unroll
        for (int i = 0; i < 4; i++) {
            int id = tid + 256 * i;
            int row = id >> 3, kq = (id & 7) * 4;
            CP16(base + (uint32_t)(row * SMP + kq) * 4, &B[(size_t)(n0 + row) * K + kt + kq]);
        }
        CP_COMMIT();
    };

    float cfr[4][4][4];
#pragma unroll
    for (int mt = 0; mt < 4; mt++)
#pragma unroll
        for (int nt = 0; nt < 4; nt++)
#pragma unroll
            for (int i = 0; i < 4; i++) cfr[mt][nt][i] = 0.f;

    const int nch = K >> 5;
    load_chunk(0, 0);
    if (nch > 1) load_chunk(1, 32);

    for (int c = 0; c < nch; c++) {
        if (c + 1 < nch) CP_WAIT(1);
        else             CP_WAIT(0);
        __syncthreads();
        const uint32_t sAs = sAu + (uint32_t)((c & 1) * 2 * STG) * 4;
        const uint32_t sBs = sAs + STG * 4;
#pragma unroll
        for (int kk = 0; kk < 32; kk += 8) {
            uint32_t af[4][4], bf[2][4];
#pragma unroll
            for (int mt = 0; mt < 4; mt++)
                LDSM4(af[mt][0], af[mt][1], af[mt][2], af[mt][3],
                      sAs + (uint32_t)((rowA + mt * 16) * SMP + kk + colA) * 4);
#pragma unroll
            for (int ntp = 0; ntp < 2; ntp++)
                LDSM4(bf[ntp][0], bf[ntp][1], bf[ntp][2], bf[ntp][3],
                      sBs + (uint32_t)((rowB + ntp * 16) * SMP + kk + colB) * 4);
#pragma unroll
            for (int mt = 0; mt < 4; mt++)
#pragma unroll
                for (int nt = 0; nt < 4; nt++)
                    mma_tf32(cfr[mt][nt], af[mt], &bf[nt >> 1][(nt & 1) * 2]);
        }
        __syncthreads();
        if (c + 2 < nch) load_chunk(c & 1, (c + 2) * 32);
    }

    if (EPI == 5 || EPI == 6) {
        // ---- fused NNMF-A epilogue ----
        float* t1s = sm;             // [128][132]
        float* lwT = sm + 16896;     // [64][68] : lwT[f][g] = lw[g][f]
        float* lwS = sm + 21248;     // [64][68] : lwS[g][f] = lw[g][f]
        const uint32_t sT = sAu, sL1 = s2u(lwT), sL2 = s2u(lwS);
        // load lw (rounded) both layouts
#pragma unroll
        for (int q = 0; q < 16; q++) {
            int idx = q * 256 + tid;
            int g = idx >> 6, f = idx & 63;
            float v = rtf(bias[idx]);
            lwT[f * 68 + g] = v;
            lwS[g * 68 + f] = v;
        }
        // stage t1 fragments (rounded)
#pragma unroll
        for (int mt = 0; mt < 4; mt++) {
            const int row = wm + mt * 16 + grp;
#pragma unroll
            for (int nt = 0; nt < 4; nt++) {
                const int col = wn + nt * 8 + qid * 2;
                t1s[row * 132 + col]           = rtf(cfr[mt][nt][0]);
                t1s[row * 132 + col + 1]       = rtf(cfr[mt][nt][1]);
                t1s[(row + 8) * 132 + col]     = rtf(cfr[mt][nt][2]);
                t1s[(row + 8) * 132 + col + 1] = rtf(cfr[mt][nt][3]);
            }
        }
        __syncthreads();

        const int wm16 = wid * 16;
        const uint32_t aB0 = sT + (uint32_t)((wm16 + (t8 & 1) * 8 + r8) * 132 + (t8 >> 1) * 4) * 4;
        const int bRow2 = (t8 >> 1) * 8 + r8, bCol2 = (t8 & 1) * 4;

#pragma unroll
        for (int hp = 0; hp < 2; hp++) {
            const uint32_t aB = aB0 + (uint32_t)(hp * 64) * 4;
            // mix1: rc[i][f] = sum_g t1[i][g] lw[g][f]
            float rc[8][4];
#pragma unroll
            for (int nt = 0; nt < 8; nt++)
#pragma unroll
                for (int j = 0; j < 4; j++) rc[nt][j] = 0.f;
#pragma unroll
            for (int kk = 0; kk < 64; kk += 8) {
                uint32_t af[4], bf[4][4];
                LDSM4(af[0], af[1], af[2], af[3], aB + (uint32_t)kk * 4);
#pragma unroll
                for (int n2 = 0; n2 < 4; n2++)
                    LDSM4(bf[n2][0], bf[n2][1], bf[n2][2], bf[n2][3],
                          sL1 + (uint32_t)((n2 * 16 + bRow2) * 68 + kk + bCol2) * 4);
#pragma unroll
                for (int nt = 0; nt < 8; nt++)
                    mma_tf32(rc[nt], af, &bf[nt >> 1][(nt & 1) * 2]);
            }
            float s0 = 0.f, s1 = 0.f;
#pragma unroll
            for (int nt = 0; nt < 8; nt++) {
#pragma unroll
                for (int j = 0; j < 4; j++) rc[nt][j] = fmaxf(rc[nt][j], MIN_POS);
                s0 += rc[nt][0] + rc[nt][1];
                s1 += rc[nt][2] + rc[nt][3];
            }
            s0 += __shfl_xor_sync(0xffffffffu, s0, 1);
            s0 += __shfl_xor_sync(0xffffffffu, s0, 2);
            s1 += __shfl_xor_sync(0xffffffffu, s1, 1);
            s1 += __shfl_xor_sync(0xffffffffu, s1, 2);

            const size_t ra = (m0 + wm16 + grp) * (size_t)N + n0 + hp * 64;
            const size_t rb = ra + 8 * (size_t)N;

            if (EPI == 6) {
                const float inv0 = 1.f / s0, inv1 = 1.f / s1;
#pragma unroll
                for (int nt = 0; nt < 8; nt++) {
                    const int f = nt * 8 + qid * 2;
                    float2 rv0; rv0.x = rtf(rc[nt][0] * inv0); rv0.y = rtf(rc[nt][1] * inv0);
                    float2 rv1; rv1.x = rtf(rc[nt][2] * inv1); rv1.y = rtf(rc[nt][3] * inv1);
                    *(float2*)&C[ra + f] = rv0;
                    *(float2*)&C[rb + f] = rv1;
                }
                continue;
            }

            // xr = xe*s/rc -> t1s (warp-private rows)
#pragma unroll
            for (int nt = 0; nt < 8; nt++) {
                const int f = nt * 8 + qid * 2;
                float2 x0 = *(const float2*)&res[ra + f];
                float2 x1 = *(const float2*)&res[rb + f];
                t1s[(wm16 + grp) * 132 + hp * 64 + f]         = rtf(x0.x * s0 / rc[nt][0]);
                t1s[(wm16 + grp) * 132 + hp * 64 + f + 1]     = rtf(x0.y * s0 / rc[nt][1]);
                t1s[(wm16 + grp + 8) * 132 + hp * 64 + f]     = rtf(x1.x * s1 / rc[nt][2]);
                t1s[(wm16 + grp + 8) * 132 + hp * 64 + f + 1] = rtf(x1.y * s1 / rc[nt][3]);
            }
            __syncwarp();

            // mix2: u1[i][g] = sum_f xr[i][f] lw[g][f]
            float uu[8][4];
#pragma unroll
            for (int nt = 0; nt < 8; nt++)
#pragma unroll
                for (int j = 0; j < 4; j++) uu[nt][j] = 0.f;
#pragma unroll
            for (int kk = 0; kk < 64; kk += 8) {
                uint32_t af[4], bf[4][4];
                LDSM4(af[0], af[1], af[2], af[3], aB + (uint32_t)kk * 4);
#pragma unroll
                for (int n2 = 0; n2 < 4; n2++)
                    LDSM4(bf[n2][0], bf[n2][1], bf[n2][2], bf[n2][3],
                          sL2 + (uint32_t)((n2 * 16 + bRow2) * 68 + kk + bCol2) * 4);
#pragma unroll
                for (int nt = 0; nt < 8; nt++)
                    mma_tf32(uu[nt], af, &bf[nt >> 1][(nt & 1) * 2]);
            }
            // direct u1T stores: aux[(e)*256 + i]
            {
                const size_t eb = (size_t)(n0 + hp * 64) * 256 + m0;
                const int i = wm16 + grp;
#pragma unroll
                for (int nt = 0; nt < 8; nt++) {
                    const int g = nt * 8 + qid * 2;
                    aux[eb + (size_t)g * 256 + i]           = rtf(uu[nt][0]);
                    aux[eb + (size_t)(g + 1) * 256 + i]     = rtf(uu[nt][1]);
                    aux[eb + (size_t)g * 256 + i + 8]       = rtf(uu[nt][2]);
                    aux[eb + (size_t)(g + 1) * 256 + i + 8] = rtf(uu[nt][3]);
                }
            }
        }
        return;
    }

    if (EPI == 0 || EPI == 4) {
        float* Ts   = sm;           // [128][132] staging (EPI4)
        float* psum = sm + 16896;   // [128][5]
#pragma unroll
        for (int mt = 0; mt < 4; mt++) {
            const size_t r0 = m0 + wm + mt * 16 + grp;
#pragma unroll
            for (int nt = 0; nt < 4; nt++) {
                const int col = n0 + wn + nt * 8 + qid * 2;
                if (EPI == 0) {
                    float2 bv = *(const float2*)&bias[col];
                    cfr[mt][nt][0] = fmaxf(cfr[mt][nt][0] + bv.x, MIN_POS);
                    cfr[mt][nt][1] = fmaxf(cfr[mt][nt][1] + bv.y, MIN_POS);
                    cfr[mt][nt][2] = fmaxf(cfr[mt][nt][2] + bv.x, MIN_POS);
                    cfr[mt][nt][3] = fmaxf(cfr[mt][nt][3] + bv.y, MIN_POS);
                } else {
                    float2 ha = *(const float2*)&res[r0 * N + col];
                    float2 hb = *(const float2*)&res[(r0 + 8) * N + col];
                    cfr[mt][nt][0] = fmaxf(cfr[mt][nt][0] * ha.x, MIN_POS);
                    cfr[mt][nt][1] = fmaxf(cfr[mt][nt][1] * ha.y, MIN_POS);
                    cfr[mt][nt][2] = fmaxf(cfr[mt][nt][2] * hb.x, MIN_POS);
                    cfr[mt][nt][3] = fmaxf(cfr[mt][nt][3] * hb.y, MIN_POS);
                }
            }
        }
#pragma unroll
        for (int mt = 0; mt < 4; mt++) {
#pragma unroll
            for (int rs = 0; rs < 2; rs++) {
                float s = 0.f;
#pragma unroll
                for (int nt = 0; nt < 4; nt++) s += cfr[mt][nt][rs*2] + cfr[mt][nt][rs*2+1];
                s += __shfl_xor_sync(0xffffffffu, s, 1);
                s += __shfl_xor_sync(0xffffffffu, s, 2);
                int row = wm + mt * 16 + grp + rs * 8;
                if (qid == 0) psum[row * 5 + (wid >> 1)] = s;
            }
        }
        __syncthreads();
        const int gc = (wid >> 2) * 2;
#pragma unroll
        for (int mt = 0; mt < 4; mt++) {
            const size_t r0 = m0 + wm + mt * 16 + grp;
            float inv0 = 1.f / (psum[(wm + mt*16 + grp) * 5 + gc]     + psum[(wm + mt*16 + grp) * 5 + gc + 1]);
            float inv1 = 1.f / (psum[(wm + mt*16 + grp + 8) * 5 + gc] + psum[(wm + mt*16 + grp + 8) * 5 + gc + 1]);
#pragma unroll
            for (int nt = 0; nt < 4; nt++) {
                const int col = wn + nt * 8 + qid * 2;
                float v0 = cfr[mt][nt][0] * inv0, v1 = cfr[mt][nt][1] * inv0;
                float v2 = cfr[mt][nt][2] * inv1, v3 = cfr[mt][nt][3] * inv1;
                float2 o0; o0.x = v0; o0.y = v1;
                float2 o1; o1.x = v2; o1.y = v3;
                *(float2*)&C[r0 * N + n0 + col] = o0;
                *(float2*)&C[(r0 + 8) * N + n0 + col] = o1;
                if (EPI == 4) {
                    int rr = wm + mt * 16 + grp;
                    Ts[(col + 0) * 132 + rr]     = rtf(v0);
                    Ts[(col + 1) * 132 + rr]     = rtf(v1);
                    Ts[(col + 0) * 132 + rr + 8] = rtf(v2);
                    Ts[(col + 1) * 132 + rr + 8] = rtf(v3);
                }
            }
        }
        if (EPI == 4) {
            __syncthreads();
#pragma unroll
            for (int q = 0; q < 16; q++) {
                int idx = q * 1024 + tid * 4;
                int col = idx >> 7, row = idx & 127;
                float4 v = *(const float4*)&Ts[col * 132 + row];
                *(float4*)&aux[(size_t)(n0 + col) * 256 + m0 + row] = v;
            }
        }
        return;
    }

#pragma unroll
    for (int mt = 0; mt < 4; mt++) {
        const size_t r0 = m0 + wm + mt * 16 + grp;
#pragma unroll
        for (int nt = 0; nt < 4; nt++) {
            const int col = n0 + wn + nt * 8 + qid * 2;
            float bx = 0.f, by = 0.f;
            if (EPI != 3) {
                float2 bv = *(const float2*)&bias[col];
                bx = bv.x; by = bv.y;
            }
            float v0 = cfr[mt][nt][0] + bx, v1 = cfr[mt][nt][1] + by;
            float v2 = cfr[mt][nt][2] + bx, v3 = cfr[mt][nt][3] + by;
            if (EPI == 1) {
                float2 ra = *(const float2*)&res[r0 * N + col];
                float2 rb = *(const float2*)&res[(r0 + 8) * N + col];
                v0 += ra.x; v1 += ra.y; v2 += rb.x; v3 += rb.y;
            } else if (EPI == 2) {
                v0 = rtf(gelu_tanh(v0)); v1 = rtf(gelu_tanh(v1));
                v2 = rtf(gelu_tanh(v2)); v3 = rtf(gelu_tanh(v3));
            }
            float2 o0; o0.x = v0; o0.y = v1;
            float2 o1; o1.x = v2; o1.y = v3;
            *(float2*)&C[r0 * N + col] = o0;
            *(float2*)&C[(r0 + 8) * N + col] = o1;
        }
    }
}

// ---------------- fused prologue round (all 5 weight tensors) ----------------
__global__ __launch_bounds__(256) void prep_kernel(
    const float* __restrict__ ew, const float* __restrict__ ow,
    const float* __restrict__ w1, const float* __restrict__ w2,
    const float* __restrict__ gw,
    float* __restrict__ ewR, float* __restrict__ owR,
    float* __restrict__ w1R, float* __restrict__ w2R,
    float* __restrict__ gwR)
{
    int i = blockIdx.x * 256 + threadIdx.x;   // float4 index, total 671744
    const float* in; float* out; int off;
    if (i < 65536)        { in = ew; out = ewR; off = i; }
    else if (i < 131072)  { in = ow; out = owR; off = i - 65536; }
    else if (i < 393216)  { in = w1; out = w1R; off = i - 131072; }
    else if (i < 655360)  { in = w2; out = w2R; off = i - 393216; }
    else                  { in = gw; out = gwR; off = i - 655360; }
    float4 v = *(const float4*)&in[(size_t)off * 4];
    v.x = rtf(v.x); v.y = rtf(v.y); v.z = rtf(v.z); v.w = rtf(v.w);
    *(float4*)&out[(size_t)off * 4] = v;
}

// ---------------- batched transpose [R,C]->[C,R], tf32-rounded ---------------
__global__ void transpose_kernel(
    const float* __restrict__ in, float* __restrict__ out, int R, int C)
{
    __shared__ float t[32][33];
    in  += (size_t)blockIdx.z * R * C;
    out += (size_t)blockIdx.z * R * C;
    int r0 = blockIdx.y * 32, c0 = blockIdx.x * 32;
    int lx = threadIdx.x, ly = threadIdx.y;
#pragma unroll
    for (int i = 0; i < 32; i += 8)
        t[ly + i][lx] = rtf(in[(size_t)(r0 + ly + i) * C + c0 + lx]);
    __syncthreads();
#pragma unroll
    for (int i = 0; i < 32; i += 8)
        out[(size_t)(c0 + ly + i) * R + r0 + lx] = t[lx][ly + i];
}

// ---------------- LayerNorm (tf32-rounded output) -----------------------------
__global__ __launch_bounds__(256) void ln_kernel(
    const float* __restrict__ x, const float* __restrict__ g,
    const float* __restrict__ b, float* __restrict__ out)
{
    int row  = blockIdx.x * 8 + (threadIdx.x >> 5);
    int lane = threadIdx.x & 31;
    const float* xr = x + (size_t)row * 512;
    float4 v[4];
    float s = 0.f, sq = 0.f;
#pragma unroll
    for (int w = 0; w < 4; w++) {
        v[w] = *(const float4*)&xr[w * 128 + lane * 4];
        s  += v[w].x + v[w].y + v[w].z + v[w].w;
        sq += v[w].x*v[w].x + v[w].y*v[w].y + v[w].z*v[w].z + v[w].w*v[w].w;
    }
#pragma unroll
    for (int off = 16; off > 0; off >>= 1) {
        s  += __shfl_xor_sync(0xffffffffu, s,  off);
        sq += __shfl_xor_sync(0xffffffffu, sq, off);
    }
    float mu = s * (1.f / 512.f);
    float var = sq * (1.f / 512.f) - mu * mu;
    float rstd = rsqrtf(var + 1e-5f);
    float* orow = out + (size_t)row * 512;
#pragma unroll
    for (int w = 0; w < 4; w++) {
        int c = w * 128 + lane * 4;
        float4 gv = *(const float4*)&g[c];
        float4 bv = *(const float4*)&b[c];
        float4 o;
        o.x = rtf((v[w].x - mu) * rstd * gv.x + bv.x);
        o.y = rtf((v[w].y - mu) * rstd * gv.y + bv.y);
        o.z = rtf((v[w].z - mu) * rstd * gv.z + bv.z);
        o.w = rtf((v[w].w - mu) * rstd * gv.w + bv.w);
        *(float4*)&orow[c] = o;
    }
}

// ---------------- host launcher -----------------------------------------------
extern "C" void kernel_launch(void* const* d_in, const int* in_sizes, int n_in,
                              void* d_out, int out_size)
{
    const float* x    = (const float*)d_in[0];
    const float* ew   = (const float*)d_in[1];
    const float* eb   = (const float*)d_in[2];
    const float* lw   = (const float*)d_in[3];
    const float* gw   = (const float*)d_in[4];
    const float* ow   = (const float*)d_in[5];
    const float* ob   = (const float*)d_in[6];
    const float* ln1g = (const float*)d_in[7];
    const float* ln1b = (const float*)d_in[8];
    const float* ln2g = (const float*)d_in[9];
    const float* ln2b = (const float*)d_in[10];
    const float* w1   = (const float*)d_in[11];
    const float* b1   = (const float*)d_in[12];
    const float* w2   = (const float*)d_in[13];
    const float* b2   = (const float*)d_in[14];
    const float* h0   = (const float*)d_in[15];
    float* out = (float*)d_out;

    float *xn, *xe, *h, *hT, *u1T, *r, *xres, *mlp, *gwT, *gwR;
    float *ewR, *owR, *w1R, *w2R;
    cudaGetSymbolAddress((void**)&xn,   g_xn);
    cudaGetSymbolAddress((void**)&xe,   g_xe);
    cudaGetSymbolAddress((void**)&h,    g_h);
    cudaGetSymbolAddress((void**)&hT,   g_hT);
    cudaGetSymbolAddress((void**)&u1T,  g_u1T);
    cudaGetSymbolAddress((void**)&r,    g_r);
    cudaGetSymbolAddress((void**)&xres, g_xres);
    cudaGetSymbolAddress((void**)&mlp,  g_mlp);
    cudaGetSymbolAddress((void**)&gwT,  g_gwT);
    cudaGetSymbolAddress((void**)&gwR,  g_gwR);
    cudaGetSymbolAddress((void**)&ewR,  g_ewR);
    cudaGetSymbolAddress((void**)&owR,  g_owR);
    cudaGetSymbolAddress((void**)&w1R,  g_w1R);
    cudaGetSymbolAddress((void**)&w2R,  g_w2R);

    cudaFuncSetAttribute(mma_gemm<0>, cudaFuncAttributeMaxDynamicSharedMemorySize, MM_SMEM);
    cudaFuncSetAttribute(mma_gemm<1>, cudaFuncAttributeMaxDynamicSharedMemorySize, MM_SMEM);
    cudaFuncSetAttribute(mma_gemm<2>, cudaFuncAttributeMaxDynamicSharedMemorySize, MM_SMEM);
    cudaFuncSetAttribute(mma_gemm<3>, cudaFuncAttributeMaxDynamicSharedMemorySize, MM_SMEM);
    cudaFuncSetAttribute(mma_gemm<4>, cudaFuncAttributeMaxDynamicSharedMemorySize, MM_SMEM);
    cudaFuncSetAttribute(mma_gemm<5>, cudaFuncAttributeMaxDynamicSharedMemorySize, MM_SMEM5);
    cudaFuncSetAttribute(mma_gemm<6>, cudaFuncAttributeMaxDynamicSharedMemorySize, MM_SMEM5);

    const long long SB = 512LL * 256;
    const long long SC = 256LL * 512;

    // prologue: 5 launches total so ncu (-s 5) lands on the fused iter GEMM
    prep_kernel<<<(671744 + 255) / 256, 256>>>(ew, ow, w1, w2, gw,
                                               ewR, owR, w1R, w2R, gwR);
    transpose_kernel<<<dim3(8, 8, 1), dim3(32, 8)>>>(gw, gwT, 256, 256);
    transpose_kernel<<<dim3(16, 8, 128), dim3(32, 8)>>>(h0, hT, 256, 512);
    ln_kernel<<<BSROWS / 8, 256>>>(x, ln1g, ln1b, xn);
    mma_gemm<0><<<dim3(4, 256, 1), 256, MM_SMEM>>>(xn, ewR, eb, nullptr, xe, nullptr, 512, 512, 0, 0);

    for (int it = 0; it < 10; it++) {
        if (it < 9) {
            mma_gemm<5><<<dim3(4, 2, 128), 256, MM_SMEM5>>>(gwT, hT, lw, xe, r, u1T, 256, 512, SB, SC);
            mma_gemm<4><<<dim3(4, 2, 128), 256, MM_SMEM>>>(gwR, u1T, nullptr,
                (it == 0) ? h0 : h, h, hT, 256, 512, SB, SC);
        } else {
            mma_gemm<6><<<dim3(4, 2, 128), 256, MM_SMEM5>>>(gwT, hT, lw, xe, r, u1T, 256, 512, SB, SC);
        }
    }

    mma_gemm<1><<<dim3(4, 256, 1), 256, MM_SMEM>>>(r, owR, ob, x, xres, nullptr, 512, 512, 0, 0);
    ln_kernel<<<BSROWS / 8, 256>>>(xres, ln2g, ln2b, xn);
    mma_gemm<2><<<dim3(16, 256, 1), 256, MM_SMEM>>>(xn, w1R, b1, nullptr, mlp, nullptr, 512, 2048, 0, 0);
    mma_gemm<1><<<dim3(4, 256, 1), 256, MM_SMEM>>>(mlp, w2R, b2, xres, out, nullptr, 2048, 512, 0, 0);
}

// round 11
// speedup vs baseline: 3.2088x; 1.0289x over previous
#include <cuda_runtime.h>
#include <cstdint>

#define BSZ   128
#define SEQ   256
#define FDIM  512
#define EDIM  512
#define HEADS 8
#define BSROWS (BSZ*SEQ)
#define MLPD  2048
#define MIN_POS 1e-6f

__device__ float g_xn  [(size_t)BSROWS*FDIM];
__device__ float g_xe  [(size_t)BSROWS*EDIM];
__device__ float g_hT  [(size_t)BSROWS*EDIM];   // hT [b,e,o] (tf32-rounded state)
__device__ float g_u1T [(size_t)BSROWS*EDIM];   // u1T[b,e,i] (tf32-rounded)
__device__ float g_r   [(size_t)BSROWS*EDIM];
__device__ float g_xres[(size_t)BSROWS*FDIM];
__device__ float g_mlp [(size_t)BSROWS*MLPD];
__device__ float g_gwT [(size_t)SEQ*SEQ];
__device__ float g_gwR [(size_t)SEQ*SEQ];
__device__ float g_ewR [(size_t)EDIM*FDIM];
__device__ float g_owR [(size_t)FDIM*EDIM];
__device__ float g_w1R [(size_t)MLPD*FDIM];
__device__ float g_w2R [(size_t)FDIM*MLPD];

// ---------------- helpers -----------------------------------------------------
__device__ __forceinline__ float rtf(float x) {   // round-to-nearest tf32
    uint32_t u;
    asm("cvt.rna.tf32.f32 %0, %1;" : "=r"(u) : "f"(x));
    return __uint_as_float(u);
}
#define CP16(dst, src) \
    asm volatile("cp.async.cg.shared.global [%0], [%1], 16;" :: "r"(dst), "l"(src))
#define CP_COMMIT() asm volatile("cp.async.commit_group;" ::: "memory")
#define CP_WAIT(n)  asm volatile("cp.async.wait_group %0;" :: "n"(n) : "memory")
#define LDSM4(r0, r1, r2, r3, addr) \
    asm volatile("ldmatrix.sync.aligned.m8n8.x4.shared.b16 {%0,%1,%2,%3}, [%4];" \
                 : "=r"(r0), "=r"(r1), "=r"(r2), "=r"(r3) : "r"(addr))
__device__ __forceinline__ uint32_t s2u(const void* p) {
    uint32_t a;
    asm("{ .reg .u64 t; cvta.to.shared.u64 t, %1; cvt.u32.u64 %0, t; }" : "=r"(a) : "l"(p));
    return a;
}
__device__ __forceinline__ void mma_tf32(float* c, const uint32_t* a, const uint32_t* b) {
    asm volatile(
        "mma.sync.aligned.m16n8k8.row.col.f32.tf32.tf32.f32 "
        "{%0,%1,%2,%3}, {%4,%5,%6,%7}, {%8,%9}, {%0,%1,%2,%3};"
        : "+f"(c[0]), "+f"(c[1]), "+f"(c[2]), "+f"(c[3])
        : "r"(a[0]), "r"(a[1]), "r"(a[2]), "r"(a[3]), "r"(b[0]), "r"(b[1]));
}
static __device__ __forceinline__ float gelu_tanh(float v) {
    float t = tanhf(0.7978845608028654f * (v + 0.044715f * v * v * v));
    return 0.5f * v * (1.f + t);
}

// ---------------- tf32 mma GEMM: C[M,N]=A[M,K]@B[N,K]^T ----------------------
// 128x128 tile, K-chunk 32, 3-stage cp.async ring (1 barrier/chunk), ldmatrix.
// EPI: 0=bias+clip+L1norm64  1=bias+res  2=bias+gelu(round)  3=plain
//      4=fused NNMF-B in-place on hT: hT=l1norm64(clip(hT*acc))^T; res=aux=hT
//      5=fused NNMF-A: local mixes on t1 fragments; bias=lw, res=xe, aux=u1T
//      6=fused NNMF-A last iter: only r=l1norm(clip(t1@lw)); C=r
#define SMP 36
#define STG (128*SMP)
#define MM_SMEM (6*STG*4)     // 110592 B: 2 ops x 3 stages

template <int EPI>
__global__ __launch_bounds__(256, 2) void mma_gemm(
    const float* __restrict__ A, const float* __restrict__ B,
    const float* __restrict__ bias, const float* __restrict__ res,
    float* __restrict__ C, float* __restrict__ aux, int K, int N,
    long long sB, long long sC)
{
    extern __shared__ float sm[];
    const int tid = threadIdx.x, wid = tid >> 5, lane = tid & 31;
    const int grp = lane >> 2, qid = lane & 3;
    const int n0 = blockIdx.x * 128;
    const size_t m0 = (size_t)blockIdx.y * 128;
    B += (size_t)blockIdx.z * sB;
    C += (size_t)blockIdx.z * sC;
    if (EPI == 1 || EPI == 4 || EPI == 5) res += (size_t)blockIdx.z * sC;
    if (EPI == 4 || EPI == 5) aux += (size_t)blockIdx.z * sC;
    const int wm = (wid & 1) * 64, wn = (wid >> 1) * 32;
    const uint32_t sAu = s2u(sm);

    const int t8 = lane >> 3, r8 = lane & 7;
    const int rowA = wm + (t8 & 1) * 8 + r8;
    const int colA = (t8 >> 1) * 4;
    const int rowB = wn + (t8 >> 1) * 8 + r8;
    const int colB = (t8 & 1) * 4;

    auto load_chunk = [&](int st, int kt) {
        uint32_t base = sAu + (uint32_t)(st * 2 * STG) * 4;
#pragma unroll
        for (int i = 0; i < 4; i++) {
            int id = tid + 256 * i;
            int row = id >> 3, kq = (id & 7) * 4;
            CP16(base + (uint32_t)(row * SMP + kq) * 4, &A[(m0 + row) * K + kt + kq]);
        }
        base += STG * 4;
#pragma unroll
        for (int i = 0; i < 4; i++) {
            int id = tid + 256 * i;
            int row = id >> 3, kq = (id & 7) * 4;
            CP16(base + (uint32_t)(row * SMP + kq) * 4, &B[(size_t)(n0 + row) * K + kt + kq]);
        }
        CP_COMMIT();
    };

    float cfr[4][4][4];
#pragma unroll
    for (int mt = 0; mt < 4; mt++)
#pragma unroll
        for (int nt = 0; nt < 4; nt++)
#pragma unroll
            for (int i = 0; i < 4; i++) cfr[mt][nt][i] = 0.f;

    const int nch = K >> 5;
    load_chunk(0, 0);
    if (nch > 1) load_chunk(1, 32);

    for (int c = 0; c < nch; c++) {
        if (c + 1 < nch) CP_WAIT(1);
        else             CP_WAIT(0);
        __syncthreads();
        if (c + 2 < nch) load_chunk((c + 2) % 3, (c + 2) * 32);
        const uint32_t sAs = sAu + (uint32_t)((c % 3) * 2 * STG) * 4;
        const uint32_t sBs = sAs + STG * 4;
#pragma unroll
        for (int kk = 0; kk < 32; kk += 8) {
            uint32_t af[4][4], bf[2][4];
#pragma unroll
            for (int mt = 0; mt < 4; mt++)
                LDSM4(af[mt][0], af[mt][1], af[mt][2], af[mt][3],
                      sAs + (uint32_t)((rowA + mt * 16) * SMP + kk + colA) * 4);
#pragma unroll
            for (int ntp = 0; ntp < 2; ntp++)
                LDSM4(bf[ntp][0], bf[ntp][1], bf[ntp][2], bf[ntp][3],
                      sBs + (uint32_t)((rowB + ntp * 16) * SMP + kk + colB) * 4);
#pragma unroll
            for (int mt = 0; mt < 4; mt++)
#pragma unroll
                for (int nt = 0; nt < 4; nt++)
                    mma_tf32(cfr[mt][nt], af[mt], &bf[nt >> 1][(nt & 1) * 2]);
        }
    }
    __syncthreads();   // mainloop smem dead; epilogues may reuse it

    if (EPI == 5 || EPI == 6) {
        // ---- fused NNMF-A epilogue ----
        float* t1s = sm;             // [128][132]
        float* lwT = sm + 16896;     // [64][68] : lwT[f][g] = lw[g][f]
        float* lwS = sm + 21248;     // [64][68] : lwS[g][f] = lw[g][f]
        const uint32_t sT = sAu, sL1 = s2u(lwT), sL2 = s2u(lwS);
#pragma unroll
        for (int q = 0; q < 16; q++) {
            int idx = q * 256 + tid;
            int g = idx >> 6, f = idx & 63;
            float v = rtf(bias[idx]);
            lwT[f * 68 + g] = v;
            lwS[g * 68 + f] = v;
        }
#pragma unroll
        for (int mt = 0; mt < 4; mt++) {
            const int row = wm + mt * 16 + grp;
#pragma unroll
            for (int nt = 0; nt < 4; nt++) {
                const int col = wn + nt * 8 + qid * 2;
                t1s[row * 132 + col]           = rtf(cfr[mt][nt][0]);
                t1s[row * 132 + col + 1]       = rtf(cfr[mt][nt][1]);
                t1s[(row + 8) * 132 + col]     = rtf(cfr[mt][nt][2]);
                t1s[(row + 8) * 132 + col + 1] = rtf(cfr[mt][nt][3]);
            }
        }
        __syncthreads();

        const int wm16 = wid * 16;
        const uint32_t aB0 = sT + (uint32_t)((wm16 + (t8 & 1) * 8 + r8) * 132 + (t8 >> 1) * 4) * 4;
        const int bRow2 = (t8 >> 1) * 8 + r8, bCol2 = (t8 & 1) * 4;

#pragma unroll
        for (int hp = 0; hp < 2; hp++) {
            const uint32_t aB = aB0 + (uint32_t)(hp * 64) * 4;
            float rc[8][4];
#pragma unroll
            for (int nt = 0; nt < 8; nt++)
#pragma unroll
                for (int j = 0; j < 4; j++) rc[nt][j] = 0.f;
#pragma unroll
            for (int kk = 0; kk < 64; kk += 8) {
                uint32_t af[4], bf[4][4];
                LDSM4(af[0], af[1], af[2], af[3], aB + (uint32_t)kk * 4);
#pragma unroll
                for (int n2 = 0; n2 < 4; n2++)
                    LDSM4(bf[n2][0], bf[n2][1], bf[n2][2], bf[n2][3],
                          sL1 + (uint32_t)((n2 * 16 + bRow2) * 68 + kk + bCol2) * 4);
#pragma unroll
                for (int nt = 0; nt < 8; nt++)
                    mma_tf32(rc[nt], af, &bf[nt >> 1][(nt & 1) * 2]);
            }
            float s0 = 0.f, s1 = 0.f;
#pragma unroll
            for (int nt = 0; nt < 8; nt++) {
#pragma unroll
                for (int j = 0; j < 4; j++) rc[nt][j] = fmaxf(rc[nt][j], MIN_POS);
                s0 += rc[nt][0] + rc[nt][1];
                s1 += rc[nt][2] + rc[nt][3];
            }
            s0 += __shfl_xor_sync(0xffffffffu, s0, 1);
            s0 += __shfl_xor_sync(0xffffffffu, s0, 2);
            s1 += __shfl_xor_sync(0xffffffffu, s1, 1);
            s1 += __shfl_xor_sync(0xffffffffu, s1, 2);

            const size_t ra = (m0 + wm16 + grp) * (size_t)N + n0 + hp * 64;
            const size_t rb = ra + 8 * (size_t)N;

            if (EPI == 6) {
                const float inv0 = 1.f / s0, inv1 = 1.f / s1;
#pragma unroll
                for (int nt = 0; nt < 8; nt++) {
                    const int f = nt * 8 + qid * 2;
                    float2 rv0; rv0.x = rtf(rc[nt][0] * inv0); rv0.y = rtf(rc[nt][1] * inv0);
                    float2 rv1; rv1.x = rtf(rc[nt][2] * inv1); rv1.y = rtf(rc[nt][3] * inv1);
                    *(float2*)&C[ra + f] = rv0;
                    *(float2*)&C[rb + f] = rv1;
                }
                continue;
            }

            // xr = xe*s/rc -> t1s (warp-private rows)
#pragma unroll
            for (int nt = 0; nt < 8; nt++) {
                const int f = nt * 8 + qid * 2;
                float2 x0 = *(const float2*)&res[ra + f];
                float2 x1 = *(const float2*)&res[rb + f];
                t1s[(wm16 + grp) * 132 + hp * 64 + f]         = rtf(x0.x * s0 / rc[nt][0]);
                t1s[(wm16 + grp) * 132 + hp * 64 + f + 1]     = rtf(x0.y * s0 / rc[nt][1]);
                t1s[(wm16 + grp + 8) * 132 + hp * 64 + f]     = rtf(x1.x * s1 / rc[nt][2]);
                t1s[(wm16 + grp + 8) * 132 + hp * 64 + f + 1] = rtf(x1.y * s1 / rc[nt][3]);
            }
            __syncwarp();

            float uu[8][4];
#pragma unroll
            for (int nt = 0; nt < 8; nt++)
#pragma unroll
                for (int j = 0; j < 4; j++) uu[nt][j] = 0.f;
#pragma unroll
            for (int kk = 0; kk < 64; kk += 8) {
                uint32_t af[4], bf[4][4];
                LDSM4(af[0], af[1], af[2], af[3], aB + (uint32_t)kk * 4);
#pragma unroll
                for (int n2 = 0; n2 < 4; n2++)
                    LDSM4(bf[n2][0], bf[n2][1], bf[n2][2], bf[n2][3],
                          sL2 + (uint32_t)((n2 * 16 + bRow2) * 68 + kk + bCol2) * 4);
#pragma unroll
                for (int nt = 0; nt < 8; nt++)
                    mma_tf32(uu[nt], af, &bf[nt >> 1][(nt & 1) * 2]);
            }
            {
                const size_t eb = (size_t)(n0 + hp * 64) * 256 + m0;
                const int i = wm16 + grp;
#pragma unroll
                for (int nt = 0; nt < 8; nt++) {
                    const int g = nt * 8 + qid * 2;
                    aux[eb + (size_t)g * 256 + i]           = rtf(uu[nt][0]);
                    aux[eb + (size_t)(g + 1) * 256 + i]     = rtf(uu[nt][1]);
                    aux[eb + (size_t)g * 256 + i + 8]       = rtf(uu[nt][2]);
                    aux[eb + (size_t)(g + 1) * 256 + i + 8] = rtf(uu[nt][3]);
                }
            }
        }
        return;
    }

    if (EPI == 4) {
        // ---- fused NNMF-B, in place on hT ----
        float* Ts   = sm;           // [128][132]: hT_in staging, then hT_out
        float* psum = sm + 16896;   // [128][5]
        // stage hT_in tile [e_local][o_local] (coalesced; same region we overwrite)
#pragma unroll
        for (int q = 0; q < 16; q++) {
            int idx = q * 1024 + tid * 4;
            int col = idx >> 7, row = idx & 127;
            float4 v = *(const float4*)&res[(size_t)(n0 + col) * 256 + m0 + row];
            *(float4*)&Ts[col * 132 + row] = v;
        }
        __syncthreads();
        // clip(h_in * acc)  (conflict-free Ts reads: bank = 8*qid + grp)
#pragma unroll
        for (int mt = 0; mt < 4; mt++) {
            const int row = wm + mt * 16 + grp;
#pragma unroll
            for (int nt = 0; nt < 4; nt++) {
                const int col = wn + nt * 8 + qid * 2;
                float h00 = Ts[col * 132 + row],     h01 = Ts[(col + 1) * 132 + row];
                float h10 = Ts[col * 132 + row + 8], h11 = Ts[(col + 1) * 132 + row + 8];
                cfr[mt][nt][0] = fmaxf(cfr[mt][nt][0] * h00, MIN_POS);
                cfr[mt][nt][1] = fmaxf(cfr[mt][nt][1] * h01, MIN_POS);
                cfr[mt][nt][2] = fmaxf(cfr[mt][nt][2] * h10, MIN_POS);
                cfr[mt][nt][3] = fmaxf(cfr[mt][nt][3] * h11, MIN_POS);
            }
        }
        // row L1 partial sums across the 4 warps sharing each row
#pragma unroll
        for (int mt = 0; mt < 4; mt++) {
#pragma unroll
            for (int rs = 0; rs < 2; rs++) {
                float s = 0.f;
#pragma unroll
                for (int nt = 0; nt < 4; nt++) s += cfr[mt][nt][rs*2] + cfr[mt][nt][rs*2+1];
                s += __shfl_xor_sync(0xffffffffu, s, 1);
                s += __shfl_xor_sync(0xffffffffu, s, 2);
                int row = wm + mt * 16 + grp + rs * 8;
                if (qid == 0) psum[row * 5 + (wid >> 1)] = s;
            }
        }
        __syncthreads();   // psum ready; all Ts_in reads complete
        const int gc = (wid >> 2) * 2;
#pragma unroll
        for (int mt = 0; mt < 4; mt++) {
            float inv0 = 1.f / (psum[(wm + mt*16 + grp) * 5 + gc]     + psum[(wm + mt*16 + grp) * 5 + gc + 1]);
            float inv1 = 1.f / (psum[(wm + mt*16 + grp + 8) * 5 + gc] + psum[(wm + mt*16 + grp + 8) * 5 + gc + 1]);
            const int rr = wm + mt * 16 + grp;
#pragma unroll
            for (int nt = 0; nt < 4; nt++) {
                const int col = wn + nt * 8 + qid * 2;
                Ts[col * 132 + rr]           = rtf(cfr[mt][nt][0] * inv0);
                Ts[(col + 1) * 132 + rr]     = rtf(cfr[mt][nt][1] * inv0);
                Ts[col * 132 + rr + 8]       = rtf(cfr[mt][nt][2] * inv1);
                Ts[(col + 1) * 132 + rr + 8] = rtf(cfr[mt][nt][3] * inv1);
            }
        }
        __syncthreads();
        // coalesced store back to hT
#pragma unroll
        for (int q = 0; q < 16; q++) {
            int idx = q * 1024 + tid * 4;
            int col = idx >> 7, row = idx & 127;
            float4 v = *(const float4*)&Ts[col * 132 + row];
            *(float4*)&aux[(size_t)(n0 + col) * 256 + m0 + row] = v;
        }
        return;
    }

    if (EPI == 0) {
        float* psum = sm + 16896;   // [128][5]
#pragma unroll
        for (int mt = 0; mt < 4; mt++) {
#pragma unroll
            for (int nt = 0; nt < 4; nt++) {
                const int col = n0 + wn + nt * 8 + qid * 2;
                float2 bv = *(const float2*)&bias[col];
                cfr[mt][nt][0] = fmaxf(cfr[mt][nt][0] + bv.x, MIN_POS);
                cfr[mt][nt][1] = fmaxf(cfr[mt][nt][1] + bv.y, MIN_POS);
                cfr[mt][nt][2] = fmaxf(cfr[mt][nt][2] + bv.x, MIN_POS);
                cfr[mt][nt][3] = fmaxf(cfr[mt][nt][3] + bv.y, MIN_POS);
            }
        }
#pragma unroll
        for (int mt = 0; mt < 4; mt++) {
#pragma unroll
            for (int rs = 0; rs < 2; rs++) {
                float s = 0.f;
#pragma unroll
                for (int nt = 0; nt < 4; nt++) s += cfr[mt][nt][rs*2] + cfr[mt][nt][rs*2+1];
                s += __shfl_xor_sync(0xffffffffu, s, 1);
                s += __shfl_xor_sync(0xffffffffu, s, 2);
                int row = wm + mt * 16 + grp + rs * 8;
                if (qid == 0) psum[row * 5 + (wid >> 1)] = s;
            }
        }
        __syncthreads();
        const int gc = (wid >> 2) * 2;
#pragma unroll
        for (int mt = 0; mt < 4; mt++) {
            const size_t r0 = m0 + wm + mt * 16 + grp;
            float inv0 = 1.f / (psum[(wm + mt*16 + grp) * 5 + gc]     + psum[(wm + mt*16 + grp) * 5 + gc + 1]);
            float inv1 = 1.f / (psum[(wm + mt*16 + grp + 8) * 5 + gc] + psum[(wm + mt*16 + grp + 8) * 5 + gc + 1]);
#pragma unroll
            for (int nt = 0; nt < 4; nt++) {
                const int col = wn + nt * 8 + qid * 2;
                float2 o0; o0.x = cfr[mt][nt][0] * inv0; o0.y = cfr[mt][nt][1] * inv0;
                float2 o1; o1.x = cfr[mt][nt][2] * inv1; o1.y = cfr[mt][nt][3] * inv1;
                *(float2*)&C[r0 * N + n0 + col] = o0;
                *(float2*)&C[(r0 + 8) * N + n0 + col] = o1;
            }
        }
        return;
    }

#pragma unroll
    for (int mt = 0; mt < 4; mt++) {
        const size_t r0 = m0 + wm + mt * 16 + grp;
#pragma unroll
        for (int nt = 0; nt < 4; nt++) {
            const int col = n0 + wn + nt * 8 + qid * 2;
            float bx = 0.f, by = 0.f;
            if (EPI != 3) {
                float2 bv = *(const float2*)&bias[col];
                bx = bv.x; by = bv.y;
            }
            float v0 = cfr[mt][nt][0] + bx, v1 = cfr[mt][nt][1] + by;
            float v2 = cfr[mt][nt][2] + bx, v3 = cfr[mt][nt][3] + by;
            if (EPI == 1) {
                float2 ra = *(const float2*)&res[r0 * N + col];
                float2 rb = *(const float2*)&res[(r0 + 8) * N + col];
                v0 += ra.x; v1 += ra.y; v2 += rb.x; v3 += rb.y;
            } else if (EPI == 2) {
                v0 = rtf(gelu_tanh(v0)); v1 = rtf(gelu_tanh(v1));
                v2 = rtf(gelu_tanh(v2)); v3 = rtf(gelu_tanh(v3));
            }
            float2 o0; o0.x = v0; o0.y = v1;
            float2 o1; o1.x = v2; o1.y = v3;
            *(float2*)&C[r0 * N + col] = o0;
            *(float2*)&C[(r0 + 8) * N + col] = o1;
        }
    }
}

// ---------------- fused prologue round (all 5 weight tensors) ----------------
__global__ __launch_bounds__(256) void prep_kernel(
    const float* __restrict__ ew, const float* __restrict__ ow,
    const float* __restrict__ w1, const float* __restrict__ w2,
    const float* __restrict__ gw,
    float* __restrict__ ewR, float* __restrict__ owR,
    float* __restrict__ w1R, float* __restrict__ w2R,
    float* __restrict__ gwR)
{
    int i = blockIdx.x * 256 + threadIdx.x;   // float4 index, total 671744
    const float* in; float* out; int off;
    if (i < 65536)        { in = ew; out = ewR; off = i; }
    else if (i < 131072)  { in = ow; out = owR; off = i - 65536; }
    else if (i < 393216)  { in = w1; out = w1R; off = i - 131072; }
    else if (i < 655360)  { in = w2; out = w2R; off = i - 393216; }
    else                  { in = gw; out = gwR; off = i - 655360; }
    float4 v = *(const float4*)&in[(size_t)off * 4];
    v.x = rtf(v.x); v.y = rtf(v.y); v.z = rtf(v.z); v.w = rtf(v.w);
    *(float4*)&out[(size_t)off * 4] = v;
}

// ---------------- batched transpose [R,C]->[C,R], tf32-rounded ---------------
__global__ void transpose_kernel(
    const float* __restrict__ in, float* __restrict__ out, int R, int C)
{
    __shared__ float t[32][33];
    in  += (size_t)blockIdx.z * R * C;
    out += (size_t)blockIdx.z * R * C;
    int r0 = blockIdx.y * 32, c0 = blockIdx.x * 32;
    int lx = threadIdx.x, ly = threadIdx.y;
#pragma unroll
    for (int i = 0; i < 32; i += 8)
        t[ly + i][lx] = rtf(in[(size_t)(r0 + ly + i) * C + c0 + lx]);
    __syncthreads();
#pragma unroll
    for (int i = 0; i < 32; i += 8)
        out[(size_t)(c0 + ly + i) * R + r0 + lx] = t[lx][ly + i];
}

// ---------------- LayerNorm (tf32-rounded output) -----------------------------
__global__ __launch_bounds__(256) void ln_kernel(
    const float* __restrict__ x, const float* __restrict__ g,
    const float* __restrict__ b, float* __restrict__ out)
{
    int row  = blockIdx.x * 8 + (threadIdx.x >> 5);
    int lane = threadIdx.x & 31;
    const float* xr = x + (size_t)row * 512;
    float4 v[4];
    float s = 0.f, sq = 0.f;
#pragma unroll
    for (int w = 0; w < 4; w++) {
        v[w] = *(const float4*)&xr[w * 128 + lane * 4];
        s  += v[w].x + v[w].y + v[w].z + v[w].w;
        sq += v[w].x*v[w].x + v[w].y*v[w].y + v[w].z*v[w].z + v[w].w*v[w].w;
    }
#pragma unroll
    for (int off = 16; off > 0; off >>= 1) {
        s  += __shfl_xor_sync(0xffffffffu, s,  off);
        sq += __shfl_xor_sync(0xffffffffu, sq, off);
    }
    float mu = s * (1.f / 512.f);
    float var = sq * (1.f / 512.f) - mu * mu;
    float rstd = rsqrtf(var + 1e-5f);
    float* orow = out + (size_t)row * 512;
#pragma unroll
    for (int w = 0; w < 4; w++) {
        int c = w * 128 + lane * 4;
        float4 gv = *(const float4*)&g[c];
        float4 bv = *(const float4*)&b[c];
        float4 o;
        o.x = rtf((v[w].x - mu) * rstd * gv.x + bv.x);
        o.y = rtf((v[w].y - mu) * rstd * gv.y + bv.y);
        o.z = rtf((v[w].z - mu) * rstd * gv.z + bv.z);
        o.w = rtf((v[w].w - mu) * rstd * gv.w + bv.w);
        *(float4*)&orow[c] = o;
    }
}

// ---------------- host launcher -----------------------------------------------
extern "C" void kernel_launch(void* const* d_in, const int* in_sizes, int n_in,
                              void* d_out, int out_size)
{
    const float* x    = (const float*)d_in[0];
    const float* ew   = (const float*)d_in[1];
    const float* eb   = (const float*)d_in[2];
    const float* lw   = (const float*)d_in[3];
    const float* gw   = (const float*)d_in[4];
    const float* ow   = (const float*)d_in[5];
    const float* ob   = (const float*)d_in[6];
    const float* ln1g = (const float*)d_in[7];
    const float* ln1b = (const float*)d_in[8];
    const float* ln2g = (const float*)d_in[9];
    const float* ln2b = (const float*)d_in[10];
    const float* w1   = (const float*)d_in[11];
    const float* b1   = (const float*)d_in[12];
    const float* w2   = (const float*)d_in[13];
    const float* b2   = (const float*)d_in[14];
    const float* h0   = (const float*)d_in[15];
    float* out = (float*)d_out;

    float *xn, *xe, *hT, *u1T, *r, *xres, *mlp, *gwT, *gwR;
    float *ewR, *owR, *w1R, *w2R;
    cudaGetSymbolAddress((void**)&xn,   g_xn);
    cudaGetSymbolAddress((void**)&xe,   g_xe);
    cudaGetSymbolAddress((void**)&hT,   g_hT);
    cudaGetSymbolAddress((void**)&u1T,  g_u1T);
    cudaGetSymbolAddress((void**)&r,    g_r);
    cudaGetSymbolAddress((void**)&xres, g_xres);
    cudaGetSymbolAddress((void**)&mlp,  g_mlp);
    cudaGetSymbolAddress((void**)&gwT,  g_gwT);
    cudaGetSymbolAddress((void**)&gwR,  g_gwR);
    cudaGetSymbolAddress((void**)&ewR,  g_ewR);
    cudaGetSymbolAddress((void**)&owR,  g_owR);
    cudaGetSymbolAddress((void**)&w1R,  g_w1R);
    cudaGetSymbolAddress((void**)&w2R,  g_w2R);

    cudaFuncSetAttribute(mma_gemm<0>, cudaFuncAttributeMaxDynamicSharedMemorySize, MM_SMEM);
    cudaFuncSetAttribute(mma_gemm<1>, cudaFuncAttributeMaxDynamicSharedMemorySize, MM_SMEM);
    cudaFuncSetAttribute(mma_gemm<2>, cudaFuncAttributeMaxDynamicSharedMemorySize, MM_SMEM);
    cudaFuncSetAttribute(mma_gemm<3>, cudaFuncAttributeMaxDynamicSharedMemorySize, MM_SMEM);
    cudaFuncSetAttribute(mma_gemm<4>, cudaFuncAttributeMaxDynamicSharedMemorySize, MM_SMEM);
    cudaFuncSetAttribute(mma_gemm<5>, cudaFuncAttributeMaxDynamicSharedMemorySize, MM_SMEM);
    cudaFuncSetAttribute(mma_gemm<6>, cudaFuncAttributeMaxDynamicSharedMemorySize, MM_SMEM);

    const long long SB = 512LL * 256;   // == 256*512; shared stride for hT/u1T/r/t-layouts
    const long long SC = 256LL * 512;

    prep_kernel<<<(671744 + 255) / 256, 256>>>(ew, ow, w1, w2, gw,
                                               ewR, owR, w1R, w2R, gwR);
    transpose_kernel<<<dim3(8, 8, 1), dim3(32, 8)>>>(gw, gwT, 256, 256);
    transpose_kernel<<<dim3(16, 8, 128), dim3(32, 8)>>>(h0, hT, 256, 512);
    ln_kernel<<<BSROWS / 8, 256>>>(x, ln1g, ln1b, xn);
    mma_gemm<0><<<dim3(4, 256, 1), 256, MM_SMEM>>>(xn, ewR, eb, nullptr, xe, nullptr, 512, 512, 0, 0);

    for (int it = 0; it < 10; it++) {
        if (it < 9) {
            mma_gemm<5><<<dim3(4, 2, 128), 256, MM_SMEM>>>(gwT, hT, lw, xe, r, u1T, 256, 512, SB, SC);
            // in-place NNMF-B: reads hT tile, writes same hT tile (per-block bijective)
            mma_gemm<4><<<dim3(4, 2, 128), 256, MM_SMEM>>>(gwR, u1T, nullptr, hT, hT, hT, 256, 512, SB, SC);
        } else {
            mma_gemm<6><<<dim3(4, 2, 128), 256, MM_SMEM>>>(gwT, hT, lw, xe, r, u1T, 256, 512, SB, SC);
        }
    }

    mma_gemm<1><<<dim3(4, 256, 1), 256, MM_SMEM>>>(r, owR, ob, x, xres, nullptr, 512, 512, 0, 0);
    ln_kernel<<<BSROWS / 8, 256>>>(xres, ln2g, ln2b, xn);
    mma_gemm<2><<<dim3(16, 256, 1), 256, MM_SMEM>>>(xn, w1R, b1, nullptr, mlp, nullptr, 512, 2048, 0, 0);
    mma_gemm<1><<<dim3(4, 256, 1), 256, MM_SMEM>>>(mlp, w2R, b2, xres, out, nullptr, 2048, 512, 0, 0);
}

// round 12
// speedup vs baseline: 3.2306x; 1.0068x over previous
#include <cuda_runtime.h>
#include <cstdint>

#define BSZ   128
#define SEQ   256
#define FDIM  512
#define EDIM  512
#define HEADS 8
#define BSROWS (BSZ*SEQ)
#define MLPD  2048
#define MIN_POS 1e-6f

__device__ float g_xn  [(size_t)BSROWS*FDIM];
__device__ float g_xe  [(size_t)BSROWS*EDIM];
__device__ float g_hT  [(size_t)BSROWS*EDIM];   // hT [b,e,o] (tf32-rounded state)
__device__ float g_u1T [(size_t)BSROWS*EDIM];   // u1T[b,e,i] (tf32-rounded)
__device__ float g_r   [(size_t)BSROWS*EDIM];
__device__ float g_xres[(size_t)BSROWS*FDIM];
__device__ float g_mlp [(size_t)BSROWS*MLPD];
__device__ float g_gwT [(size_t)SEQ*SEQ];
__device__ float g_gwR [(size_t)SEQ*SEQ];
__device__ float g_ewR [(size_t)EDIM*FDIM];
__device__ float g_owR [(size_t)FDIM*EDIM];
__device__ float g_w1R [(size_t)MLPD*FDIM];
__device__ float g_w2R [(size_t)FDIM*MLPD];

// ---------------- helpers -----------------------------------------------------
__device__ __forceinline__ float rtf(float x) {   // round-to-nearest tf32
    uint32_t u;
    asm("cvt.rna.tf32.f32 %0, %1;" : "=r"(u) : "f"(x));
    return __uint_as_float(u);
}
#define CP16(dst, src) \
    asm volatile("cp.async.cg.shared.global [%0], [%1], 16;" :: "r"(dst), "l"(src))
#define CP_COMMIT() asm volatile("cp.async.commit_group;" ::: "memory")
#define CP_WAIT(n)  asm volatile("cp.async.wait_group %0;" :: "n"(n) : "memory")
#define L2PF(p) asm volatile("prefetch.global.L2 [%0];" :: "l"(p))
#define LDSM4(r0, r1, r2, r3, addr) \
    asm volatile("ldmatrix.sync.aligned.m8n8.x4.shared.b16 {%0,%1,%2,%3}, [%4];" \
                 : "=r"(r0), "=r"(r1), "=r"(r2), "=r"(r3) : "r"(addr))
__device__ __forceinline__ uint32_t s2u(const void* p) {
    uint32_t a;
    asm("{ .reg .u64 t; cvta.to.shared.u64 t, %1; cvt.u32.u64 %0, t; }" : "=r"(a) : "l"(p));
    return a;
}
__device__ __forceinline__ void mma_tf32(float* c, const uint32_t* a, const uint32_t* b) {
    asm volatile(
        "mma.sync.aligned.m16n8k8.row.col.f32.tf32.tf32.f32 "
        "{%0,%1,%2,%3}, {%4,%5,%6,%7}, {%8,%9}, {%0,%1,%2,%3};"
        : "+f"(c[0]), "+f"(c[1]), "+f"(c[2]), "+f"(c[3])
        : "r"(a[0]), "r"(a[1]), "r"(a[2]), "r"(a[3]), "r"(b[0]), "r"(b[1]));
}
static __device__ __forceinline__ float gelu_tanh(float v) {
    float t = tanhf(0.7978845608028654f * (v + 0.044715f * v * v * v));
    return 0.5f * v * (1.f + t);
}

// ---------------- tf32 mma GEMM: C[M,N]=A[M,K]@B[N,K]^T ----------------------
// 128x128 tile, K-chunk 32, 3-stage cp.async ring (1 barrier/chunk), ldmatrix.
// EPI: 0=bias+clip+L1norm64  1=bias+res  2=bias+gelu(round)  3=plain
//      4=fused NNMF-B in-place on hT: hT=l1norm64(clip(hT*acc))^T; res=aux=hT
//      5=fused NNMF-A: local mixes on t1 fragments; bias=lw, res=xe, aux=u1T
//      6=fused NNMF-A last iter: only r=l1norm(clip(t1@lw)); C=r
#define SMP 36
#define STG (128*SMP)
#define MM_SMEM (6*STG*4)     // 110592 B: 2 ops x 3 stages

template <int EPI>
__global__ __launch_bounds__(256, 2) void mma_gemm(
    const float* __restrict__ A, const float* __restrict__ B,
    const float* __restrict__ bias, const float* __restrict__ res,
    float* __restrict__ C, float* __restrict__ aux, int K, int N,
    long long sB, long long sC)
{
    extern __shared__ float sm[];
    const int tid = threadIdx.x, wid = tid >> 5, lane = tid & 31;
    const int grp = lane >> 2, qid = lane & 3;
    const int n0 = blockIdx.x * 128;
    const size_t m0 = (size_t)blockIdx.y * 128;
    B += (size_t)blockIdx.z * sB;
    C += (size_t)blockIdx.z * sC;
    if (EPI == 1 || EPI == 4 || EPI == 5) res += (size_t)blockIdx.z * sC;
    if (EPI == 4 || EPI == 5) aux += (size_t)blockIdx.z * sC;
    const int wm = (wid & 1) * 64, wn = (wid >> 1) * 32;
    const uint32_t sAu = s2u(sm);

    const int t8 = lane >> 3, r8 = lane & 7;
    const int rowA = wm + (t8 & 1) * 8 + r8;
    const int colA = (t8 >> 1) * 4;
    const int rowB = wn + (t8 >> 1) * 8 + r8;
    const int colB = (t8 & 1) * 4;

    auto load_chunk = [&](int st, int kt) {
        uint32_t base = sAu + (uint32_t)(st * 2 * STG) * 4;
#pragma unroll
        for (int i = 0; i < 4; i++) {
            int id = tid + 256 * i;
            int row = id >> 3, kq = (id & 7) * 4;
            CP16(base + (uint32_t)(row * SMP + kq) * 4, &A[(m0 + row) * K + kt + kq]);
        }
        base += STG * 4;
#pragma unroll
        for (int i = 0; i < 4; i++) {
            int id = tid + 256 * i;
            int row = id >> 3, kq = (id & 7) * 4;
            CP16(base + (uint32_t)(row * SMP + kq) * 4, &B[(size_t)(n0 + row) * K + kt + kq]);
        }
        CP_COMMIT();
    };

    float cfr[4][4][4];
#pragma unroll
    for (int mt = 0; mt < 4; mt++)
#pragma unroll
        for (int nt = 0; nt < 4; nt++)
#pragma unroll
            for (int i = 0; i < 4; i++) cfr[mt][nt][i] = 0.f;

    const int nch = K >> 5;
    load_chunk(0, 0);
    if (nch > 1) load_chunk(1, 32);

    // L2 prefetch of epilogue inputs (consumed after the mainloop)
    if (EPI == 5) {
#pragma unroll
        for (int q = 0; q < 2; q++) {
            int idx = tid + q * 256;           // 512 lines: 128 rows x 4 lines
            int row = idx >> 2, l = idx & 3;
            L2PF(&res[(m0 + row) * (size_t)N + n0 + l * 32]);
        }
        if (tid < 128) L2PF(&bias[tid * 32]); // lw: 16KB
    } else if (EPI == 4) {
#pragma unroll
        for (int q = 0; q < 2; q++) {
            int idx = tid + q * 256;
            int col = idx >> 2, l = idx & 3;
            L2PF(&res[(size_t)(n0 + col) * 256 + m0 + l * 32]);
        }
    }

    for (int c = 0; c < nch; c++) {
        if (c + 1 < nch) CP_WAIT(1);
        else             CP_WAIT(0);
        __syncthreads();
        if (c + 2 < nch) load_chunk((c + 2) % 3, (c + 2) * 32);
        const uint32_t sAs = sAu + (uint32_t)((c % 3) * 2 * STG) * 4;
        const uint32_t sBs = sAs + STG * 4;
#pragma unroll
        for (int kk = 0; kk < 32; kk += 8) {
            uint32_t af[4][4], bf[2][4];
#pragma unroll
            for (int mt = 0; mt < 4; mt++)
                LDSM4(af[mt][0], af[mt][1], af[mt][2], af[mt][3],
                      sAs + (uint32_t)((rowA + mt * 16) * SMP + kk + colA) * 4);
#pragma unroll
            for (int ntp = 0; ntp < 2; ntp++)
                LDSM4(bf[ntp][0], bf[ntp][1], bf[ntp][2], bf[ntp][3],
                      sBs + (uint32_t)((rowB + ntp * 16) * SMP + kk + colB) * 4);
#pragma unroll
            for (int mt = 0; mt < 4; mt++)
#pragma unroll
                for (int nt = 0; nt < 4; nt++)
                    mma_tf32(cfr[mt][nt], af[mt], &bf[nt >> 1][(nt & 1) * 2]);
        }
    }
    __syncthreads();   // mainloop smem dead; epilogues may reuse it

    if (EPI == 5 || EPI == 6) {
        // ---- fused NNMF-A epilogue ----
        float* t1s = sm;             // [128][132]
        float* lwT = sm + 16896;     // [64][68] : lwT[f][g] = lw[g][f]
        float* lwS = sm + 21248;     // [64][68] : lwS[g][f] = lw[g][f]
        const uint32_t sT = sAu, sL1 = s2u(lwT), sL2 = s2u(lwS);
#pragma unroll
        for (int q = 0; q < 16; q++) {
            int idx = q * 256 + tid;
            int g = idx >> 6, f = idx & 63;
            float v = rtf(bias[idx]);
            lwT[f * 68 + g] = v;
            lwS[g * 68 + f] = v;
        }
#pragma unroll
        for (int mt = 0; mt < 4; mt++) {
            const int row = wm + mt * 16 + grp;
#pragma unroll
            for (int nt = 0; nt < 4; nt++) {
                const int col = wn + nt * 8 + qid * 2;
                t1s[row * 132 + col]           = rtf(cfr[mt][nt][0]);
                t1s[row * 132 + col + 1]       = rtf(cfr[mt][nt][1]);
                t1s[(row + 8) * 132 + col]     = rtf(cfr[mt][nt][2]);
                t1s[(row + 8) * 132 + col + 1] = rtf(cfr[mt][nt][3]);
            }
        }
        __syncthreads();

        const int wm16 = wid * 16;
        const uint32_t aB0 = sT + (uint32_t)((wm16 + (t8 & 1) * 8 + r8) * 132 + (t8 >> 1) * 4) * 4;
        const int bRow2 = (t8 >> 1) * 8 + r8, bCol2 = (t8 & 1) * 4;

#pragma unroll
        for (int hp = 0; hp < 2; hp++) {
            const uint32_t aB = aB0 + (uint32_t)(hp * 64) * 4;
            float rc[8][4];
#pragma unroll
            for (int nt = 0; nt < 8; nt++)
#pragma unroll
                for (int j = 0; j < 4; j++) rc[nt][j] = 0.f;
#pragma unroll
            for (int kk = 0; kk < 64; kk += 8) {
                uint32_t af[4], bf[4][4];
                LDSM4(af[0], af[1], af[2], af[3], aB + (uint32_t)kk * 4);
#pragma unroll
                for (int n2 = 0; n2 < 4; n2++)
                    LDSM4(bf[n2][0], bf[n2][1], bf[n2][2], bf[n2][3],
                          sL1 + (uint32_t)((n2 * 16 + bRow2) * 68 + kk + bCol2) * 4);
#pragma unroll
                for (int nt = 0; nt < 8; nt++)
                    mma_tf32(rc[nt], af, &bf[nt >> 1][(nt & 1) * 2]);
            }
            float s0 = 0.f, s1 = 0.f;
#pragma unroll
            for (int nt = 0; nt < 8; nt++) {
#pragma unroll
                for (int j = 0; j < 4; j++) rc[nt][j] = fmaxf(rc[nt][j], MIN_POS);
                s0 += rc[nt][0] + rc[nt][1];
                s1 += rc[nt][2] + rc[nt][3];
            }
            s0 += __shfl_xor_sync(0xffffffffu, s0, 1);
            s0 += __shfl_xor_sync(0xffffffffu, s0, 2);
            s1 += __shfl_xor_sync(0xffffffffu, s1, 1);
            s1 += __shfl_xor_sync(0xffffffffu, s1, 2);

            const size_t ra = (m0 + wm16 + grp) * (size_t)N + n0 + hp * 64;
            const size_t rb = ra + 8 * (size_t)N;

            if (EPI == 6) {
                const float inv0 = 1.f / s0, inv1 = 1.f / s1;
#pragma unroll
                for (int nt = 0; nt < 8; nt++) {
                    const int f = nt * 8 + qid * 2;
                    float2 rv0; rv0.x = rtf(rc[nt][0] * inv0); rv0.y = rtf(rc[nt][1] * inv0);
                    float2 rv1; rv1.x = rtf(rc[nt][2] * inv1); rv1.y = rtf(rc[nt][3] * inv1);
                    *(float2*)&C[ra + f] = rv0;
                    *(float2*)&C[rb + f] = rv1;
                }
                continue;
            }

            // xr = xe*s/rc -> t1s (warp-private rows)
#pragma unroll
            for (int nt = 0; nt < 8; nt++) {
                const int f = nt * 8 + qid * 2;
                float2 x0 = *(const float2*)&res[ra + f];
                float2 x1 = *(const float2*)&res[rb + f];
                t1s[(wm16 + grp) * 132 + hp * 64 + f]         = rtf(x0.x * s0 / rc[nt][0]);
                t1s[(wm16 + grp) * 132 + hp * 64 + f + 1]     = rtf(x0.y * s0 / rc[nt][1]);
                t1s[(wm16 + grp + 8) * 132 + hp * 64 + f]     = rtf(x1.x * s1 / rc[nt][2]);
                t1s[(wm16 + grp + 8) * 132 + hp * 64 + f + 1] = rtf(x1.y * s1 / rc[nt][3]);
            }
            __syncwarp();

            float uu[8][4];
#pragma unroll
            for (int nt = 0; nt < 8; nt++)
#pragma unroll
                for (int j = 0; j < 4; j++) uu[nt][j] = 0.f;
#pragma unroll
            for (int kk = 0; kk < 64; kk += 8) {
                uint32_t af[4], bf[4][4];
                LDSM4(af[0], af[1], af[2], af[3], aB + (uint32_t)kk * 4);
#pragma unroll
                for (int n2 = 0; n2 < 4; n2++)
                    LDSM4(bf[n2][0], bf[n2][1], bf[n2][2], bf[n2][3],
                          sL2 + (uint32_t)((n2 * 16 + bRow2) * 68 + kk + bCol2) * 4);
#pragma unroll
                for (int nt = 0; nt < 8; nt++)
                    mma_tf32(uu[nt], af, &bf[nt >> 1][(nt & 1) * 2]);
            }
            {
                const size_t eb = (size_t)(n0 + hp * 64) * 256 + m0;
                const int i = wm16 + grp;
#pragma unroll
                for (int nt = 0; nt < 8; nt++) {
                    const int g = nt * 8 + qid * 2;
                    aux[eb + (size_t)g * 256 + i]           = rtf(uu[nt][0]);
                    aux[eb + (size_t)(g + 1) * 256 + i]     = rtf(uu[nt][1]);
                    aux[eb + (size_t)g * 256 + i + 8]       = rtf(uu[nt][2]);
                    aux[eb + (size_t)(g + 1) * 256 + i + 8] = rtf(uu[nt][3]);
                }
            }
        }
        return;
    }

    if (EPI == 4) {
        // ---- fused NNMF-B, in place on hT ----
        float* Ts   = sm;           // [128][132]: hT_in staging, then hT_out
        float* psum = sm + 16896;   // [128][5]
#pragma unroll
        for (int q = 0; q < 16; q++) {
            int idx = q * 1024 + tid * 4;
            int col = idx >> 7, row = idx & 127;
            float4 v = *(const float4*)&res[(size_t)(n0 + col) * 256 + m0 + row];
            *(float4*)&Ts[col * 132 + row] = v;
        }
        __syncthreads();
#pragma unroll
        for (int mt = 0; mt < 4; mt++) {
            const int row = wm + mt * 16 + grp;
#pragma unroll
            for (int nt = 0; nt < 4; nt++) {
                const int col = wn + nt * 8 + qid * 2;
                float h00 = Ts[col * 132 + row],     h01 = Ts[(col + 1) * 132 + row];
                float h10 = Ts[col * 132 + row + 8], h11 = Ts[(col + 1) * 132 + row + 8];
                cfr[mt][nt][0] = fmaxf(cfr[mt][nt][0] * h00, MIN_POS);
                cfr[mt][nt][1] = fmaxf(cfr[mt][nt][1] * h01, MIN_POS);
                cfr[mt][nt][2] = fmaxf(cfr[mt][nt][2] * h10, MIN_POS);
                cfr[mt][nt][3] = fmaxf(cfr[mt][nt][3] * h11, MIN_POS);
            }
        }
#pragma unroll
        for (int mt = 0; mt < 4; mt++) {
#pragma unroll
            for (int rs = 0; rs < 2; rs++) {
                float s = 0.f;
#pragma unroll
                for (int nt = 0; nt < 4; nt++) s += cfr[mt][nt][rs*2] + cfr[mt][nt][rs*2+1];
                s += __shfl_xor_sync(0xffffffffu, s, 1);
                s += __shfl_xor_sync(0xffffffffu, s, 2);
                int row = wm + mt * 16 + grp + rs * 8;
                if (qid == 0) psum[row * 5 + (wid >> 1)] = s;
            }
        }
        __syncthreads();
        const int gc = (wid >> 2) * 2;
#pragma unroll
        for (int mt = 0; mt < 4; mt++) {
            float inv0 = 1.f / (psum[(wm + mt*16 + grp) * 5 + gc]     + psum[(wm + mt*16 + grp) * 5 + gc + 1]);
            float inv1 = 1.f / (psum[(wm + mt*16 + grp + 8) * 5 + gc] + psum[(wm + mt*16 + grp + 8) * 5 + gc + 1]);
            const int rr = wm + mt * 16 + grp;
#pragma unroll
            for (int nt = 0; nt < 4; nt++) {
                const int col = wn + nt * 8 + qid * 2;
                Ts[col * 132 + rr]           = rtf(cfr[mt][nt][0] * inv0);
                Ts[(col + 1) * 132 + rr]     = rtf(cfr[mt][nt][1] * inv0);
                Ts[col * 132 + rr + 8]       = rtf(cfr[mt][nt][2] * inv1);
                Ts[(col + 1) * 132 + rr + 8] = rtf(cfr[mt][nt][3] * inv1);
            }
        }
        __syncthreads();
#pragma unroll
        for (int q = 0; q < 16; q++) {
            int idx = q * 1024 + tid * 4;
            int col = idx >> 7, row = idx & 127;
            float4 v = *(const float4*)&Ts[col * 132 + row];
            *(float4*)&aux[(size_t)(n0 + col) * 256 + m0 + row] = v;
        }
        return;
    }

    if (EPI == 0) {
        float* psum = sm + 16896;   // [128][5]
#pragma unroll
        for (int mt = 0; mt < 4; mt++) {
#pragma unroll
            for (int nt = 0; nt < 4; nt++) {
                const int col = n0 + wn + nt * 8 + qid * 2;
                float2 bv = *(const float2*)&bias[col];
                cfr[mt][nt][0] = fmaxf(cfr[mt][nt][0] + bv.x, MIN_POS);
                cfr[mt][nt][1] = fmaxf(cfr[mt][nt][1] + bv.y, MIN_POS);
                cfr[mt][nt][2] = fmaxf(cfr[mt][nt][2] + bv.x, MIN_POS);
                cfr[mt][nt][3] = fmaxf(cfr[mt][nt][3] + bv.y, MIN_POS);
            }
        }
#pragma unroll
        for (int mt = 0; mt < 4; mt++) {
#pragma unroll
            for (int rs = 0; rs < 2; rs++) {
                float s = 0.f;
#pragma unroll
                for (int nt = 0; nt < 4; nt++) s += cfr[mt][nt][rs*2] + cfr[mt][nt][rs*2+1];
                s += __shfl_xor_sync(0xffffffffu, s, 1);
                s += __shfl_xor_sync(0xffffffffu, s, 2);
                int row = wm + mt * 16 + grp + rs * 8;
                if (qid == 0) psum[row * 5 + (wid >> 1)] = s;
            }
        }
        __syncthreads();
        const int gc = (wid >> 2) * 2;
#pragma unroll
        for (int mt = 0; mt < 4; mt++) {
            const size_t r0 = m0 + wm + mt * 16 + grp;
            float inv0 = 1.f / (psum[(wm + mt*16 + grp) * 5 + gc]     + psum[(wm + mt*16 + grp) * 5 + gc + 1]);
            float inv1 = 1.f / (psum[(wm + mt*16 + grp + 8) * 5 + gc] + psum[(wm + mt*16 + grp + 8) * 5 + gc + 1]);
#pragma unroll
            for (int nt = 0; nt < 4; nt++) {
                const int col = wn + nt * 8 + qid * 2;
                float2 o0; o0.x = cfr[mt][nt][0] * inv0; o0.y = cfr[mt][nt][1] * inv0;
                float2 o1; o1.x = cfr[mt][nt][2] * inv1; o1.y = cfr[mt][nt][3] * inv1;
                *(float2*)&C[r0 * N + n0 + col] = o0;
                *(float2*)&C[(r0 + 8) * N + n0 + col] = o1;
            }
        }
        return;
    }

#pragma unroll
    for (int mt = 0; mt < 4; mt++) {
        const size_t r0 = m0 + wm + mt * 16 + grp;
#pragma unroll
        for (int nt = 0; nt < 4; nt++) {
            const int col = n0 + wn + nt * 8 + qid * 2;
            float bx = 0.f, by = 0.f;
            if (EPI != 3) {
                float2 bv = *(const float2*)&bias[col];
                bx = bv.x; by = bv.y;
            }
            float v0 = cfr[mt][nt][0] + bx, v1 = cfr[mt][nt][1] + by;
            float v2 = cfr[mt][nt][2] + bx, v3 = cfr[mt][nt][3] + by;
            if (EPI == 1) {
                float2 ra = *(const float2*)&res[r0 * N + col];
                float2 rb = *(const float2*)&res[(r0 + 8) * N + col];
                v0 += ra.x; v1 += ra.y; v2 += rb.x; v3 += rb.y;
            } else if (EPI == 2) {
                v0 = rtf(gelu_tanh(v0)); v1 = rtf(gelu_tanh(v1));
                v2 = rtf(gelu_tanh(v2)); v3 = rtf(gelu_tanh(v3));
            }
            float2 o0; o0.x = v0; o0.y = v1;
            float2 o1; o1.x = v2; o1.y = v3;
            *(float2*)&C[r0 * N + col] = o0;
            *(float2*)&C[(r0 + 8) * N + col] = o1;
        }
    }
}

// ---------------- fused prologue: rounds + both transposes in ONE launch -----
// blocks [0, 2624): round 5 weight tensors (671744 float4 total)
// blocks [2624, 2688): gw -> gwT transpose (8x8 tiles)
// blocks [2688, 19072): h0 -> hT batched transpose (16x8 x 128 batches)
__global__ __launch_bounds__(256) void prep_kernel(
    const float* __restrict__ ew, const float* __restrict__ ow,
    const float* __restrict__ w1, const float* __restrict__ w2,
    const float* __restrict__ gw, const float* __restrict__ h0,
    float* __restrict__ ewR, float* __restrict__ owR,
    float* __restrict__ w1R, float* __restrict__ w2R,
    float* __restrict__ gwR, float* __restrict__ gwT,
    float* __restrict__ hT)
{
    __shared__ float t[32][33];
    const int b = blockIdx.x, tid = threadIdx.x;
    if (b < 2624) {
        int i = b * 256 + tid;
        if (i >= 671744) return;
        const float* in; float* out; int off;
        if (i < 65536)        { in = ew; out = ewR; off = i; }
        else if (i < 131072)  { in = ow; out = owR; off = i - 65536; }
        else if (i < 393216)  { in = w1; out = w1R; off = i - 131072; }
        else if (i < 655360)  { in = w2; out = w2R; off = i - 393216; }
        else                  { in = gw; out = gwR; off = i - 655360; }
        float4 v = *(const float4*)&in[(size_t)off * 4];
        v.x = rtf(v.x); v.y = rtf(v.y); v.z = rtf(v.z); v.w = rtf(v.w);
        *(float4*)&out[(size_t)off * 4] = v;
        return;
    }
    const int lx = tid & 31, ly = tid >> 5;   // 32 x 8
    if (b < 2688) {
        int bb = b - 2624;
        int c0 = (bb & 7) * 32, r0 = (bb >> 3) * 32;
#pragma unroll
        for (int i = 0; i < 32; i += 8)
            t[ly + i][lx] = rtf(gw[(size_t)(r0 + ly + i) * 256 + c0 + lx]);
        __syncthreads();
#pragma unroll
        for (int i = 0; i < 32; i += 8)
            gwT[(size_t)(c0 + ly + i) * 256 + r0 + lx] = t[lx][ly + i];
        return;
    }
    {
        int bb = b - 2688;
        int bz = bb >> 7, rem = bb & 127;
        int c0 = (rem & 15) * 32, r0 = (rem >> 4) * 32;
        const float* in = h0 + (size_t)bz * 256 * 512;
        float* out = hT + (size_t)bz * 256 * 512;
#pragma unroll
        for (int i = 0; i < 32; i += 8)
            t[ly + i][lx] = rtf(in[(size_t)(r0 + ly + i) * 512 + c0 + lx]);
        __syncthreads();
#pragma unroll
        for (int i = 0; i < 32; i += 8)
            out[(size_t)(c0 + ly + i) * 256 + r0 + lx] = t[lx][ly + i];
    }
}

// ---------------- LayerNorm (tf32-rounded output) -----------------------------
__global__ __launch_bounds__(256) void ln_kernel(
    const float* __restrict__ x, const float* __restrict__ g,
    const float* __restrict__ b, float* __restrict__ out)
{
    int row  = blockIdx.x * 8 + (threadIdx.x >> 5);
    int lane = threadIdx.x & 31;
    const float* xr = x + (size_t)row * 512;
    float4 v[4];
    float s = 0.f, sq = 0.f;
#pragma unroll
    for (int w = 0; w < 4; w++) {
        v[w] = *(const float4*)&xr[w * 128 + lane * 4];
        s  += v[w].x + v[w].y + v[w].z + v[w].w;
        sq += v[w].x*v[w].x + v[w].y*v[w].y + v[w].z*v[w].z + v[w].w*v[w].w;
    }
#pragma unroll
    for (int off = 16; off > 0; off >>= 1) {
        s  += __shfl_xor_sync(0xffffffffu, s,  off);
        sq += __shfl_xor_sync(0xffffffffu, sq, off);
    }
    float mu = s * (1.f / 512.f);
    float var = sq * (1.f / 512.f) - mu * mu;
    float rstd = rsqrtf(var + 1e-5f);
    float* orow = out + (size_t)row * 512;
#pragma unroll
    for (int w = 0; w < 4; w++) {
        int c = w * 128 + lane * 4;
        float4 gv = *(const float4*)&g[c];
        float4 bv = *(const float4*)&b[c];
        float4 o;
        o.x = rtf((v[w].x - mu) * rstd * gv.x + bv.x);
        o.y = rtf((v[w].y - mu) * rstd * gv.y + bv.y);
        o.z = rtf((v[w].z - mu) * rstd * gv.z + bv.z);
        o.w = rtf((v[w].w - mu) * rstd * gv.w + bv.w);
        *(float4*)&orow[c] = o;
    }
}

// ---------------- host launcher -----------------------------------------------
extern "C" void kernel_launch(void* const* d_in, const int* in_sizes, int n_in,
                              void* d_out, int out_size)
{
    const float* x    = (const float*)d_in[0];
    const float* ew   = (const float*)d_in[1];
    const float* eb   = (const float*)d_in[2];
    const float* lw   = (const float*)d_in[3];
    const float* gw   = (const float*)d_in[4];
    const float* ow   = (const float*)d_in[5];
    const float* ob   = (const float*)d_in[6];
    const float* ln1g = (const float*)d_in[7];
    const float* ln1b = (const float*)d_in[8];
    const float* ln2g = (const float*)d_in[9];
    const float* ln2b = (const float*)d_in[10];
    const float* w1   = (const float*)d_in[11];
    const float* b1   = (const float*)d_in[12];
    const float* w2   = (const float*)d_in[13];
    const float* b2   = (const float*)d_in[14];
    const float* h0   = (const float*)d_in[15];
    float* out = (float*)d_out;

    float *xn, *xe, *hT, *u1T, *r, *xres, *mlp, *gwT, *gwR;
    float *ewR, *owR, *w1R, *w2R;
    cudaGetSymbolAddress((void**)&xn,   g_xn);
    cudaGetSymbolAddress((void**)&xe,   g_xe);
    cudaGetSymbolAddress((void**)&hT,   g_hT);
    cudaGetSymbolAddress((void**)&u1T,  g_u1T);
    cudaGetSymbolAddress((void**)&r,    g_r);
    cudaGetSymbolAddress((void**)&xres, g_xres);
    cudaGetSymbolAddress((void**)&mlp,  g_mlp);
    cudaGetSymbolAddress((void**)&gwT,  g_gwT);
    cudaGetSymbolAddress((void**)&gwR,  g_gwR);
    cudaGetSymbolAddress((void**)&ewR,  g_ewR);
    cudaGetSymbolAddress((void**)&owR,  g_owR);
    cudaGetSymbolAddress((void**)&w1R,  g_w1R);
    cudaGetSymbolAddress((void**)&w2R,  g_w2R);

    cudaFuncSetAttribute(mma_gemm<0>, cudaFuncAttributeMaxDynamicSharedMemorySize, MM_SMEM);
    cudaFuncSetAttribute(mma_gemm<1>, cudaFuncAttributeMaxDynamicSharedMemorySize, MM_SMEM);
    cudaFuncSetAttribute(mma_gemm<2>, cudaFuncAttributeMaxDynamicSharedMemorySize, MM_SMEM);
    cudaFuncSetAttribute(mma_gemm<3>, cudaFuncAttributeMaxDynamicSharedMemorySize, MM_SMEM);
    cudaFuncSetAttribute(mma_gemm<4>, cudaFuncAttributeMaxDynamicSharedMemorySize, MM_SMEM);
    cudaFuncSetAttribute(mma_gemm<5>, cudaFuncAttributeMaxDynamicSharedMemorySize, MM_SMEM);
    cudaFuncSetAttribute(mma_gemm<6>, cudaFuncAttributeMaxDynamicSharedMemorySize, MM_SMEM);

    const long long SB = 512LL * 256;
    const long long SC = 256LL * 512;

    // launch 1: fused prep (round + both transposes)
    prep_kernel<<<19072, 256>>>(ew, ow, w1, w2, gw, h0,
                                ewR, owR, w1R, w2R, gwR, gwT, hT);
    // launch 2: LN1
    ln_kernel<<<BSROWS / 8, 256>>>(x, ln1g, ln1b, xn);
    // launch 3: embed + clip + per-head l1norm
    mma_gemm<0><<<dim3(4, 256, 1), 256, MM_SMEM>>>(xn, ewR, eb, nullptr, xe, nullptr, 512, 512, 0, 0);

    for (int it = 0; it < 10; it++) {
        if (it < 9) {
            mma_gemm<5><<<dim3(4, 2, 128), 256, MM_SMEM>>>(gwT, hT, lw, xe, r, u1T, 256, 512, SB, SC);
            mma_gemm<4><<<dim3(4, 2, 128), 256, MM_SMEM>>>(gwR, u1T, nullptr, hT, hT, hT, 256, 512, SB, SC);
        } else {
            mma_gemm<6><<<dim3(4, 2, 128), 256, MM_SMEM>>>(gwT, hT, lw, xe, r, u1T, 256, 512, SB, SC);
        }
    }

    mma_gemm<1><<<dim3(4, 256, 1), 256, MM_SMEM>>>(r, owR, ob, x, xres, nullptr, 512, 512, 0, 0);
    ln_kernel<<<BSROWS / 8, 256>>>(xres, ln2g, ln2b, xn);
    mma_gemm<2><<<dim3(16, 256, 1), 256, MM_SMEM>>>(xn, w1R, b1, nullptr, mlp, nullptr, 512, 2048, 0, 0);
    mma_gemm<1><<<dim3(4, 256, 1), 256, MM_SMEM>>>(mlp, w2R, b2, xres, out, nullptr, 2048, 512, 0, 0);
}